// round 9
// baseline (speedup 1.0000x reference)
#include <cuda_runtime.h>
#include <cuda_bf16.h>
#include <math.h>

#define NE      30000
#define NREL    18
#define NB      8
#define D       128
#define NEDGE   1000000
#define BATCH   64
#define LSEQ    256
#define NCTX    32
#define NHEAD   2
#define DH      64
#define FFND    512
#define NLAY    2
#define NEGV    (-1e9f)

// ---------------- device scratch (static, referenced ONLY in device code) ---
static __device__ float g_W[(size_t)NREL * NE * D];     // 276 MB
static __device__ float g_kg[(size_t)NE * D];
static __device__ int   g_cnt[NE * NREL];
static __device__ int   g_off[NE + 1];
static __device__ int   g_cur[NE];
static __device__ int   g_elist[NEDGE];
static __device__ float g_x [BATCH * LSEQ * D];
static __device__ float g_q [BATCH * LSEQ * D];
static __device__ float g_k [BATCH * LSEQ * D];
static __device__ float g_v [BATCH * LSEQ * D];
static __device__ float g_sc[(size_t)BATCH * NHEAD * LSEQ * LSEQ]; // 33.5MB
static __device__ float g_ao[BATCH * LSEQ * D];
static __device__ float g_tmp[BATCH * LSEQ * D];
static __device__ float g_ffn[BATCH * LSEQ * FFND];
static __device__ float g_trep[BATCH * D];
static __device__ float g_erep[BATCH * D];
static __device__ float g_user[BATCH * D];
static __device__ float* g_bufs[8];

#define BUF_X   0
#define BUF_Q   1
#define BUF_K   2
#define BUF_V   3
#define BUF_AO  4
#define BUF_TMP 5
#define BUF_FFN 6

__global__ void init_ptrs_kernel() {
    g_bufs[BUF_X] = g_x;  g_bufs[BUF_Q] = g_q;  g_bufs[BUF_K] = g_k;
    g_bufs[BUF_V] = g_v;  g_bufs[BUF_AO] = g_ao; g_bufs[BUF_TMP] = g_tmp;
    g_bufs[BUF_FFN] = g_ffn;
}

// ---------------- helpers ----------------
__device__ __forceinline__ float warp_sum(float v) {
    #pragma unroll
    for (int o = 16; o > 0; o >>= 1) v += __shfl_xor_sync(0xFFFFFFFFu, v, o);
    return v;
}
__device__ __forceinline__ float warp_max(float v) {
    #pragma unroll
    for (int o = 16; o > 0; o >>= 1) v = fmaxf(v, __shfl_xor_sync(0xFFFFFFFFu, v, o));
    return v;
}
__device__ __forceinline__ void mma_tf32(float* c, const unsigned* a, const unsigned* b) {
    asm volatile(
        "mma.sync.aligned.m16n8k8.row.col.f32.tf32.tf32.f32 "
        "{%0,%1,%2,%3}, {%4,%5,%6,%7}, {%8,%9}, {%0,%1,%2,%3};\n"
        : "+f"(c[0]), "+f"(c[1]), "+f"(c[2]), "+f"(c[3])
        : "r"(a[0]), "r"(a[1]), "r"(a[2]), "r"(a[3]), "r"(b[0]), "r"(b[1]));
}
__device__ __forceinline__ unsigned f2tf(float x) {
    unsigned r;
    asm("cvt.rna.tf32.f32 %0, %1;" : "=r"(r) : "f"(x));
    return r;
}
__device__ __forceinline__ void tf_split(float x, unsigned& hi, unsigned& lo) {
    hi = f2tf(x);
    lo = f2tf(__fsub_rn(x, __uint_as_float(hi)));
}

// ---------------- RGCN ----------------
__global__ void __launch_bounds__(256) zero_cnt_kernel() {
    int i = blockIdx.x * blockDim.x + threadIdx.x;
    if (i < NE * NREL) g_cnt[i] = 0;
}

__global__ void __launch_bounds__(128) rgcn_w_kernel(const float* __restrict__ basis,
                                                     const float* __restrict__ comp,
                                                     const float* __restrict__ root,
                                                     const float* __restrict__ bias) {
    int n = blockIdx.x, d = threadIdx.x;
    __shared__ float sc[NREL * NB];
    for (int i = d; i < NREL * NB; i += 128) sc[i] = comp[i];
    __syncthreads();
    float bb[NB];
    #pragma unroll
    for (int q = 0; q < NB; q++) bb[q] = basis[((size_t)q * NE + n) * D + d];
    #pragma unroll
    for (int r = 0; r < NREL; r++) {
        float a = 0.f;
        #pragma unroll
        for (int q = 0; q < NB; q++) a = fmaf(sc[r * NB + q], bb[q], a);
        g_W[((size_t)r * NE + n) * D + d] = a;
    }
    g_kg[(size_t)n * D + d] = root[(size_t)n * D + d] + bias[d];
}

__global__ void __launch_bounds__(256) count_kernel(const int* __restrict__ ei,
                                                    const int* __restrict__ et) {
    int e = blockIdx.x * blockDim.x + threadIdx.x;
    if (e < NEDGE) {
        int dst = ei[NEDGE + e];
        atomicAdd(&g_cnt[dst * NREL + et[e]], 1);
    }
}

// exclusive prefix sum over per-dst degree (degree = sum of cnt row)
__global__ void __launch_bounds__(1024) scan_kernel() {
    __shared__ int warp_sums[32];
    __shared__ int carry_s;
    int tid = threadIdx.x, lane = tid & 31, w = tid >> 5;
    if (tid == 0) carry_s = 0;
    __syncthreads();
    for (int base = 0; base < NE; base += 1024) {
        int i = base + tid;
        int v = 0;
        if (i < NE) {
            #pragma unroll
            for (int r = 0; r < NREL; r++) v += g_cnt[i * NREL + r];
        }
        int x = v;
        #pragma unroll
        for (int o = 1; o < 32; o <<= 1) {
            int y = __shfl_up_sync(0xFFFFFFFFu, x, o);
            if (lane >= o) x += y;
        }
        if (lane == 31) warp_sums[w] = x;
        __syncthreads();
        if (w == 0) {
            int s = warp_sums[lane];
            #pragma unroll
            for (int o = 1; o < 32; o <<= 1) {
                int y = __shfl_up_sync(0xFFFFFFFFu, s, o);
                if (lane >= o) s += y;
            }
            warp_sums[lane] = s;
        }
        __syncthreads();
        int block_excl = (w > 0) ? warp_sums[w - 1] : 0;
        int excl = carry_s + block_excl + x - v;
        if (i < NE) { g_off[i] = excl; g_cur[i] = excl; }
        __syncthreads();
        if (tid == 0) carry_s += warp_sums[31];
        __syncthreads();
    }
    if (tid == 0) g_off[NE] = carry_s;
}

__global__ void __launch_bounds__(256) fill_kernel(const int* __restrict__ ei,
                                                   const int* __restrict__ et) {
    int e = blockIdx.x * blockDim.x + threadIdx.x;
    if (e >= NEDGE) return;
    int dst = ei[NEDGE + e];
    int pos = atomicAdd(&g_cur[dst], 1);
    g_elist[pos] = ei[e] | (et[e] << 16);
}

// one warp per dst: accumulate W rows of its edges (MLP-4 unrolled), add into kg
__global__ void __launch_bounds__(256) agg_kernel() {
    int gw = (blockIdx.x * blockDim.x + threadIdx.x) >> 5;
    int lane = threadIdx.x & 31;
    if (gw >= NE) return;
    int off = g_off[gw], end = g_off[gw + 1];
    float a0 = 0.f, a1 = 0.f, a2 = 0.f, a3 = 0.f;
    for (int b = off; b < end; b += 32) {
        int n = min(32, end - b);
        int pk = (b + lane < end) ? g_elist[b + lane] : 0;
        int j = 0;
        for (; j + 4 <= n; j += 4) {
            int p0 = __shfl_sync(0xFFFFFFFFu, pk, j);
            int p1 = __shfl_sync(0xFFFFFFFFu, pk, j + 1);
            int p2 = __shfl_sync(0xFFFFFFFFu, pk, j + 2);
            int p3 = __shfl_sync(0xFFFFFFFFu, pk, j + 3);
            float4 v0 = *(const float4*)(g_W + ((size_t)(p0 >> 16) * NE + (p0 & 0xFFFF)) * D + lane * 4);
            float4 v1 = *(const float4*)(g_W + ((size_t)(p1 >> 16) * NE + (p1 & 0xFFFF)) * D + lane * 4);
            float4 v2 = *(const float4*)(g_W + ((size_t)(p2 >> 16) * NE + (p2 & 0xFFFF)) * D + lane * 4);
            float4 v3 = *(const float4*)(g_W + ((size_t)(p3 >> 16) * NE + (p3 & 0xFFFF)) * D + lane * 4);
            float n0 = 1.f / fmaxf((float)g_cnt[gw * NREL + (p0 >> 16)], 1.f);
            float n1 = 1.f / fmaxf((float)g_cnt[gw * NREL + (p1 >> 16)], 1.f);
            float n2 = 1.f / fmaxf((float)g_cnt[gw * NREL + (p2 >> 16)], 1.f);
            float n3 = 1.f / fmaxf((float)g_cnt[gw * NREL + (p3 >> 16)], 1.f);
            a0 = fmaf(v0.x, n0, a0); a1 = fmaf(v0.y, n0, a1); a2 = fmaf(v0.z, n0, a2); a3 = fmaf(v0.w, n0, a3);
            a0 = fmaf(v1.x, n1, a0); a1 = fmaf(v1.y, n1, a1); a2 = fmaf(v1.z, n1, a2); a3 = fmaf(v1.w, n1, a3);
            a0 = fmaf(v2.x, n2, a0); a1 = fmaf(v2.y, n2, a1); a2 = fmaf(v2.z, n2, a2); a3 = fmaf(v2.w, n2, a3);
            a0 = fmaf(v3.x, n3, a0); a1 = fmaf(v3.y, n3, a1); a2 = fmaf(v3.z, n3, a2); a3 = fmaf(v3.w, n3, a3);
        }
        for (; j < n; j++) {
            int p = __shfl_sync(0xFFFFFFFFu, pk, j);
            int src = p & 0xFFFF, r = p >> 16;
            float norm = 1.f / fmaxf((float)g_cnt[gw * NREL + r], 1.f);
            float4 v = *(const float4*)(g_W + ((size_t)r * NE + src) * D + lane * 4);
            a0 = fmaf(v.x, norm, a0); a1 = fmaf(v.y, norm, a1);
            a2 = fmaf(v.z, norm, a2); a3 = fmaf(v.w, norm, a3);
        }
    }
    float* o = g_kg + (size_t)gw * D + lane * 4;
    float4 cur = *(float4*)o;
    *(float4*)o = make_float4(cur.x + a0, cur.y + a1, cur.z + a2, cur.w + a3);
}

// ---------------- encoder ----------------
__global__ void __launch_bounds__(256) embed_kernel(const int* __restrict__ tokens,
                                                    const float* __restrict__ tok_emb,
                                                    const float* __restrict__ pos_emb) {
    int i = blockIdx.x * blockDim.x + threadIdx.x;
    int d = i & (D - 1);
    int bl = i >> 7;
    int l = bl & (LSEQ - 1);
    int tk = tokens[bl];
    g_x[i] = tok_emb[(size_t)tk * D + d] * 11.3137084989847603904f + pos_emb[l * D + d];
}

// ---- 3xTF32 tensor-core GEMM: 64x128 tile, BK=16, 2 CTAs/SM ----
// 8 warps as 2(m) x 4(n); warp tile 32x32. Pre-split smem + reg prefetch.
__global__ void __launch_bounds__(256, 2) gemm_tc_kernel(const float* __restrict__ Bw,
                                                         const float* __restrict__ bias,
                                                         int asel, int csel,
                                                         int M, int N, int K, int relu,
                                                         int qkv_mode) {
    int n0;
    if (qkv_mode) { Bw += (size_t)blockIdx.y * D * D; csel += blockIdx.y; n0 = 0; }
    else n0 = blockIdx.y * 128;
    const float* __restrict__ A = g_bufs[asel];
    float* __restrict__ C = g_bufs[csel];
    __shared__ unsigned Ah[16][136], Al[16][136];   // [k][m] tf32 hi/lo (m<64 used)
    __shared__ unsigned Bh[16][136], Bl[16][136];   // [k][n]
    int m0 = blockIdx.x * 64;
    int tid = threadIdx.x;
    int wid = tid >> 5, lane = tid & 31;
    int wm = wid & 1, wn = wid >> 1;               // 2 m-warps x 4 n-warps
    int g = lane >> 2, t4 = lane & 3;

    float acc[2][4][4];
    #pragma unroll
    for (int i = 0; i < 2; i++)
        #pragma unroll
        for (int j = 0; j < 4; j++)
            #pragma unroll
            for (int q = 0; q < 4; q++) acc[i][j][q] = 0.f;

    int ar = tid >> 2, ak = (tid & 3) * 4;   // A fill: 64 rows x 16k, 4 floats/thread
    int bk = tid >> 4, bn = (tid & 15) * 8;  // B fill: 16 rows x 128n, 8 floats/thread

    // prefetch tile 0
    float4 pa, pb0, pb1;
    {
        pa  = *(const float4*)(A + (size_t)(m0 + ar) * K + ak);
        const float* bp = Bw + (size_t)bk * N + n0 + bn;
        pb0 = *(const float4*)bp; pb1 = *(const float4*)(bp + 4);
    }

    for (int kc = 0; kc < K; kc += 16) {
        {   // split-store prefetched regs into smem
            float av[4] = {pa.x, pa.y, pa.z, pa.w};
            #pragma unroll
            for (int i = 0; i < 4; i++) {
                unsigned hi, lo; tf_split(av[i], hi, lo);
                Ah[ak + i][ar] = hi; Al[ak + i][ar] = lo;
            }
            float bv[8] = {pb0.x, pb0.y, pb0.z, pb0.w, pb1.x, pb1.y, pb1.z, pb1.w};
            unsigned h4[8], l4[8];
            #pragma unroll
            for (int i = 0; i < 8; i++) tf_split(bv[i], h4[i], l4[i]);
            *(uint4*)&Bh[bk][bn]     = make_uint4(h4[0], h4[1], h4[2], h4[3]);
            *(uint4*)&Bh[bk][bn + 4] = make_uint4(h4[4], h4[5], h4[6], h4[7]);
            *(uint4*)&Bl[bk][bn]     = make_uint4(l4[0], l4[1], l4[2], l4[3]);
            *(uint4*)&Bl[bk][bn + 4] = make_uint4(l4[4], l4[5], l4[6], l4[7]);
        }
        __syncthreads();
        if (kc + 16 < K) {   // prefetch next tile (overlaps with compute)
            pa  = *(const float4*)(A + (size_t)(m0 + ar) * K + kc + 16 + ak);
            const float* bp = Bw + (size_t)(kc + 16 + bk) * N + n0 + bn;
            pb0 = *(const float4*)bp; pb1 = *(const float4*)(bp + 4);
        }
        #pragma unroll
        for (int ks = 0; ks < 16; ks += 8) {
            unsigned ah[2][4], al_[2][4];
            #pragma unroll
            for (int mf = 0; mf < 2; mf++) {
                int mm = wm * 32 + mf * 16;
                ah[mf][0] = Ah[ks + t4    ][mm + g    ];  al_[mf][0] = Al[ks + t4    ][mm + g    ];
                ah[mf][1] = Ah[ks + t4    ][mm + g + 8];  al_[mf][1] = Al[ks + t4    ][mm + g + 8];
                ah[mf][2] = Ah[ks + t4 + 4][mm + g    ];  al_[mf][2] = Al[ks + t4 + 4][mm + g    ];
                ah[mf][3] = Ah[ks + t4 + 4][mm + g + 8];  al_[mf][3] = Al[ks + t4 + 4][mm + g + 8];
            }
            #pragma unroll
            for (int nf = 0; nf < 4; nf++) {
                int nn = wn * 32 + nf * 8 + g;
                unsigned bh2[2] = {Bh[ks + t4][nn], Bh[ks + t4 + 4][nn]};
                unsigned bl2[2] = {Bl[ks + t4][nn], Bl[ks + t4 + 4][nn]};
                #pragma unroll
                for (int mf = 0; mf < 2; mf++) {
                    mma_tf32(acc[mf][nf], al_[mf], bh2);
                    mma_tf32(acc[mf][nf], ah[mf], bl2);
                    mma_tf32(acc[mf][nf], ah[mf], bh2);
                }
            }
        }
        __syncthreads();
    }
    #pragma unroll
    for (int mf = 0; mf < 2; mf++) {
        int r0 = m0 + wm * 32 + mf * 16 + g;
        #pragma unroll
        for (int nf = 0; nf < 4; nf++) {
            int c0 = n0 + wn * 32 + nf * 8 + t4 * 2;
            float bb0 = bias ? bias[c0] : 0.f;
            float bb1 = bias ? bias[c0 + 1] : 0.f;
            float v0 = acc[mf][nf][0] + bb0, v1 = acc[mf][nf][1] + bb1;
            float v2 = acc[mf][nf][2] + bb0, v3 = acc[mf][nf][3] + bb1;
            if (relu) {
                v0 = fmaxf(v0, 0.f); v1 = fmaxf(v1, 0.f);
                v2 = fmaxf(v2, 0.f); v3 = fmaxf(v3, 0.f);
            }
            *(float2*)&C[(size_t)r0 * N + c0]       = make_float2(v0, v1);
            *(float2*)&C[(size_t)(r0 + 8) * N + c0] = make_float2(v2, v3);
        }
    }
}

// ---- tensor-core attention scores (3xTF32) ----
__global__ void __launch_bounds__(256) attn_scores_tc(const int* __restrict__ tokens) {
    int bh = blockIdx.x;
    int b = bh >> 1, h = bh & 1;
    int q0 = blockIdx.y * 64, k0 = blockIdx.z * 64;
    __shared__ float Qs[64][68];
    __shared__ float Ks[64][68];
    int tid = threadIdx.x;
    int r = tid >> 2, dg = (tid & 3) * 16;
    {
        const float* qp = g_q + (size_t)(b * LSEQ + q0 + r) * D + h * DH + dg;
        const float* kp = g_k + (size_t)(b * LSEQ + k0 + r) * D + h * DH + dg;
        #pragma unroll
        for (int u = 0; u < 4; u++) {
            *(float4*)&Qs[r][dg + u * 4] = *(const float4*)(qp + u * 4);
            *(float4*)&Ks[r][dg + u * 4] = *(const float4*)(kp + u * 4);
        }
    }
    __syncthreads();
    int wid = tid >> 5, lane = tid & 31;
    int wm = wid & 3, wn = wid >> 2;
    int g = lane >> 2, t4 = lane & 3;
    int m0 = wm * 16;

    float acc[4][4];
    #pragma unroll
    for (int j = 0; j < 4; j++)
        #pragma unroll
        for (int q = 0; q < 4; q++) acc[j][q] = 0.f;

    #pragma unroll
    for (int ks = 0; ks < 64; ks += 8) {
        unsigned ah[4], al[4];
        tf_split(Qs[m0 + g    ][ks + t4    ], ah[0], al[0]);
        tf_split(Qs[m0 + g + 8][ks + t4    ], ah[1], al[1]);
        tf_split(Qs[m0 + g    ][ks + t4 + 4], ah[2], al[2]);
        tf_split(Qs[m0 + g + 8][ks + t4 + 4], ah[3], al[3]);
        #pragma unroll
        for (int nf = 0; nf < 4; nf++) {
            int nn = wn * 32 + nf * 8 + g;
            unsigned bh2[2], bl2[2];
            tf_split(Ks[nn][ks + t4    ], bh2[0], bl2[0]);
            tf_split(Ks[nn][ks + t4 + 4], bh2[1], bl2[1]);
            mma_tf32(acc[nf], al, bh2);
            mma_tf32(acc[nf], ah, bl2);
            mma_tf32(acc[nf], ah, bh2);
        }
    }
    int row0 = bh * LSEQ + q0 + m0 + g;
    #pragma unroll
    for (int nf = 0; nf < 4; nf++) {
        int c0 = k0 + wn * 32 + nf * 8 + t4 * 2;
        float mb0 = (tokens[b * LSEQ + c0] != 0) ? 0.f : NEGV;
        float mb1 = (tokens[b * LSEQ + c0 + 1] != 0) ? 0.f : NEGV;
        *(float2*)&g_sc[(size_t)row0 * LSEQ + c0] =
            make_float2(acc[nf][0] * 0.125f + mb0, acc[nf][1] * 0.125f + mb1);
        *(float2*)&g_sc[(size_t)(row0 + 8) * LSEQ + c0] =
            make_float2(acc[nf][2] * 0.125f + mb0, acc[nf][3] * 0.125f + mb1);
    }
}

__global__ void __launch_bounds__(128) softmax_kernel() {
    int row = blockIdx.x * 4 + (threadIdx.x >> 5);
    int lane = threadIdx.x & 31;
    float* p = g_sc + (size_t)row * LSEQ;
    float v[8];
    float m = -INFINITY;
    #pragma unroll
    for (int i = 0; i < 8; i++) { v[i] = p[lane + 32 * i]; m = fmaxf(m, v[i]); }
    m = warp_max(m);
    float s = 0.f;
    #pragma unroll
    for (int i = 0; i < 8; i++) { v[i] = expf(v[i] - m); s += v[i]; }
    s = warp_sum(s);
    float inv = 1.f / s;
    #pragma unroll
    for (int i = 0; i < 8; i++) p[lane + 32 * i] = v[i] * inv;
}

// ---- tensor-core AV (3xTF32) ----
__global__ void __launch_bounds__(256) attn_av_tc() {
    int bh = blockIdx.x;
    int b = bh >> 1, h = bh & 1;
    int l0 = blockIdx.y * 128;
    __shared__ float Ps[128][36];
    __shared__ float Vs[32][68];
    int tid = threadIdx.x;
    int wid = tid >> 5, lane = tid & 31;
    int wm = wid & 3, wn = wid >> 2;
    int g = lane >> 2, t4 = lane & 3;

    float acc[2][4][4];
    #pragma unroll
    for (int i = 0; i < 2; i++)
        #pragma unroll
        for (int j = 0; j < 4; j++)
            #pragma unroll
            for (int q = 0; q < 4; q++) acc[i][j][q] = 0.f;

    int pr = tid >> 1, pk = (tid & 1) * 16;
    int vr = tid >> 3, vd = (tid & 7) * 8;

    for (int kc = 0; kc < 8; kc++) {
        const float* pp = g_sc + (size_t)(bh * LSEQ + l0 + pr) * LSEQ + kc * 32 + pk;
        #pragma unroll
        for (int u = 0; u < 4; u++)
            *(float4*)&Ps[pr][pk + u * 4] = *(const float4*)(pp + u * 4);
        const float* vp = g_v + (size_t)(b * LSEQ + kc * 32 + vr) * D + h * DH + vd;
        #pragma unroll
        for (int u = 0; u < 2; u++)
            *(float4*)&Vs[vr][vd + u * 4] = *(const float4*)(vp + u * 4);
        __syncthreads();
        #pragma unroll
        for (int ks = 0; ks < 32; ks += 8) {
            unsigned ah[2][4], al[2][4];
            #pragma unroll
            for (int mf = 0; mf < 2; mf++) {
                int mm = wm * 32 + mf * 16;
                tf_split(Ps[mm + g    ][ks + t4    ], ah[mf][0], al[mf][0]);
                tf_split(Ps[mm + g + 8][ks + t4    ], ah[mf][1], al[mf][1]);
                tf_split(Ps[mm + g    ][ks + t4 + 4], ah[mf][2], al[mf][2]);
                tf_split(Ps[mm + g + 8][ks + t4 + 4], ah[mf][3], al[mf][3]);
            }
            #pragma unroll
            for (int nf = 0; nf < 4; nf++) {
                int nn = wn * 32 + nf * 8 + g;
                unsigned bh2[2], bl2[2];
                tf_split(Vs[ks + t4    ][nn], bh2[0], bl2[0]);
                tf_split(Vs[ks + t4 + 4][nn], bh2[1], bl2[1]);
                #pragma unroll
                for (int mf = 0; mf < 2; mf++) {
                    mma_tf32(acc[mf][nf], al[mf], bh2);
                    mma_tf32(acc[mf][nf], ah[mf], bl2);
                    mma_tf32(acc[mf][nf], ah[mf], bh2);
                }
            }
        }
        __syncthreads();
    }
    #pragma unroll
    for (int mf = 0; mf < 2; mf++) {
        int r0 = b * LSEQ + l0 + wm * 32 + mf * 16 + g;
        #pragma unroll
        for (int nf = 0; nf < 4; nf++) {
            int c0 = h * DH + wn * 32 + nf * 8 + t4 * 2;
            *(float2*)&g_ao[(size_t)r0 * D + c0] = make_float2(acc[mf][nf][0], acc[mf][nf][1]);
            *(float2*)&g_ao[(size_t)(r0 + 8) * D + c0] = make_float2(acc[mf][nf][2], acc[mf][nf][3]);
        }
    }
}

__global__ void __launch_bounds__(128) add_ln_kernel(const float* __restrict__ g,
                                                     const float* __restrict__ b) {
    int row = blockIdx.x, tid = threadIdx.x;
    int w = tid >> 5, lane = tid & 31;
    float v = g_x[(size_t)row * D + tid] + g_tmp[(size_t)row * D + tid];
    float s = warp_sum(v);
    float s2 = warp_sum(v * v);
    __shared__ float ws[4], ws2[4];
    if (lane == 0) { ws[w] = s; ws2[w] = s2; }
    __syncthreads();
    s = ws[0] + ws[1] + ws[2] + ws[3];
    s2 = ws2[0] + ws2[1] + ws2[2] + ws2[3];
    float m = s * (1.f / D);
    float var = s2 * (1.f / D) - m * m;
    float inv = rsqrtf(var + 1e-5f);
    g_x[(size_t)row * D + tid] = (v - m) * inv * g[tid] + b[tid];
}

// ---------------- pooling / gate / final ----------------
__global__ void __launch_bounds__(128) tok_pool_kernel(const int* __restrict__ tokens,
                                                       const float* __restrict__ vvec) {
    int b = blockIdx.x, tid = threadIdx.x;
    int w = tid >> 5, lane = tid & 31;
    __shared__ float s_s[LSEQ];
    __shared__ float red[4];
    for (int l = w; l < LSEQ; l += 4) {
        float val = 0.f;
        #pragma unroll
        for (int d = lane; d < D; d += 32)
            val += tanhf(g_ffn[((size_t)(b * LSEQ + l)) * D + d]) * vvec[d];
        val = warp_sum(val);
        if (lane == 0) s_s[l] = (tokens[b * LSEQ + l] != 0) ? val : NEGV;
    }
    __syncthreads();
    float m = fmaxf(s_s[tid], s_s[tid + 128]);
    m = warp_max(m);
    if (lane == 0) red[w] = m;
    __syncthreads();
    m = fmaxf(fmaxf(red[0], red[1]), fmaxf(red[2], red[3]));
    __syncthreads();
    float e0 = expf(s_s[tid] - m), e1 = expf(s_s[tid + 128] - m);
    float ssum = warp_sum(e0 + e1);
    if (lane == 0) red[w] = ssum;
    __syncthreads();
    ssum = red[0] + red[1] + red[2] + red[3];
    float inv = 1.f / ssum;
    __syncthreads();
    s_s[tid] = e0 * inv; s_s[tid + 128] = e1 * inv;
    __syncthreads();
    float acc = 0.f;
    for (int l = 0; l < LSEQ; l++)
        acc = fmaf(s_s[l], g_x[((size_t)(b * LSEQ + l)) * D + tid], acc);
    g_trep[b * D + tid] = acc;
}

__global__ void __launch_bounds__(128) ent_pool_kernel(const int* __restrict__ ctx,
                                                       const float* __restrict__ Wa,
                                                       const float* __restrict__ ba,
                                                       const float* __restrict__ vvec) {
    int b = blockIdx.x, tid = threadIdx.x;
    int w = tid >> 5, lane = tid & 31;
    __shared__ float h_s[NCTX][D];
    __shared__ float s_s[NCTX];
    __shared__ int cs[NCTX];
    if (tid < NCTX) cs[tid] = ctx[b * NCTX + tid];
    __syncthreads();
    for (int j = 0; j < NCTX; j++)
        h_s[j][tid] = g_kg[(size_t)cs[j] * D + tid];
    __syncthreads();
    for (int j = w; j < NCTX; j += 4) {
        float val = 0.f;
        for (int d = lane; d < D; d += 32) {
            float acc = ba[d];
            #pragma unroll 8
            for (int kk = 0; kk < D; kk++)
                acc = fmaf(h_s[j][kk], Wa[kk * D + d], acc);
            val += tanhf(acc) * vvec[d];
        }
        val = warp_sum(val);
        if (lane == 0) s_s[j] = (cs[j] != 0) ? val : NEGV;
    }
    __syncthreads();
    if (w == 0) {
        float sv = s_s[lane];
        float m = warp_max(sv);
        float e = expf(sv - m);
        float ssum = warp_sum(e);
        s_s[lane] = e / ssum;
    }
    __syncthreads();
    float acc = 0.f;
    #pragma unroll
    for (int j = 0; j < NCTX; j++) acc = fmaf(s_s[j], h_s[j][tid], acc);
    g_erep[b * D + tid] = acc;
}

__global__ void __launch_bounds__(128) gate_kernel(const float* __restrict__ Wg,
                                                   const float* __restrict__ bg) {
    int b = blockIdx.x, tid = threadIdx.x;
    __shared__ float cat[2 * D];
    cat[tid] = g_trep[b * D + tid];
    cat[D + tid] = g_erep[b * D + tid];
    __syncthreads();
    float acc = bg[tid];
    #pragma unroll 8
    for (int j = 0; j < 2 * D; j++) acc = fmaf(cat[j], Wg[j * D + tid], acc);
    float sg = 1.f / (1.f + expf(-acc));
    g_user[b * D + tid] = sg * cat[tid] + (1.f - sg) * cat[D + tid];
}

__global__ void __launch_bounds__(256) final_kernel(float* __restrict__ out) {
    __shared__ float kg_s[128][17];
    __shared__ float user_t[D][BATCH];
    int n0 = blockIdx.x * 128, tid = threadIdx.x;
    for (int i = tid; i < D * BATCH; i += 256) {
        int d = i >> 6, bb = i & 63;
        user_t[d][bb] = g_user[bb * D + d];
    }
    int tn = tid >> 3, tb = tid & 7;
    float acc[4][8];
    #pragma unroll
    for (int i = 0; i < 4; i++)
        #pragma unroll
        for (int j = 0; j < 8; j++) acc[i][j] = 0.f;
    for (int dc = 0; dc < D; dc += 16) {
        __syncthreads();
        for (int i = tid; i < 128 * 16; i += 256) {
            int nl = i >> 4, dd = i & 15;
            int n = n0 + nl;
            kg_s[nl][dd] = (n < NE) ? g_kg[(size_t)n * D + dc + dd] : 0.f;
        }
        __syncthreads();
        #pragma unroll
        for (int dd = 0; dd < 16; dd++) {
            float kv[4], uv[8];
            #pragma unroll
            for (int i = 0; i < 4; i++) kv[i] = kg_s[tn * 4 + i][dd];
            #pragma unroll
            for (int j = 0; j < 8; j++) uv[j] = user_t[dc + dd][tb * 8 + j];
            #pragma unroll
            for (int i = 0; i < 4; i++)
                #pragma unroll
                for (int j = 0; j < 8; j++) acc[i][j] = fmaf(kv[i], uv[j], acc[i][j]);
        }
    }
    #pragma unroll
    for (int i = 0; i < 4; i++) {
        int n = n0 + tn * 4 + i;
        if (n < NE) {
            #pragma unroll
            for (int j = 0; j < 8; j++)
                out[(size_t)(tb * 8 + j) * NE + n] = acc[i][j];
        }
    }
}

// ---------------- launch ----------------
extern "C" void kernel_launch(void* const* d_in, const int* in_sizes, int n_in,
                              void* d_out, int out_size) {
    const int*   edge_idx = (const int*)d_in[0];
    const int*   edge_type = (const int*)d_in[1];
    const int*   ctx_ent  = (const int*)d_in[2];
    const int*   ctx_tok  = (const int*)d_in[3];
    const float* basis    = (const float*)d_in[4];
    const float* comp     = (const float*)d_in[5];
    const float* root     = (const float*)d_in[6];
    const float* rgcn_b   = (const float*)d_in[7];
    const float* tok_emb  = (const float*)d_in[8];
    const float* pos_emb  = (const float*)d_in[9];
    const float* Wqkv     = (const float*)d_in[10];
    const float* Wo       = (const float*)d_in[11];
    const float* ln1_g    = (const float*)d_in[12];
    const float* ln1_b    = (const float*)d_in[13];
    const float* ln2_g    = (const float*)d_in[14];
    const float* ln2_b    = (const float*)d_in[15];
    const float* W1       = (const float*)d_in[16];
    const float* b1       = (const float*)d_in[17];
    const float* W2       = (const float*)d_in[18];
    const float* b2       = (const float*)d_in[19];
    const float* ent_Wa   = (const float*)d_in[20];
    const float* ent_ba   = (const float*)d_in[21];
    const float* ent_v    = (const float*)d_in[22];
    const float* tok_Wa   = (const float*)d_in[23];
    const float* tok_ba   = (const float*)d_in[24];
    const float* tok_v    = (const float*)d_in[25];
    const float* Wg       = (const float*)d_in[26];
    const float* bg       = (const float*)d_in[27];
    float* out = (float*)d_out;

    const int M = BATCH * LSEQ;  // 16384

    // --- encoder FIRST (independent of RGCN; puts QKV GEMM at the ncu-profiled
    //     launch slot so the next profile shows the suspected dominant kernel) ---
    init_ptrs_kernel<<<1, 1>>>();
    zero_cnt_kernel<<<(NE * NREL + 255) / 256, 256>>>();
    embed_kernel<<<(BATCH * LSEQ * D) / 256, 256>>>(ctx_tok, tok_emb, pos_emb);
    for (int l = 0; l < NLAY; l++) {
        gemm_tc_kernel<<<dim3(M / 64, 3), 256>>>(Wqkv + (size_t)l * 3 * D * D, nullptr, BUF_X, BUF_Q, M, D, D, 0, 1);
        attn_scores_tc<<<dim3(BATCH * NHEAD, LSEQ / 64, LSEQ / 64), 256>>>(ctx_tok);
        softmax_kernel<<<(BATCH * NHEAD * LSEQ) / 4, 128>>>();
        attn_av_tc<<<dim3(BATCH * NHEAD, LSEQ / 128), 256>>>();
        gemm_tc_kernel<<<dim3(M / 64, 1), 256>>>(Wo + (size_t)l * D * D, nullptr, BUF_AO, BUF_TMP, M, D, D, 0, 0);
        add_ln_kernel<<<M, 128>>>(ln1_g + l * D, ln1_b + l * D);
        gemm_tc_kernel<<<dim3(M / 64, FFND / 128), 256>>>(W1 + (size_t)l * D * FFND, b1 + l * FFND, BUF_X, BUF_FFN, M, FFND, D, 1, 0);
        gemm_tc_kernel<<<dim3(M / 64, 1), 256>>>(W2 + (size_t)l * FFND * D, b2 + l * D, BUF_FFN, BUF_TMP, M, D, FFND, 0, 0);
        add_ln_kernel<<<M, 128>>>(ln2_g + l * D, ln2_b + l * D);
    }
    gemm_tc_kernel<<<dim3(M / 64, 1), 256>>>(tok_Wa, tok_ba, BUF_X, BUF_FFN, M, D, D, 0, 0);

    // --- RGCN (CSR, no atomics on kg) ---
    rgcn_w_kernel<<<NE, 128>>>(basis, comp, root, rgcn_b);
    count_kernel<<<(NEDGE + 255) / 256, 256>>>(edge_idx, edge_type);
    scan_kernel<<<1, 1024>>>();
    fill_kernel<<<(NEDGE + 255) / 256, 256>>>(edge_idx, edge_type);
    agg_kernel<<<(NE * 32 + 255) / 256, 256>>>();

    // --- pooling / gate / score ---
    tok_pool_kernel<<<BATCH, 128>>>(ctx_tok, tok_v);
    ent_pool_kernel<<<BATCH, 128>>>(ctx_ent, ent_Wa, ent_ba, ent_v);
    gate_kernel<<<BATCH, 128>>>(Wg, bg);
    final_kernel<<<(NE + 127) / 128, 256>>>(out);
}

// round 10
// speedup vs baseline: 1.1039x; 1.1039x over previous
#include <cuda_runtime.h>
#include <cuda_bf16.h>
#include <math.h>

#define NE      30000
#define NREL    18
#define NB      8
#define D       128
#define NEDGE   1000000
#define BATCH   64
#define LSEQ    256
#define NCTX    32
#define NHEAD   2
#define DH      64
#define FFND    512
#define NLAY    2
#define NEGV    (-1e9f)

// ---------------- device scratch (static, referenced ONLY in device code) ---
static __device__ float g_W[(size_t)NREL * NE * D];     // 276 MB
static __device__ float g_kg[(size_t)NE * D];
static __device__ int   g_cnt[NE * NREL];
static __device__ int   g_off[NE + 1];
static __device__ int   g_cur[NE];
static __device__ int   g_elist[NEDGE];
static __device__ float g_x [BATCH * LSEQ * D];
static __device__ float g_q [BATCH * LSEQ * D];
static __device__ float g_k [BATCH * LSEQ * D];
static __device__ float g_v [BATCH * LSEQ * D];
static __device__ float g_sc[(size_t)BATCH * NHEAD * LSEQ * LSEQ]; // 33.5MB
static __device__ float g_ao[BATCH * LSEQ * D];
static __device__ float g_tmp[BATCH * LSEQ * D];
static __device__ float g_ffn[BATCH * LSEQ * FFND];
static __device__ float g_trep[BATCH * D];
static __device__ float g_erep[BATCH * D];
static __device__ float g_user[BATCH * D];
static __device__ float* g_bufs[8];

#define BUF_X   0
#define BUF_Q   1
#define BUF_K   2
#define BUF_V   3
#define BUF_AO  4
#define BUF_TMP 5
#define BUF_FFN 6

__global__ void init_ptrs_kernel() {
    g_bufs[BUF_X] = g_x;  g_bufs[BUF_Q] = g_q;  g_bufs[BUF_K] = g_k;
    g_bufs[BUF_V] = g_v;  g_bufs[BUF_AO] = g_ao; g_bufs[BUF_TMP] = g_tmp;
    g_bufs[BUF_FFN] = g_ffn;
}

// ---------------- helpers ----------------
__device__ __forceinline__ float warp_sum(float v) {
    #pragma unroll
    for (int o = 16; o > 0; o >>= 1) v += __shfl_xor_sync(0xFFFFFFFFu, v, o);
    return v;
}
__device__ __forceinline__ float warp_max(float v) {
    #pragma unroll
    for (int o = 16; o > 0; o >>= 1) v = fmaxf(v, __shfl_xor_sync(0xFFFFFFFFu, v, o));
    return v;
}
// tf32 m16n8k8 (used by attention kernels)
__device__ __forceinline__ void mma_tf32(float* c, const unsigned* a, const unsigned* b) {
    asm volatile(
        "mma.sync.aligned.m16n8k8.row.col.f32.tf32.tf32.f32 "
        "{%0,%1,%2,%3}, {%4,%5,%6,%7}, {%8,%9}, {%0,%1,%2,%3};\n"
        : "+f"(c[0]), "+f"(c[1]), "+f"(c[2]), "+f"(c[3])
        : "r"(a[0]), "r"(a[1]), "r"(a[2]), "r"(a[3]), "r"(b[0]), "r"(b[1]));
}
// bf16 m16n8k16 (GEMM path)
__device__ __forceinline__ void mma_bf16(float* c, const unsigned* a, const unsigned* b) {
    asm volatile(
        "mma.sync.aligned.m16n8k16.row.col.f32.bf16.bf16.f32 "
        "{%0,%1,%2,%3}, {%4,%5,%6,%7}, {%8,%9}, {%0,%1,%2,%3};\n"
        : "+f"(c[0]), "+f"(c[1]), "+f"(c[2]), "+f"(c[3])
        : "r"(a[0]), "r"(a[1]), "r"(a[2]), "r"(a[3]), "r"(b[0]), "r"(b[1]));
}
__device__ __forceinline__ unsigned f2tf(float x) {
    unsigned r;
    asm("cvt.rna.tf32.f32 %0, %1;" : "=r"(r) : "f"(x));
    return r;
}
__device__ __forceinline__ void tf_split(float x, unsigned& hi, unsigned& lo) {
    hi = f2tf(x);
    lo = f2tf(__fsub_rn(x, __uint_as_float(hi)));
}
// split two floats (consecutive k) into packed bf16x2 hi and lo words
__device__ __forceinline__ void bf_split2(float x0, float x1, unsigned& hi, unsigned& lo) {
    __nv_bfloat16 h0 = __float2bfloat16_rn(x0);
    __nv_bfloat16 h1 = __float2bfloat16_rn(x1);
    __nv_bfloat16 l0 = __float2bfloat16_rn(__fsub_rn(x0, __bfloat162float(h0)));
    __nv_bfloat16 l1 = __float2bfloat16_rn(__fsub_rn(x1, __bfloat162float(h1)));
    __nv_bfloat162 hp = __halves2bfloat162(h0, h1);   // .x low bits
    __nv_bfloat162 lp = __halves2bfloat162(l0, l1);
    hi = *(unsigned*)&hp;
    lo = *(unsigned*)&lp;
}

// ---------------- RGCN ----------------
__global__ void __launch_bounds__(256) zero_cnt_kernel() {
    int i = blockIdx.x * blockDim.x + threadIdx.x;
    if (i < NE * NREL) g_cnt[i] = 0;
}

__global__ void __launch_bounds__(128) rgcn_w_kernel(const float* __restrict__ basis,
                                                     const float* __restrict__ comp,
                                                     const float* __restrict__ root,
                                                     const float* __restrict__ bias) {
    int n = blockIdx.x, d = threadIdx.x;
    __shared__ float sc[NREL * NB];
    for (int i = d; i < NREL * NB; i += 128) sc[i] = comp[i];
    __syncthreads();
    float bb[NB];
    #pragma unroll
    for (int q = 0; q < NB; q++) bb[q] = basis[((size_t)q * NE + n) * D + d];
    #pragma unroll
    for (int r = 0; r < NREL; r++) {
        float a = 0.f;
        #pragma unroll
        for (int q = 0; q < NB; q++) a = fmaf(sc[r * NB + q], bb[q], a);
        g_W[((size_t)r * NE + n) * D + d] = a;
    }
    g_kg[(size_t)n * D + d] = root[(size_t)n * D + d] + bias[d];
}

__global__ void __launch_bounds__(256) count_kernel(const int* __restrict__ ei,
                                                    const int* __restrict__ et) {
    int e = blockIdx.x * blockDim.x + threadIdx.x;
    if (e < NEDGE) {
        int dst = ei[NEDGE + e];
        atomicAdd(&g_cnt[dst * NREL + et[e]], 1);
    }
}

// exclusive prefix sum over per-dst degree (degree = sum of cnt row)
__global__ void __launch_bounds__(1024) scan_kernel() {
    __shared__ int warp_sums[32];
    __shared__ int carry_s;
    int tid = threadIdx.x, lane = tid & 31, w = tid >> 5;
    if (tid == 0) carry_s = 0;
    __syncthreads();
    for (int base = 0; base < NE; base += 1024) {
        int i = base + tid;
        int v = 0;
        if (i < NE) {
            #pragma unroll
            for (int r = 0; r < NREL; r++) v += g_cnt[i * NREL + r];
        }
        int x = v;
        #pragma unroll
        for (int o = 1; o < 32; o <<= 1) {
            int y = __shfl_up_sync(0xFFFFFFFFu, x, o);
            if (lane >= o) x += y;
        }
        if (lane == 31) warp_sums[w] = x;
        __syncthreads();
        if (w == 0) {
            int s = warp_sums[lane];
            #pragma unroll
            for (int o = 1; o < 32; o <<= 1) {
                int y = __shfl_up_sync(0xFFFFFFFFu, s, o);
                if (lane >= o) s += y;
            }
            warp_sums[lane] = s;
        }
        __syncthreads();
        int block_excl = (w > 0) ? warp_sums[w - 1] : 0;
        int excl = carry_s + block_excl + x - v;
        if (i < NE) { g_off[i] = excl; g_cur[i] = excl; }
        __syncthreads();
        if (tid == 0) carry_s += warp_sums[31];
        __syncthreads();
    }
    if (tid == 0) g_off[NE] = carry_s;
}

__global__ void __launch_bounds__(256) fill_kernel(const int* __restrict__ ei,
                                                   const int* __restrict__ et) {
    int e = blockIdx.x * blockDim.x + threadIdx.x;
    if (e >= NEDGE) return;
    int dst = ei[NEDGE + e];
    int pos = atomicAdd(&g_cur[dst], 1);
    g_elist[pos] = ei[e] | (et[e] << 16);
}

// one warp per dst: accumulate W rows of its edges (MLP-4 unrolled), add into kg
__global__ void __launch_bounds__(256) agg_kernel() {
    int gw = (blockIdx.x * blockDim.x + threadIdx.x) >> 5;
    int lane = threadIdx.x & 31;
    if (gw >= NE) return;
    int off = g_off[gw], end = g_off[gw + 1];
    float a0 = 0.f, a1 = 0.f, a2 = 0.f, a3 = 0.f;
    for (int b = off; b < end; b += 32) {
        int n = min(32, end - b);
        int pk = (b + lane < end) ? g_elist[b + lane] : 0;
        int j = 0;
        for (; j + 4 <= n; j += 4) {
            int p0 = __shfl_sync(0xFFFFFFFFu, pk, j);
            int p1 = __shfl_sync(0xFFFFFFFFu, pk, j + 1);
            int p2 = __shfl_sync(0xFFFFFFFFu, pk, j + 2);
            int p3 = __shfl_sync(0xFFFFFFFFu, pk, j + 3);
            float4 v0 = *(const float4*)(g_W + ((size_t)(p0 >> 16) * NE + (p0 & 0xFFFF)) * D + lane * 4);
            float4 v1 = *(const float4*)(g_W + ((size_t)(p1 >> 16) * NE + (p1 & 0xFFFF)) * D + lane * 4);
            float4 v2 = *(const float4*)(g_W + ((size_t)(p2 >> 16) * NE + (p2 & 0xFFFF)) * D + lane * 4);
            float4 v3 = *(const float4*)(g_W + ((size_t)(p3 >> 16) * NE + (p3 & 0xFFFF)) * D + lane * 4);
            float n0 = 1.f / fmaxf((float)g_cnt[gw * NREL + (p0 >> 16)], 1.f);
            float n1 = 1.f / fmaxf((float)g_cnt[gw * NREL + (p1 >> 16)], 1.f);
            float n2 = 1.f / fmaxf((float)g_cnt[gw * NREL + (p2 >> 16)], 1.f);
            float n3 = 1.f / fmaxf((float)g_cnt[gw * NREL + (p3 >> 16)], 1.f);
            a0 = fmaf(v0.x, n0, a0); a1 = fmaf(v0.y, n0, a1); a2 = fmaf(v0.z, n0, a2); a3 = fmaf(v0.w, n0, a3);
            a0 = fmaf(v1.x, n1, a0); a1 = fmaf(v1.y, n1, a1); a2 = fmaf(v1.z, n1, a2); a3 = fmaf(v1.w, n1, a3);
            a0 = fmaf(v2.x, n2, a0); a1 = fmaf(v2.y, n2, a1); a2 = fmaf(v2.z, n2, a2); a3 = fmaf(v2.w, n2, a3);
            a0 = fmaf(v3.x, n3, a0); a1 = fmaf(v3.y, n3, a1); a2 = fmaf(v3.z, n3, a2); a3 = fmaf(v3.w, n3, a3);
        }
        for (; j < n; j++) {
            int p = __shfl_sync(0xFFFFFFFFu, pk, j);
            int src = p & 0xFFFF, r = p >> 16;
            float norm = 1.f / fmaxf((float)g_cnt[gw * NREL + r], 1.f);
            float4 v = *(const float4*)(g_W + ((size_t)r * NE + src) * D + lane * 4);
            a0 = fmaf(v.x, norm, a0); a1 = fmaf(v.y, norm, a1);
            a2 = fmaf(v.z, norm, a2); a3 = fmaf(v.w, norm, a3);
        }
    }
    float* o = g_kg + (size_t)gw * D + lane * 4;
    float4 cur = *(float4*)o;
    *(float4*)o = make_float4(cur.x + a0, cur.y + a1, cur.z + a2, cur.w + a3);
}

// ---------------- encoder ----------------
__global__ void __launch_bounds__(256) embed_kernel(const int* __restrict__ tokens,
                                                    const float* __restrict__ tok_emb,
                                                    const float* __restrict__ pos_emb) {
    int i = blockIdx.x * blockDim.x + threadIdx.x;
    int d = i & (D - 1);
    int bl = i >> 7;
    int l = bl & (LSEQ - 1);
    int tk = tokens[bl];
    g_x[i] = tok_emb[(size_t)tk * D + d] * 11.3137084989847603904f + pos_emb[l * D + d];
}

// ---- split-bf16 tensor-core GEMM: C = act(A@B + bias) ----
// 128x128 tile, BK=16, 8 warps (4m x 2n), warp tile 32x64 of m16n8k16 frags.
// smem holds pre-split packed bf16x2 hi/lo; row stride 12 words (conflict-free).
__global__ void __launch_bounds__(256, 2) gemm_tc_kernel(const float* __restrict__ Bw,
                                                         const float* __restrict__ bias,
                                                         int asel, int csel,
                                                         int M, int N, int K, int relu,
                                                         int qkv_mode) {
    int n0;
    if (qkv_mode) { Bw += (size_t)blockIdx.y * D * D; csel += blockIdx.y; n0 = 0; }
    else n0 = blockIdx.y * 128;
    const float* __restrict__ A = g_bufs[asel];
    float* __restrict__ C = g_bufs[csel];
    // [row][word]: 8 words used (16 bf16 = BK), stride 12 for conflict-free frags
    __shared__ unsigned Ah_s[128][12], Al_s[128][12];   // A as [m][k]
    __shared__ unsigned Bh_s[128][12], Bl_s[128][12];   // B as [n][k]
    int m0 = blockIdx.x * 128;
    int tid = threadIdx.x;
    int wid = tid >> 5, lane = tid & 31;
    int wm = wid & 3, wn = wid >> 2;            // 4 m-warps x 2 n-warps
    int g = lane >> 2, t4 = lane & 3;

    float acc[2][8][4];
    #pragma unroll
    for (int i = 0; i < 2; i++)
        #pragma unroll
        for (int j = 0; j < 8; j++)
            #pragma unroll
            for (int q = 0; q < 4; q++) acc[i][j][q] = 0.f;

    int ar = tid >> 1, aw = (tid & 1) * 4;      // A fill: row ar, words aw..aw+3 (k = aw*2..)
    int bkp = tid & 7, bn4 = (tid >> 3) * 4;    // B fill: k-pair bkp, n bn4..bn4+3

    // prefetch tile 0
    float4 pa0, pa1, pb0, pb1;
    {
        const float* ap = A + (size_t)(m0 + ar) * K + aw * 2;
        pa0 = *(const float4*)ap; pa1 = *(const float4*)(ap + 4);
        pb0 = *(const float4*)(Bw + (size_t)(2 * bkp)     * N + n0 + bn4);
        pb1 = *(const float4*)(Bw + (size_t)(2 * bkp + 1) * N + n0 + bn4);
    }

    for (int kc = 0; kc < K; kc += 16) {
        {   // split+pack prefetched regs into smem
            float av[8] = {pa0.x, pa0.y, pa0.z, pa0.w, pa1.x, pa1.y, pa1.z, pa1.w};
            unsigned h4[4], l4[4];
            #pragma unroll
            for (int i = 0; i < 4; i++) bf_split2(av[2 * i], av[2 * i + 1], h4[i], l4[i]);
            *(uint4*)&Ah_s[ar][aw] = make_uint4(h4[0], h4[1], h4[2], h4[3]);
            *(uint4*)&Al_s[ar][aw] = make_uint4(l4[0], l4[1], l4[2], l4[3]);
            float b0v[4] = {pb0.x, pb0.y, pb0.z, pb0.w};   // k = 2bkp,   n = bn4+i
            float b1v[4] = {pb1.x, pb1.y, pb1.z, pb1.w};   // k = 2bkp+1
            #pragma unroll
            for (int i = 0; i < 4; i++) {
                unsigned hw, lw;
                bf_split2(b0v[i], b1v[i], hw, lw);         // pack along k
                Bh_s[bn4 + i][bkp] = hw;
                Bl_s[bn4 + i][bkp] = lw;
            }
        }
        __syncthreads();
        if (kc + 16 < K) {   // prefetch next tile (overlaps with compute)
            const float* ap = A + (size_t)(m0 + ar) * K + kc + 16 + aw * 2;
            pa0 = *(const float4*)ap; pa1 = *(const float4*)(ap + 4);
            pb0 = *(const float4*)(Bw + (size_t)(kc + 16 + 2 * bkp)     * N + n0 + bn4);
            pb1 = *(const float4*)(Bw + (size_t)(kc + 16 + 2 * bkp + 1) * N + n0 + bn4);
        }
        // one k16 step
        {
            unsigned ah[2][4], al_[2][4];
            #pragma unroll
            for (int mf = 0; mf < 2; mf++) {
                int mm = wm * 32 + mf * 16;
                ah[mf][0] = Ah_s[mm + g    ][t4    ];  al_[mf][0] = Al_s[mm + g    ][t4    ];
                ah[mf][1] = Ah_s[mm + g + 8][t4    ];  al_[mf][1] = Al_s[mm + g + 8][t4    ];
                ah[mf][2] = Ah_s[mm + g    ][t4 + 4];  al_[mf][2] = Al_s[mm + g    ][t4 + 4];
                ah[mf][3] = Ah_s[mm + g + 8][t4 + 4];  al_[mf][3] = Al_s[mm + g + 8][t4 + 4];
            }
            #pragma unroll
            for (int nf = 0; nf < 8; nf++) {
                int nn = wn * 64 + nf * 8 + g;
                unsigned bh2[2] = {Bh_s[nn][t4], Bh_s[nn][t4 + 4]};
                unsigned bl2[2] = {Bl_s[nn][t4], Bl_s[nn][t4 + 4]};
                #pragma unroll
                for (int mf = 0; mf < 2; mf++) {
                    mma_bf16(acc[mf][nf], al_[mf], bh2);
                    mma_bf16(acc[mf][nf], ah[mf], bl2);
                    mma_bf16(acc[mf][nf], ah[mf], bh2);
                }
            }
        }
        __syncthreads();
    }
    #pragma unroll
    for (int mf = 0; mf < 2; mf++) {
        int r0 = m0 + wm * 32 + mf * 16 + g;
        #pragma unroll
        for (int nf = 0; nf < 8; nf++) {
            int c0 = n0 + wn * 64 + nf * 8 + t4 * 2;
            float bb0 = bias ? bias[c0] : 0.f;
            float bb1 = bias ? bias[c0 + 1] : 0.f;
            float v0 = acc[mf][nf][0] + bb0, v1 = acc[mf][nf][1] + bb1;
            float v2 = acc[mf][nf][2] + bb0, v3 = acc[mf][nf][3] + bb1;
            if (relu) {
                v0 = fmaxf(v0, 0.f); v1 = fmaxf(v1, 0.f);
                v2 = fmaxf(v2, 0.f); v3 = fmaxf(v3, 0.f);
            }
            *(float2*)&C[(size_t)r0 * N + c0]       = make_float2(v0, v1);
            *(float2*)&C[(size_t)(r0 + 8) * N + c0] = make_float2(v2, v3);
        }
    }
}

// ---- tensor-core attention scores (3xTF32) ----
__global__ void __launch_bounds__(256) attn_scores_tc(const int* __restrict__ tokens) {
    int bh = blockIdx.x;
    int b = bh >> 1, h = bh & 1;
    int q0 = blockIdx.y * 64, k0 = blockIdx.z * 64;
    __shared__ float Qs[64][68];
    __shared__ float Ks[64][68];
    int tid = threadIdx.x;
    int r = tid >> 2, dg = (tid & 3) * 16;
    {
        const float* qp = g_q + (size_t)(b * LSEQ + q0 + r) * D + h * DH + dg;
        const float* kp = g_k + (size_t)(b * LSEQ + k0 + r) * D + h * DH + dg;
        #pragma unroll
        for (int u = 0; u < 4; u++) {
            *(float4*)&Qs[r][dg + u * 4] = *(const float4*)(qp + u * 4);
            *(float4*)&Ks[r][dg + u * 4] = *(const float4*)(kp + u * 4);
        }
    }
    __syncthreads();
    int wid = tid >> 5, lane = tid & 31;
    int wm = wid & 3, wn = wid >> 2;
    int g = lane >> 2, t4 = lane & 3;
    int m0 = wm * 16;

    float acc[4][4];
    #pragma unroll
    for (int j = 0; j < 4; j++)
        #pragma unroll
        for (int q = 0; q < 4; q++) acc[j][q] = 0.f;

    #pragma unroll
    for (int ks = 0; ks < 64; ks += 8) {
        unsigned ah[4], al[4];
        tf_split(Qs[m0 + g    ][ks + t4    ], ah[0], al[0]);
        tf_split(Qs[m0 + g + 8][ks + t4    ], ah[1], al[1]);
        tf_split(Qs[m0 + g    ][ks + t4 + 4], ah[2], al[2]);
        tf_split(Qs[m0 + g + 8][ks + t4 + 4], ah[3], al[3]);
        #pragma unroll
        for (int nf = 0; nf < 4; nf++) {
            int nn = wn * 32 + nf * 8 + g;
            unsigned bh2[2], bl2[2];
            tf_split(Ks[nn][ks + t4    ], bh2[0], bl2[0]);
            tf_split(Ks[nn][ks + t4 + 4], bh2[1], bl2[1]);
            mma_tf32(acc[nf], al, bh2);
            mma_tf32(acc[nf], ah, bl2);
            mma_tf32(acc[nf], ah, bh2);
        }
    }
    int row0 = bh * LSEQ + q0 + m0 + g;
    #pragma unroll
    for (int nf = 0; nf < 4; nf++) {
        int c0 = k0 + wn * 32 + nf * 8 + t4 * 2;
        float mb0 = (tokens[b * LSEQ + c0] != 0) ? 0.f : NEGV;
        float mb1 = (tokens[b * LSEQ + c0 + 1] != 0) ? 0.f : NEGV;
        *(float2*)&g_sc[(size_t)row0 * LSEQ + c0] =
            make_float2(acc[nf][0] * 0.125f + mb0, acc[nf][1] * 0.125f + mb1);
        *(float2*)&g_sc[(size_t)(row0 + 8) * LSEQ + c0] =
            make_float2(acc[nf][2] * 0.125f + mb0, acc[nf][3] * 0.125f + mb1);
    }
}

__global__ void __launch_bounds__(128) softmax_kernel() {
    int row = blockIdx.x * 4 + (threadIdx.x >> 5);
    int lane = threadIdx.x & 31;
    float* p = g_sc + (size_t)row * LSEQ;
    float v[8];
    float m = -INFINITY;
    #pragma unroll
    for (int i = 0; i < 8; i++) { v[i] = p[lane + 32 * i]; m = fmaxf(m, v[i]); }
    m = warp_max(m);
    float s = 0.f;
    #pragma unroll
    for (int i = 0; i < 8; i++) { v[i] = expf(v[i] - m); s += v[i]; }
    s = warp_sum(s);
    float inv = 1.f / s;
    #pragma unroll
    for (int i = 0; i < 8; i++) p[lane + 32 * i] = v[i] * inv;
}

// ---- tensor-core AV (3xTF32) ----
__global__ void __launch_bounds__(256) attn_av_tc() {
    int bh = blockIdx.x;
    int b = bh >> 1, h = bh & 1;
    int l0 = blockIdx.y * 128;
    __shared__ float Ps[128][36];
    __shared__ float Vs[32][68];
    int tid = threadIdx.x;
    int wid = tid >> 5, lane = tid & 31;
    int wm = wid & 3, wn = wid >> 2;
    int g = lane >> 2, t4 = lane & 3;

    float acc[2][4][4];
    #pragma unroll
    for (int i = 0; i < 2; i++)
        #pragma unroll
        for (int j = 0; j < 4; j++)
            #pragma unroll
            for (int q = 0; q < 4; q++) acc[i][j][q] = 0.f;

    int pr = tid >> 1, pk = (tid & 1) * 16;
    int vr = tid >> 3, vd = (tid & 7) * 8;

    for (int kc = 0; kc < 8; kc++) {
        const float* pp = g_sc + (size_t)(bh * LSEQ + l0 + pr) * LSEQ + kc * 32 + pk;
        #pragma unroll
        for (int u = 0; u < 4; u++)
            *(float4*)&Ps[pr][pk + u * 4] = *(const float4*)(pp + u * 4);
        const float* vp = g_v + (size_t)(b * LSEQ + kc * 32 + vr) * D + h * DH + vd;
        #pragma unroll
        for (int u = 0; u < 2; u++)
            *(float4*)&Vs[vr][vd + u * 4] = *(const float4*)(vp + u * 4);
        __syncthreads();
        #pragma unroll
        for (int ks = 0; ks < 32; ks += 8) {
            unsigned ah[2][4], al[2][4];
            #pragma unroll
            for (int mf = 0; mf < 2; mf++) {
                int mm = wm * 32 + mf * 16;
                tf_split(Ps[mm + g    ][ks + t4    ], ah[mf][0], al[mf][0]);
                tf_split(Ps[mm + g + 8][ks + t4    ], ah[mf][1], al[mf][1]);
                tf_split(Ps[mm + g    ][ks + t4 + 4], ah[mf][2], al[mf][2]);
                tf_split(Ps[mm + g + 8][ks + t4 + 4], ah[mf][3], al[mf][3]);
            }
            #pragma unroll
            for (int nf = 0; nf < 4; nf++) {
                int nn = wn * 32 + nf * 8 + g;
                unsigned bh2[2], bl2[2];
                tf_split(Vs[ks + t4    ][nn], bh2[0], bl2[0]);
                tf_split(Vs[ks + t4 + 4][nn], bh2[1], bl2[1]);
                #pragma unroll
                for (int mf = 0; mf < 2; mf++) {
                    mma_tf32(acc[mf][nf], al[mf], bh2);
                    mma_tf32(acc[mf][nf], ah[mf], bl2);
                    mma_tf32(acc[mf][nf], ah[mf], bh2);
                }
            }
        }
        __syncthreads();
    }
    #pragma unroll
    for (int mf = 0; mf < 2; mf++) {
        int r0 = b * LSEQ + l0 + wm * 32 + mf * 16 + g;
        #pragma unroll
        for (int nf = 0; nf < 4; nf++) {
            int c0 = h * DH + wn * 32 + nf * 8 + t4 * 2;
            *(float2*)&g_ao[(size_t)r0 * D + c0] = make_float2(acc[mf][nf][0], acc[mf][nf][1]);
            *(float2*)&g_ao[(size_t)(r0 + 8) * D + c0] = make_float2(acc[mf][nf][2], acc[mf][nf][3]);
        }
    }
}

__global__ void __launch_bounds__(128) add_ln_kernel(const float* __restrict__ g,
                                                     const float* __restrict__ b) {
    int row = blockIdx.x, tid = threadIdx.x;
    int w = tid >> 5, lane = tid & 31;
    float v = g_x[(size_t)row * D + tid] + g_tmp[(size_t)row * D + tid];
    float s = warp_sum(v);
    float s2 = warp_sum(v * v);
    __shared__ float ws[4], ws2[4];
    if (lane == 0) { ws[w] = s; ws2[w] = s2; }
    __syncthreads();
    s = ws[0] + ws[1] + ws[2] + ws[3];
    s2 = ws2[0] + ws2[1] + ws2[2] + ws2[3];
    float m = s * (1.f / D);
    float var = s2 * (1.f / D) - m * m;
    float inv = rsqrtf(var + 1e-5f);
    g_x[(size_t)row * D + tid] = (v - m) * inv * g[tid] + b[tid];
}

// ---------------- pooling / gate / final ----------------
__global__ void __launch_bounds__(128) tok_pool_kernel(const int* __restrict__ tokens,
                                                       const float* __restrict__ vvec) {
    int b = blockIdx.x, tid = threadIdx.x;
    int w = tid >> 5, lane = tid & 31;
    __shared__ float s_s[LSEQ];
    __shared__ float red[4];
    for (int l = w; l < LSEQ; l += 4) {
        float val = 0.f;
        #pragma unroll
        for (int d = lane; d < D; d += 32)
            val += tanhf(g_ffn[((size_t)(b * LSEQ + l)) * D + d]) * vvec[d];
        val = warp_sum(val);
        if (lane == 0) s_s[l] = (tokens[b * LSEQ + l] != 0) ? val : NEGV;
    }
    __syncthreads();
    float m = fmaxf(s_s[tid], s_s[tid + 128]);
    m = warp_max(m);
    if (lane == 0) red[w] = m;
    __syncthreads();
    m = fmaxf(fmaxf(red[0], red[1]), fmaxf(red[2], red[3]));
    __syncthreads();
    float e0 = expf(s_s[tid] - m), e1 = expf(s_s[tid + 128] - m);
    float ssum = warp_sum(e0 + e1);
    if (lane == 0) red[w] = ssum;
    __syncthreads();
    ssum = red[0] + red[1] + red[2] + red[3];
    float inv = 1.f / ssum;
    __syncthreads();
    s_s[tid] = e0 * inv; s_s[tid + 128] = e1 * inv;
    __syncthreads();
    float acc = 0.f;
    for (int l = 0; l < LSEQ; l++)
        acc = fmaf(s_s[l], g_x[((size_t)(b * LSEQ + l)) * D + tid], acc);
    g_trep[b * D + tid] = acc;
}

__global__ void __launch_bounds__(128) ent_pool_kernel(const int* __restrict__ ctx,
                                                       const float* __restrict__ Wa,
                                                       const float* __restrict__ ba,
                                                       const float* __restrict__ vvec) {
    int b = blockIdx.x, tid = threadIdx.x;
    int w = tid >> 5, lane = tid & 31;
    __shared__ float h_s[NCTX][D];
    __shared__ float s_s[NCTX];
    __shared__ int cs[NCTX];
    if (tid < NCTX) cs[tid] = ctx[b * NCTX + tid];
    __syncthreads();
    for (int j = 0; j < NCTX; j++)
        h_s[j][tid] = g_kg[(size_t)cs[j] * D + tid];
    __syncthreads();
    for (int j = w; j < NCTX; j += 4) {
        float val = 0.f;
        for (int d = lane; d < D; d += 32) {
            float acc = ba[d];
            #pragma unroll 8
            for (int kk = 0; kk < D; kk++)
                acc = fmaf(h_s[j][kk], Wa[kk * D + d], acc);
            val += tanhf(acc) * vvec[d];
        }
        val = warp_sum(val);
        if (lane == 0) s_s[j] = (cs[j] != 0) ? val : NEGV;
    }
    __syncthreads();
    if (w == 0) {
        float sv = s_s[lane];
        float m = warp_max(sv);
        float e = expf(sv - m);
        float ssum = warp_sum(e);
        s_s[lane] = e / ssum;
    }
    __syncthreads();
    float acc = 0.f;
    #pragma unroll
    for (int j = 0; j < NCTX; j++) acc = fmaf(s_s[j], h_s[j][tid], acc);
    g_erep[b * D + tid] = acc;
}

__global__ void __launch_bounds__(128) gate_kernel(const float* __restrict__ Wg,
                                                   const float* __restrict__ bg) {
    int b = blockIdx.x, tid = threadIdx.x;
    __shared__ float cat[2 * D];
    cat[tid] = g_trep[b * D + tid];
    cat[D + tid] = g_erep[b * D + tid];
    __syncthreads();
    float acc = bg[tid];
    #pragma unroll 8
    for (int j = 0; j < 2 * D; j++) acc = fmaf(cat[j], Wg[j * D + tid], acc);
    float sg = 1.f / (1.f + expf(-acc));
    g_user[b * D + tid] = sg * cat[tid] + (1.f - sg) * cat[D + tid];
}

__global__ void __launch_bounds__(256) final_kernel(float* __restrict__ out) {
    __shared__ float kg_s[128][17];
    __shared__ float user_t[D][BATCH];
    int n0 = blockIdx.x * 128, tid = threadIdx.x;
    for (int i = tid; i < D * BATCH; i += 256) {
        int d = i >> 6, bb = i & 63;
        user_t[d][bb] = g_user[bb * D + d];
    }
    int tn = tid >> 3, tb = tid & 7;
    float acc[4][8];
    #pragma unroll
    for (int i = 0; i < 4; i++)
        #pragma unroll
        for (int j = 0; j < 8; j++) acc[i][j] = 0.f;
    for (int dc = 0; dc < D; dc += 16) {
        __syncthreads();
        for (int i = tid; i < 128 * 16; i += 256) {
            int nl = i >> 4, dd = i & 15;
            int n = n0 + nl;
            kg_s[nl][dd] = (n < NE) ? g_kg[(size_t)n * D + dc + dd] : 0.f;
        }
        __syncthreads();
        #pragma unroll
        for (int dd = 0; dd < 16; dd++) {
            float kv[4], uv[8];
            #pragma unroll
            for (int i = 0; i < 4; i++) kv[i] = kg_s[tn * 4 + i][dd];
            #pragma unroll
            for (int j = 0; j < 8; j++) uv[j] = user_t[dc + dd][tb * 8 + j];
            #pragma unroll
            for (int i = 0; i < 4; i++)
                #pragma unroll
                for (int j = 0; j < 8; j++) acc[i][j] = fmaf(kv[i], uv[j], acc[i][j]);
        }
    }
    #pragma unroll
    for (int i = 0; i < 4; i++) {
        int n = n0 + tn * 4 + i;
        if (n < NE) {
            #pragma unroll
            for (int j = 0; j < 8; j++)
                out[(size_t)(tb * 8 + j) * NE + n] = acc[i][j];
        }
    }
}

// ---------------- launch ----------------
extern "C" void kernel_launch(void* const* d_in, const int* in_sizes, int n_in,
                              void* d_out, int out_size) {
    const int*   edge_idx = (const int*)d_in[0];
    const int*   edge_type = (const int*)d_in[1];
    const int*   ctx_ent  = (const int*)d_in[2];
    const int*   ctx_tok  = (const int*)d_in[3];
    const float* basis    = (const float*)d_in[4];
    const float* comp     = (const float*)d_in[5];
    const float* root     = (const float*)d_in[6];
    const float* rgcn_b   = (const float*)d_in[7];
    const float* tok_emb  = (const float*)d_in[8];
    const float* pos_emb  = (const float*)d_in[9];
    const float* Wqkv     = (const float*)d_in[10];
    const float* Wo       = (const float*)d_in[11];
    const float* ln1_g    = (const float*)d_in[12];
    const float* ln1_b    = (const float*)d_in[13];
    const float* ln2_g    = (const float*)d_in[14];
    const float* ln2_b    = (const float*)d_in[15];
    const float* W1       = (const float*)d_in[16];
    const float* b1       = (const float*)d_in[17];
    const float* W2       = (const float*)d_in[18];
    const float* b2       = (const float*)d_in[19];
    const float* ent_Wa   = (const float*)d_in[20];
    const float* ent_ba   = (const float*)d_in[21];
    const float* ent_v    = (const float*)d_in[22];
    const float* tok_Wa   = (const float*)d_in[23];
    const float* tok_ba   = (const float*)d_in[24];
    const float* tok_v    = (const float*)d_in[25];
    const float* Wg       = (const float*)d_in[26];
    const float* bg       = (const float*)d_in[27];
    float* out = (float*)d_out;

    const int M = BATCH * LSEQ;  // 16384

    // --- encoder FIRST (QKV GEMM stays at the ncu-profiled launch slot) ---
    init_ptrs_kernel<<<1, 1>>>();
    zero_cnt_kernel<<<(NE * NREL + 255) / 256, 256>>>();
    embed_kernel<<<(BATCH * LSEQ * D) / 256, 256>>>(ctx_tok, tok_emb, pos_emb);
    for (int l = 0; l < NLAY; l++) {
        gemm_tc_kernel<<<dim3(M / 128, 3), 256>>>(Wqkv + (size_t)l * 3 * D * D, nullptr, BUF_X, BUF_Q, M, D, D, 0, 1);
        attn_scores_tc<<<dim3(BATCH * NHEAD, LSEQ / 64, LSEQ / 64), 256>>>(ctx_tok);
        softmax_kernel<<<(BATCH * NHEAD * LSEQ) / 4, 128>>>();
        attn_av_tc<<<dim3(BATCH * NHEAD, LSEQ / 128), 256>>>();
        gemm_tc_kernel<<<dim3(M / 128, 1), 256>>>(Wo + (size_t)l * D * D, nullptr, BUF_AO, BUF_TMP, M, D, D, 0, 0);
        add_ln_kernel<<<M, 128>>>(ln1_g + l * D, ln1_b + l * D);
        gemm_tc_kernel<<<dim3(M / 128, FFND / 128), 256>>>(W1 + (size_t)l * D * FFND, b1 + l * FFND, BUF_X, BUF_FFN, M, FFND, D, 1, 0);
        gemm_tc_kernel<<<dim3(M / 128, 1), 256>>>(W2 + (size_t)l * FFND * D, b2 + l * D, BUF_FFN, BUF_TMP, M, D, FFND, 0, 0);
        add_ln_kernel<<<M, 128>>>(ln2_g + l * D, ln2_b + l * D);
    }
    gemm_tc_kernel<<<dim3(M / 128, 1), 256>>>(tok_Wa, tok_ba, BUF_X, BUF_FFN, M, D, D, 0, 0);

    // --- RGCN (CSR, no atomics on kg) ---
    rgcn_w_kernel<<<NE, 128>>>(basis, comp, root, rgcn_b);
    count_kernel<<<(NEDGE + 255) / 256, 256>>>(edge_idx, edge_type);
    scan_kernel<<<1, 1024>>>();
    fill_kernel<<<(NEDGE + 255) / 256, 256>>>(edge_idx, edge_type);
    agg_kernel<<<(NE * 32 + 255) / 256, 256>>>();

    // --- pooling / gate / score ---
    tok_pool_kernel<<<BATCH, 128>>>(ctx_tok, tok_v);
    ent_pool_kernel<<<BATCH, 128>>>(ctx_ent, ent_Wa, ent_ba, ent_v);
    gate_kernel<<<BATCH, 128>>>(Wg, bg);
    final_kernel<<<(NE + 127) / 128, 256>>>(out);
}

// round 11
// speedup vs baseline: 1.1280x; 1.0218x over previous
#include <cuda_runtime.h>
#include <cuda_bf16.h>
#include <math.h>

#define NE      30000
#define NREL    18
#define NB      8
#define D       128
#define NEDGE   1000000
#define BATCH   64
#define LSEQ    256
#define NCTX    32
#define NHEAD   2
#define DH      64
#define FFND    512
#define NLAY    2
#define NEGV    (-1e9f)

// ---------------- device scratch (static, referenced ONLY in device code) ---
static __device__ float g_W[(size_t)NREL * NE * D];     // 276 MB
static __device__ float g_kg[(size_t)NE * D];
static __device__ int   g_cnt[NE * NREL];
static __device__ int   g_off[NE + 1];
static __device__ int   g_cur[NE];
static __device__ int   g_elist[NEDGE];
static __device__ float g_x [BATCH * LSEQ * D];
static __device__ float g_q [BATCH * LSEQ * D];
static __device__ float g_k [BATCH * LSEQ * D];
static __device__ float g_v [BATCH * LSEQ * D];
static __device__ float g_sc[(size_t)BATCH * NHEAD * LSEQ * LSEQ]; // 33.5MB
static __device__ float g_ao[BATCH * LSEQ * D];
static __device__ float g_tmp[BATCH * LSEQ * D];
static __device__ float g_ffn[BATCH * LSEQ * FFND];
static __device__ float g_trep[BATCH * D];
static __device__ float g_erep[BATCH * D];
static __device__ float g_user[BATCH * D];
static __device__ float* g_bufs[8];

#define BUF_X   0
#define BUF_Q   1
#define BUF_K   2
#define BUF_V   3
#define BUF_AO  4
#define BUF_TMP 5
#define BUF_FFN 6

__global__ void init_ptrs_kernel() {
    g_bufs[BUF_X] = g_x;  g_bufs[BUF_Q] = g_q;  g_bufs[BUF_K] = g_k;
    g_bufs[BUF_V] = g_v;  g_bufs[BUF_AO] = g_ao; g_bufs[BUF_TMP] = g_tmp;
    g_bufs[BUF_FFN] = g_ffn;
}

// ---------------- helpers ----------------
__device__ __forceinline__ float warp_sum(float v) {
    #pragma unroll
    for (int o = 16; o > 0; o >>= 1) v += __shfl_xor_sync(0xFFFFFFFFu, v, o);
    return v;
}
__device__ __forceinline__ float warp_max(float v) {
    #pragma unroll
    for (int o = 16; o > 0; o >>= 1) v = fmaxf(v, __shfl_xor_sync(0xFFFFFFFFu, v, o));
    return v;
}
// bf16 m16n8k16
__device__ __forceinline__ void mma_bf16(float* c, const unsigned* a, const unsigned* b) {
    asm volatile(
        "mma.sync.aligned.m16n8k16.row.col.f32.bf16.bf16.f32 "
        "{%0,%1,%2,%3}, {%4,%5,%6,%7}, {%8,%9}, {%0,%1,%2,%3};\n"
        : "+f"(c[0]), "+f"(c[1]), "+f"(c[2]), "+f"(c[3])
        : "r"(a[0]), "r"(a[1]), "r"(a[2]), "r"(a[3]), "r"(b[0]), "r"(b[1]));
}
// split two floats (consecutive k) into packed bf16x2 hi and lo words
__device__ __forceinline__ void bf_split2(float x0, float x1, unsigned& hi, unsigned& lo) {
    __nv_bfloat16 h0 = __float2bfloat16_rn(x0);
    __nv_bfloat16 h1 = __float2bfloat16_rn(x1);
    __nv_bfloat16 l0 = __float2bfloat16_rn(__fsub_rn(x0, __bfloat162float(h0)));
    __nv_bfloat16 l1 = __float2bfloat16_rn(__fsub_rn(x1, __bfloat162float(h1)));
    __nv_bfloat162 hp = __halves2bfloat162(h0, h1);
    __nv_bfloat162 lp = __halves2bfloat162(l0, l1);
    hi = *(unsigned*)&hp;
    lo = *(unsigned*)&lp;
}

// ---------------- RGCN ----------------
__global__ void __launch_bounds__(256) zero_cnt_kernel() {
    int i = blockIdx.x * blockDim.x + threadIdx.x;
    if (i < NE * NREL) g_cnt[i] = 0;
}

__global__ void __launch_bounds__(128) rgcn_w_kernel(const float* __restrict__ basis,
                                                     const float* __restrict__ comp,
                                                     const float* __restrict__ root,
                                                     const float* __restrict__ bias) {
    int n = blockIdx.x, d = threadIdx.x;
    __shared__ float sc[NREL * NB];
    for (int i = d; i < NREL * NB; i += 128) sc[i] = comp[i];
    __syncthreads();
    float bb[NB];
    #pragma unroll
    for (int q = 0; q < NB; q++) bb[q] = basis[((size_t)q * NE + n) * D + d];
    #pragma unroll
    for (int r = 0; r < NREL; r++) {
        float a = 0.f;
        #pragma unroll
        for (int q = 0; q < NB; q++) a = fmaf(sc[r * NB + q], bb[q], a);
        g_W[((size_t)r * NE + n) * D + d] = a;
    }
    g_kg[(size_t)n * D + d] = root[(size_t)n * D + d] + bias[d];
}

__global__ void __launch_bounds__(256) count_kernel(const int* __restrict__ ei,
                                                    const int* __restrict__ et) {
    int e = blockIdx.x * blockDim.x + threadIdx.x;
    if (e < NEDGE) {
        int dst = ei[NEDGE + e];
        atomicAdd(&g_cnt[dst * NREL + et[e]], 1);
    }
}

__global__ void __launch_bounds__(1024) scan_kernel() {
    __shared__ int warp_sums[32];
    __shared__ int carry_s;
    int tid = threadIdx.x, lane = tid & 31, w = tid >> 5;
    if (tid == 0) carry_s = 0;
    __syncthreads();
    for (int base = 0; base < NE; base += 1024) {
        int i = base + tid;
        int v = 0;
        if (i < NE) {
            #pragma unroll
            for (int r = 0; r < NREL; r++) v += g_cnt[i * NREL + r];
        }
        int x = v;
        #pragma unroll
        for (int o = 1; o < 32; o <<= 1) {
            int y = __shfl_up_sync(0xFFFFFFFFu, x, o);
            if (lane >= o) x += y;
        }
        if (lane == 31) warp_sums[w] = x;
        __syncthreads();
        if (w == 0) {
            int s = warp_sums[lane];
            #pragma unroll
            for (int o = 1; o < 32; o <<= 1) {
                int y = __shfl_up_sync(0xFFFFFFFFu, s, o);
                if (lane >= o) s += y;
            }
            warp_sums[lane] = s;
        }
        __syncthreads();
        int block_excl = (w > 0) ? warp_sums[w - 1] : 0;
        int excl = carry_s + block_excl + x - v;
        if (i < NE) { g_off[i] = excl; g_cur[i] = excl; }
        __syncthreads();
        if (tid == 0) carry_s += warp_sums[31];
        __syncthreads();
    }
    if (tid == 0) g_off[NE] = carry_s;
}

__global__ void __launch_bounds__(256) fill_kernel(const int* __restrict__ ei,
                                                   const int* __restrict__ et) {
    int e = blockIdx.x * blockDim.x + threadIdx.x;
    if (e >= NEDGE) return;
    int dst = ei[NEDGE + e];
    int pos = atomicAdd(&g_cur[dst], 1);
    g_elist[pos] = ei[e] | (et[e] << 16);
}

__global__ void __launch_bounds__(256) agg_kernel() {
    int gw = (blockIdx.x * blockDim.x + threadIdx.x) >> 5;
    int lane = threadIdx.x & 31;
    if (gw >= NE) return;
    int off = g_off[gw], end = g_off[gw + 1];
    float a0 = 0.f, a1 = 0.f, a2 = 0.f, a3 = 0.f;
    for (int b = off; b < end; b += 32) {
        int n = min(32, end - b);
        int pk = (b + lane < end) ? g_elist[b + lane] : 0;
        int j = 0;
        for (; j + 4 <= n; j += 4) {
            int p0 = __shfl_sync(0xFFFFFFFFu, pk, j);
            int p1 = __shfl_sync(0xFFFFFFFFu, pk, j + 1);
            int p2 = __shfl_sync(0xFFFFFFFFu, pk, j + 2);
            int p3 = __shfl_sync(0xFFFFFFFFu, pk, j + 3);
            float4 v0 = *(const float4*)(g_W + ((size_t)(p0 >> 16) * NE + (p0 & 0xFFFF)) * D + lane * 4);
            float4 v1 = *(const float4*)(g_W + ((size_t)(p1 >> 16) * NE + (p1 & 0xFFFF)) * D + lane * 4);
            float4 v2 = *(const float4*)(g_W + ((size_t)(p2 >> 16) * NE + (p2 & 0xFFFF)) * D + lane * 4);
            float4 v3 = *(const float4*)(g_W + ((size_t)(p3 >> 16) * NE + (p3 & 0xFFFF)) * D + lane * 4);
            float n0 = 1.f / fmaxf((float)g_cnt[gw * NREL + (p0 >> 16)], 1.f);
            float n1 = 1.f / fmaxf((float)g_cnt[gw * NREL + (p1 >> 16)], 1.f);
            float n2 = 1.f / fmaxf((float)g_cnt[gw * NREL + (p2 >> 16)], 1.f);
            float n3 = 1.f / fmaxf((float)g_cnt[gw * NREL + (p3 >> 16)], 1.f);
            a0 = fmaf(v0.x, n0, a0); a1 = fmaf(v0.y, n0, a1); a2 = fmaf(v0.z, n0, a2); a3 = fmaf(v0.w, n0, a3);
            a0 = fmaf(v1.x, n1, a0); a1 = fmaf(v1.y, n1, a1); a2 = fmaf(v1.z, n1, a2); a3 = fmaf(v1.w, n1, a3);
            a0 = fmaf(v2.x, n2, a0); a1 = fmaf(v2.y, n2, a1); a2 = fmaf(v2.z, n2, a2); a3 = fmaf(v2.w, n2, a3);
            a0 = fmaf(v3.x, n3, a0); a1 = fmaf(v3.y, n3, a1); a2 = fmaf(v3.z, n3, a2); a3 = fmaf(v3.w, n3, a3);
        }
        for (; j < n; j++) {
            int p = __shfl_sync(0xFFFFFFFFu, pk, j);
            int src = p & 0xFFFF, r = p >> 16;
            float norm = 1.f / fmaxf((float)g_cnt[gw * NREL + r], 1.f);
            float4 v = *(const float4*)(g_W + ((size_t)r * NE + src) * D + lane * 4);
            a0 = fmaf(v.x, norm, a0); a1 = fmaf(v.y, norm, a1);
            a2 = fmaf(v.z, norm, a2); a3 = fmaf(v.w, norm, a3);
        }
    }
    float* o = g_kg + (size_t)gw * D + lane * 4;
    float4 cur = *(float4*)o;
    *(float4*)o = make_float4(cur.x + a0, cur.y + a1, cur.z + a2, cur.w + a3);
}

// ---------------- encoder ----------------
__global__ void __launch_bounds__(256) embed_kernel(const int* __restrict__ tokens,
                                                    const float* __restrict__ tok_emb,
                                                    const float* __restrict__ pos_emb) {
    int i = blockIdx.x * blockDim.x + threadIdx.x;
    int d = i & (D - 1);
    int bl = i >> 7;
    int l = bl & (LSEQ - 1);
    int tk = tokens[bl];
    g_x[i] = tok_emb[(size_t)tk * D + d] * 11.3137084989847603904f + pos_emb[l * D + d];
}

// ---- split-bf16 tensor-core GEMM (unchanged from R10) ----
__global__ void __launch_bounds__(256, 2) gemm_tc_kernel(const float* __restrict__ Bw,
                                                         const float* __restrict__ bias,
                                                         int asel, int csel,
                                                         int M, int N, int K, int relu,
                                                         int qkv_mode) {
    int n0;
    if (qkv_mode) { Bw += (size_t)blockIdx.y * D * D; csel += blockIdx.y; n0 = 0; }
    else n0 = blockIdx.y * 128;
    const float* __restrict__ A = g_bufs[asel];
    float* __restrict__ C = g_bufs[csel];
    __shared__ unsigned Ah_s[128][12], Al_s[128][12];
    __shared__ unsigned Bh_s[128][12], Bl_s[128][12];
    int m0 = blockIdx.x * 128;
    int tid = threadIdx.x;
    int wid = tid >> 5, lane = tid & 31;
    int wm = wid & 3, wn = wid >> 2;
    int g = lane >> 2, t4 = lane & 3;

    float acc[2][8][4];
    #pragma unroll
    for (int i = 0; i < 2; i++)
        #pragma unroll
        for (int j = 0; j < 8; j++)
            #pragma unroll
            for (int q = 0; q < 4; q++) acc[i][j][q] = 0.f;

    int ar = tid >> 1, aw = (tid & 1) * 4;
    int bkp = tid & 7, bn4 = (tid >> 3) * 4;

    float4 pa0, pa1, pb0, pb1;
    {
        const float* ap = A + (size_t)(m0 + ar) * K + aw * 2;
        pa0 = *(const float4*)ap; pa1 = *(const float4*)(ap + 4);
        pb0 = *(const float4*)(Bw + (size_t)(2 * bkp)     * N + n0 + bn4);
        pb1 = *(const float4*)(Bw + (size_t)(2 * bkp + 1) * N + n0 + bn4);
    }

    for (int kc = 0; kc < K; kc += 16) {
        {
            float av[8] = {pa0.x, pa0.y, pa0.z, pa0.w, pa1.x, pa1.y, pa1.z, pa1.w};
            unsigned h4[4], l4[4];
            #pragma unroll
            for (int i = 0; i < 4; i++) bf_split2(av[2 * i], av[2 * i + 1], h4[i], l4[i]);
            *(uint4*)&Ah_s[ar][aw] = make_uint4(h4[0], h4[1], h4[2], h4[3]);
            *(uint4*)&Al_s[ar][aw] = make_uint4(l4[0], l4[1], l4[2], l4[3]);
            float b0v[4] = {pb0.x, pb0.y, pb0.z, pb0.w};
            float b1v[4] = {pb1.x, pb1.y, pb1.z, pb1.w};
            #pragma unroll
            for (int i = 0; i < 4; i++) {
                unsigned hw, lw;
                bf_split2(b0v[i], b1v[i], hw, lw);
                Bh_s[bn4 + i][bkp] = hw;
                Bl_s[bn4 + i][bkp] = lw;
            }
        }
        __syncthreads();
        if (kc + 16 < K) {
            const float* ap = A + (size_t)(m0 + ar) * K + kc + 16 + aw * 2;
            pa0 = *(const float4*)ap; pa1 = *(const float4*)(ap + 4);
            pb0 = *(const float4*)(Bw + (size_t)(kc + 16 + 2 * bkp)     * N + n0 + bn4);
            pb1 = *(const float4*)(Bw + (size_t)(kc + 16 + 2 * bkp + 1) * N + n0 + bn4);
        }
        {
            unsigned ah[2][4], al_[2][4];
            #pragma unroll
            for (int mf = 0; mf < 2; mf++) {
                int mm = wm * 32 + mf * 16;
                ah[mf][0] = Ah_s[mm + g    ][t4    ];  al_[mf][0] = Al_s[mm + g    ][t4    ];
                ah[mf][1] = Ah_s[mm + g + 8][t4    ];  al_[mf][1] = Al_s[mm + g + 8][t4    ];
                ah[mf][2] = Ah_s[mm + g    ][t4 + 4];  al_[mf][2] = Al_s[mm + g    ][t4 + 4];
                ah[mf][3] = Ah_s[mm + g + 8][t4 + 4];  al_[mf][3] = Al_s[mm + g + 8][t4 + 4];
            }
            #pragma unroll
            for (int nf = 0; nf < 8; nf++) {
                int nn = wn * 64 + nf * 8 + g;
                unsigned bh2[2] = {Bh_s[nn][t4], Bh_s[nn][t4 + 4]};
                unsigned bl2[2] = {Bl_s[nn][t4], Bl_s[nn][t4 + 4]};
                #pragma unroll
                for (int mf = 0; mf < 2; mf++) {
                    mma_bf16(acc[mf][nf], al_[mf], bh2);
                    mma_bf16(acc[mf][nf], ah[mf], bl2);
                    mma_bf16(acc[mf][nf], ah[mf], bh2);
                }
            }
        }
        __syncthreads();
    }
    #pragma unroll
    for (int mf = 0; mf < 2; mf++) {
        int r0 = m0 + wm * 32 + mf * 16 + g;
        #pragma unroll
        for (int nf = 0; nf < 8; nf++) {
            int c0 = n0 + wn * 64 + nf * 8 + t4 * 2;
            float bb0 = bias ? bias[c0] : 0.f;
            float bb1 = bias ? bias[c0 + 1] : 0.f;
            float v0 = acc[mf][nf][0] + bb0, v1 = acc[mf][nf][1] + bb1;
            float v2 = acc[mf][nf][2] + bb0, v3 = acc[mf][nf][3] + bb1;
            if (relu) {
                v0 = fmaxf(v0, 0.f); v1 = fmaxf(v1, 0.f);
                v2 = fmaxf(v2, 0.f); v3 = fmaxf(v3, 0.f);
            }
            *(float2*)&C[(size_t)r0 * N + c0]       = make_float2(v0, v1);
            *(float2*)&C[(size_t)(r0 + 8) * N + c0] = make_float2(v2, v3);
        }
    }
}

// ---- split-bf16 attention scores: 64q x 64k tile, d=64 ----
// Q/K pre-split once per block into packed bf16x2 hi/lo smem ([row][d-pair], stride 36).
__global__ void __launch_bounds__(256, 2) attn_scores_tc(const int* __restrict__ tokens) {
    int bh = blockIdx.x;
    int b = bh >> 1, h = bh & 1;
    int q0 = blockIdx.y * 64, k0 = blockIdx.z * 64;
    __shared__ unsigned Qh[64][36], Ql[64][36];
    __shared__ unsigned Kh[64][36], Kl[64][36];
    int tid = threadIdx.x;
    {   // fill: r = row, c8 = word base (8 words = 16 floats per thread per tensor)
        int r = tid >> 2, c8 = (tid & 3) * 8;
        const float* qp = g_q + (size_t)(b * LSEQ + q0 + r) * D + h * DH + c8 * 2;
        const float* kp = g_k + (size_t)(b * LSEQ + k0 + r) * D + h * DH + c8 * 2;
        float qf[16], kf[16];
        #pragma unroll
        for (int u = 0; u < 4; u++) {
            *(float4*)&qf[u * 4] = *(const float4*)(qp + u * 4);
            *(float4*)&kf[u * 4] = *(const float4*)(kp + u * 4);
        }
        #pragma unroll
        for (int i = 0; i < 8; i++) {
            unsigned hw, lw;
            bf_split2(qf[2 * i], qf[2 * i + 1], hw, lw);
            Qh[r][c8 + i] = hw; Ql[r][c8 + i] = lw;
            bf_split2(kf[2 * i], kf[2 * i + 1], hw, lw);
            Kh[r][c8 + i] = hw; Kl[r][c8 + i] = lw;
        }
    }
    __syncthreads();
    int wid = tid >> 5, lane = tid & 31;
    int wm = wid & 3, wn = wid >> 2;   // 4 q-warps x 2 key-warps; warp tile 16x32
    int g = lane >> 2, t4 = lane & 3;
    int m0 = wm * 16;

    float acc[4][4];
    #pragma unroll
    for (int j = 0; j < 4; j++)
        #pragma unroll
        for (int q = 0; q < 4; q++) acc[j][q] = 0.f;

    #pragma unroll
    for (int ks = 0; ks < 4; ks++) {     // 4 x k16 steps (d=64)
        int wb = ks * 8;
        unsigned ah[4], al[4];
        ah[0] = Qh[m0 + g    ][wb + t4    ];  al[0] = Ql[m0 + g    ][wb + t4    ];
        ah[1] = Qh[m0 + g + 8][wb + t4    ];  al[1] = Ql[m0 + g + 8][wb + t4    ];
        ah[2] = Qh[m0 + g    ][wb + t4 + 4];  al[2] = Ql[m0 + g    ][wb + t4 + 4];
        ah[3] = Qh[m0 + g + 8][wb + t4 + 4];  al[3] = Ql[m0 + g + 8][wb + t4 + 4];
        #pragma unroll
        for (int nf = 0; nf < 4; nf++) {
            int nn = wn * 32 + nf * 8 + g;
            unsigned bh2[2] = {Kh[nn][wb + t4], Kh[nn][wb + t4 + 4]};
            unsigned bl2[2] = {Kl[nn][wb + t4], Kl[nn][wb + t4 + 4]};
            mma_bf16(acc[nf], al, bh2);
            mma_bf16(acc[nf], ah, bl2);
            mma_bf16(acc[nf], ah, bh2);
        }
    }
    int row0 = bh * LSEQ + q0 + m0 + g;
    #pragma unroll
    for (int nf = 0; nf < 4; nf++) {
        int c0 = k0 + wn * 32 + nf * 8 + t4 * 2;
        float mb0 = (tokens[b * LSEQ + c0] != 0) ? 0.f : NEGV;
        float mb1 = (tokens[b * LSEQ + c0 + 1] != 0) ? 0.f : NEGV;
        *(float2*)&g_sc[(size_t)row0 * LSEQ + c0] =
            make_float2(acc[nf][0] * 0.125f + mb0, acc[nf][1] * 0.125f + mb1);
        *(float2*)&g_sc[(size_t)(row0 + 8) * LSEQ + c0] =
            make_float2(acc[nf][2] * 0.125f + mb0, acc[nf][3] * 0.125f + mb1);
    }
}

__global__ void __launch_bounds__(128) softmax_kernel() {
    int row = blockIdx.x * 4 + (threadIdx.x >> 5);
    int lane = threadIdx.x & 31;
    float* p = g_sc + (size_t)row * LSEQ;
    float v[8];
    float m = -INFINITY;
    #pragma unroll
    for (int i = 0; i < 8; i++) { v[i] = p[lane + 32 * i]; m = fmaxf(m, v[i]); }
    m = warp_max(m);
    float s = 0.f;
    #pragma unroll
    for (int i = 0; i < 8; i++) { v[i] = expf(v[i] - m); s += v[i]; }
    s = warp_sum(s);
    float inv = 1.f / s;
    #pragma unroll
    for (int i = 0; i < 8; i++) p[lane + 32 * i] = v[i] * inv;
}

// ---- split-bf16 AV: o[128l x 64d] = P[128l x 256k] @ V[256k x 64d] ----
// per 32-k chunk: P pre-split [l][k-pair] (stride 20), V transposed-split [d][k-pair].
__global__ void __launch_bounds__(256, 2) attn_av_tc() {
    int bh = blockIdx.x;
    int b = bh >> 1, h = bh & 1;
    int l0 = blockIdx.y * 128;
    __shared__ unsigned Ph[128][20], Pl[128][20];
    __shared__ unsigned Vh[64][20], Vl[64][20];
    int tid = threadIdx.x;
    int wid = tid >> 5, lane = tid & 31;
    int wm = wid & 3, wn = wid >> 2;   // 4 l-warps x 2 d-warps; warp tile 32x32
    int g = lane >> 2, t4 = lane & 3;

    float acc[2][4][4];
    #pragma unroll
    for (int i = 0; i < 2; i++)
        #pragma unroll
        for (int j = 0; j < 4; j++)
            #pragma unroll
            for (int q = 0; q < 4; q++) acc[i][j][q] = 0.f;

    int pr = tid >> 1, pw8 = (tid & 1) * 8;     // P fill: row pr, words pw8..pw8+7
    int td = tid & 63, tk4 = (tid >> 6) * 4;    // V fill: d col td, k-pairs tk4..tk4+3

    for (int kc = 0; kc < 8; kc++) {
        {   // P chunk [128 l][32 k] -> split words
            const float* pp = g_sc + (size_t)(bh * LSEQ + l0 + pr) * LSEQ + kc * 32 + pw8 * 2;
            float pf[16];
            #pragma unroll
            for (int u = 0; u < 4; u++)
                *(float4*)&pf[u * 4] = *(const float4*)(pp + u * 4);
            #pragma unroll
            for (int i = 0; i < 8; i++) {
                unsigned hw, lw;
                bf_split2(pf[2 * i], pf[2 * i + 1], hw, lw);
                Ph[pr][pw8 + i] = hw; Pl[pr][pw8 + i] = lw;
            }
            // V chunk: rows kc*32 + 2kp, 2kp+1; col td
            #pragma unroll
            for (int kp = 0; kp < 4; kp++) {
                int kk = tk4 + kp;
                float v0 = g_v[(size_t)(b * LSEQ + kc * 32 + 2 * kk)     * D + h * DH + td];
                float v1 = g_v[(size_t)(b * LSEQ + kc * 32 + 2 * kk + 1) * D + h * DH + td];
                unsigned hw, lw;
                bf_split2(v0, v1, hw, lw);
                Vh[td][kk] = hw; Vl[td][kk] = lw;
            }
        }
        __syncthreads();
        #pragma unroll
        for (int ks = 0; ks < 2; ks++) {   // 2 x k16 steps per 32-chunk
            int wb = ks * 8;
            unsigned ah[2][4], al_[2][4];
            #pragma unroll
            for (int mf = 0; mf < 2; mf++) {
                int mm = wm * 32 + mf * 16;
                ah[mf][0] = Ph[mm + g    ][wb + t4    ];  al_[mf][0] = Pl[mm + g    ][wb + t4    ];
                ah[mf][1] = Ph[mm + g + 8][wb + t4    ];  al_[mf][1] = Pl[mm + g + 8][wb + t4    ];
                ah[mf][2] = Ph[mm + g    ][wb + t4 + 4];  al_[mf][2] = Pl[mm + g    ][wb + t4 + 4];
                ah[mf][3] = Ph[mm + g + 8][wb + t4 + 4];  al_[mf][3] = Pl[mm + g + 8][wb + t4 + 4];
            }
            #pragma unroll
            for (int nf = 0; nf < 4; nf++) {
                int nn = wn * 32 + nf * 8 + g;
                unsigned bh2[2] = {Vh[nn][wb + t4], Vh[nn][wb + t4 + 4]};
                unsigned bl2[2] = {Vl[nn][wb + t4], Vl[nn][wb + t4 + 4]};
                #pragma unroll
                for (int mf = 0; mf < 2; mf++) {
                    mma_bf16(acc[mf][nf], al_[mf], bh2);
                    mma_bf16(acc[mf][nf], ah[mf], bl2);
                    mma_bf16(acc[mf][nf], ah[mf], bh2);
                }
            }
        }
        __syncthreads();
    }
    #pragma unroll
    for (int mf = 0; mf < 2; mf++) {
        int r0 = b * LSEQ + l0 + wm * 32 + mf * 16 + g;
        #pragma unroll
        for (int nf = 0; nf < 4; nf++) {
            int c0 = h * DH + wn * 32 + nf * 8 + t4 * 2;
            *(float2*)&g_ao[(size_t)r0 * D + c0] = make_float2(acc[mf][nf][0], acc[mf][nf][1]);
            *(float2*)&g_ao[(size_t)(r0 + 8) * D + c0] = make_float2(acc[mf][nf][2], acc[mf][nf][3]);
        }
    }
}

__global__ void __launch_bounds__(128) add_ln_kernel(const float* __restrict__ g,
                                                     const float* __restrict__ b) {
    int row = blockIdx.x, tid = threadIdx.x;
    int w = tid >> 5, lane = tid & 31;
    float v = g_x[(size_t)row * D + tid] + g_tmp[(size_t)row * D + tid];
    float s = warp_sum(v);
    float s2 = warp_sum(v * v);
    __shared__ float ws[4], ws2[4];
    if (lane == 0) { ws[w] = s; ws2[w] = s2; }
    __syncthreads();
    s = ws[0] + ws[1] + ws[2] + ws[3];
    s2 = ws2[0] + ws2[1] + ws2[2] + ws2[3];
    float m = s * (1.f / D);
    float var = s2 * (1.f / D) - m * m;
    float inv = rsqrtf(var + 1e-5f);
    g_x[(size_t)row * D + tid] = (v - m) * inv * g[tid] + b[tid];
}

// ---------------- pooling / gate / final ----------------
__global__ void __launch_bounds__(128) tok_pool_kernel(const int* __restrict__ tokens,
                                                       const float* __restrict__ vvec) {
    int b = blockIdx.x, tid = threadIdx.x;
    int w = tid >> 5, lane = tid & 31;
    __shared__ float s_s[LSEQ];
    __shared__ float red[4];
    for (int l = w; l < LSEQ; l += 4) {
        float val = 0.f;
        #pragma unroll
        for (int d = lane; d < D; d += 32)
            val += tanhf(g_ffn[((size_t)(b * LSEQ + l)) * D + d]) * vvec[d];
        val = warp_sum(val);
        if (lane == 0) s_s[l] = (tokens[b * LSEQ + l] != 0) ? val : NEGV;
    }
    __syncthreads();
    float m = fmaxf(s_s[tid], s_s[tid + 128]);
    m = warp_max(m);
    if (lane == 0) red[w] = m;
    __syncthreads();
    m = fmaxf(fmaxf(red[0], red[1]), fmaxf(red[2], red[3]));
    __syncthreads();
    float e0 = expf(s_s[tid] - m), e1 = expf(s_s[tid + 128] - m);
    float ssum = warp_sum(e0 + e1);
    if (lane == 0) red[w] = ssum;
    __syncthreads();
    ssum = red[0] + red[1] + red[2] + red[3];
    float inv = 1.f / ssum;
    __syncthreads();
    s_s[tid] = e0 * inv; s_s[tid + 128] = e1 * inv;
    __syncthreads();
    float acc = 0.f;
    for (int l = 0; l < LSEQ; l++)
        acc = fmaf(s_s[l], g_x[((size_t)(b * LSEQ + l)) * D + tid], acc);
    g_trep[b * D + tid] = acc;
}

__global__ void __launch_bounds__(128) ent_pool_kernel(const int* __restrict__ ctx,
                                                       const float* __restrict__ Wa,
                                                       const float* __restrict__ ba,
                                                       const float* __restrict__ vvec) {
    int b = blockIdx.x, tid = threadIdx.x;
    int w = tid >> 5, lane = tid & 31;
    __shared__ float h_s[NCTX][D];
    __shared__ float s_s[NCTX];
    __shared__ int cs[NCTX];
    if (tid < NCTX) cs[tid] = ctx[b * NCTX + tid];
    __syncthreads();
    for (int j = 0; j < NCTX; j++)
        h_s[j][tid] = g_kg[(size_t)cs[j] * D + tid];
    __syncthreads();
    for (int j = w; j < NCTX; j += 4) {
        float val = 0.f;
        for (int d = lane; d < D; d += 32) {
            float acc = ba[d];
            #pragma unroll 8
            for (int kk = 0; kk < D; kk++)
                acc = fmaf(h_s[j][kk], Wa[kk * D + d], acc);
            val += tanhf(acc) * vvec[d];
        }
        val = warp_sum(val);
        if (lane == 0) s_s[j] = (cs[j] != 0) ? val : NEGV;
    }
    __syncthreads();
    if (w == 0) {
        float sv = s_s[lane];
        float m = warp_max(sv);
        float e = expf(sv - m);
        float ssum = warp_sum(e);
        s_s[lane] = e / ssum;
    }
    __syncthreads();
    float acc = 0.f;
    #pragma unroll
    for (int j = 0; j < NCTX; j++) acc = fmaf(s_s[j], h_s[j][tid], acc);
    g_erep[b * D + tid] = acc;
}

__global__ void __launch_bounds__(128) gate_kernel(const float* __restrict__ Wg,
                                                   const float* __restrict__ bg) {
    int b = blockIdx.x, tid = threadIdx.x;
    __shared__ float cat[2 * D];
    cat[tid] = g_trep[b * D + tid];
    cat[D + tid] = g_erep[b * D + tid];
    __syncthreads();
    float acc = bg[tid];
    #pragma unroll 8
    for (int j = 0; j < 2 * D; j++) acc = fmaf(cat[j], Wg[j * D + tid], acc);
    float sg = 1.f / (1.f + expf(-acc));
    g_user[b * D + tid] = sg * cat[tid] + (1.f - sg) * cat[D + tid];
}

__global__ void __launch_bounds__(256) final_kernel(float* __restrict__ out) {
    __shared__ float kg_s[128][17];
    __shared__ float user_t[D][BATCH];
    int n0 = blockIdx.x * 128, tid = threadIdx.x;
    for (int i = tid; i < D * BATCH; i += 256) {
        int d = i >> 6, bb = i & 63;
        user_t[d][bb] = g_user[bb * D + d];
    }
    int tn = tid >> 3, tb = tid & 7;
    float acc[4][8];
    #pragma unroll
    for (int i = 0; i < 4; i++)
        #pragma unroll
        for (int j = 0; j < 8; j++) acc[i][j] = 0.f;
    for (int dc = 0; dc < D; dc += 16) {
        __syncthreads();
        for (int i = tid; i < 128 * 16; i += 256) {
            int nl = i >> 4, dd = i & 15;
            int n = n0 + nl;
            kg_s[nl][dd] = (n < NE) ? g_kg[(size_t)n * D + dc + dd] : 0.f;
        }
        __syncthreads();
        #pragma unroll
        for (int dd = 0; dd < 16; dd++) {
            float kv[4], uv[8];
            #pragma unroll
            for (int i = 0; i < 4; i++) kv[i] = kg_s[tn * 4 + i][dd];
            #pragma unroll
            for (int j = 0; j < 8; j++) uv[j] = user_t[dc + dd][tb * 8 + j];
            #pragma unroll
            for (int i = 0; i < 4; i++)
                #pragma unroll
                for (int j = 0; j < 8; j++) acc[i][j] = fmaf(kv[i], uv[j], acc[i][j]);
        }
    }
    #pragma unroll
    for (int i = 0; i < 4; i++) {
        int n = n0 + tn * 4 + i;
        if (n < NE) {
            #pragma unroll
            for (int j = 0; j < 8; j++)
                out[(size_t)(tb * 8 + j) * NE + n] = acc[i][j];
        }
    }
}

// ---------------- launch ----------------
extern "C" void kernel_launch(void* const* d_in, const int* in_sizes, int n_in,
                              void* d_out, int out_size) {
    const int*   edge_idx = (const int*)d_in[0];
    const int*   edge_type = (const int*)d_in[1];
    const int*   ctx_ent  = (const int*)d_in[2];
    const int*   ctx_tok  = (const int*)d_in[3];
    const float* basis    = (const float*)d_in[4];
    const float* comp     = (const float*)d_in[5];
    const float* root     = (const float*)d_in[6];
    const float* rgcn_b   = (const float*)d_in[7];
    const float* tok_emb  = (const float*)d_in[8];
    const float* pos_emb  = (const float*)d_in[9];
    const float* Wqkv     = (const float*)d_in[10];
    const float* Wo       = (const float*)d_in[11];
    const float* ln1_g    = (const float*)d_in[12];
    const float* ln1_b    = (const float*)d_in[13];
    const float* ln2_g    = (const float*)d_in[14];
    const float* ln2_b    = (const float*)d_in[15];
    const float* W1       = (const float*)d_in[16];
    const float* b1       = (const float*)d_in[17];
    const float* W2       = (const float*)d_in[18];
    const float* b2       = (const float*)d_in[19];
    const float* ent_Wa   = (const float*)d_in[20];
    const float* ent_ba   = (const float*)d_in[21];
    const float* ent_v    = (const float*)d_in[22];
    const float* tok_Wa   = (const float*)d_in[23];
    const float* tok_ba   = (const float*)d_in[24];
    const float* tok_v    = (const float*)d_in[25];
    const float* Wg       = (const float*)d_in[26];
    const float* bg       = (const float*)d_in[27];
    float* out = (float*)d_out;

    const int M = BATCH * LSEQ;  // 16384

    // --- encoder FIRST (QKV GEMM stays at the ncu-profiled launch slot) ---
    init_ptrs_kernel<<<1, 1>>>();
    zero_cnt_kernel<<<(NE * NREL + 255) / 256, 256>>>();
    embed_kernel<<<(BATCH * LSEQ * D) / 256, 256>>>(ctx_tok, tok_emb, pos_emb);
    for (int l = 0; l < NLAY; l++) {
        gemm_tc_kernel<<<dim3(M / 128, 3), 256>>>(Wqkv + (size_t)l * 3 * D * D, nullptr, BUF_X, BUF_Q, M, D, D, 0, 1);
        attn_scores_tc<<<dim3(BATCH * NHEAD, LSEQ / 64, LSEQ / 64), 256>>>(ctx_tok);
        softmax_kernel<<<(BATCH * NHEAD * LSEQ) / 4, 128>>>();
        attn_av_tc<<<dim3(BATCH * NHEAD, LSEQ / 128), 256>>>();
        gemm_tc_kernel<<<dim3(M / 128, 1), 256>>>(Wo + (size_t)l * D * D, nullptr, BUF_AO, BUF_TMP, M, D, D, 0, 0);
        add_ln_kernel<<<M, 128>>>(ln1_g + l * D, ln1_b + l * D);
        gemm_tc_kernel<<<dim3(M / 128, FFND / 128), 256>>>(W1 + (size_t)l * D * FFND, b1 + l * FFND, BUF_X, BUF_FFN, M, FFND, D, 1, 0);
        gemm_tc_kernel<<<dim3(M / 128, 1), 256>>>(W2 + (size_t)l * FFND * D, b2 + l * D, BUF_FFN, BUF_TMP, M, D, FFND, 0, 0);
        add_ln_kernel<<<M, 128>>>(ln2_g + l * D, ln2_b + l * D);
    }
    gemm_tc_kernel<<<dim3(M / 128, 1), 256>>>(tok_Wa, tok_ba, BUF_X, BUF_FFN, M, D, D, 0, 0);

    // --- RGCN (CSR, no atomics on kg) ---
    rgcn_w_kernel<<<NE, 128>>>(basis, comp, root, rgcn_b);
    count_kernel<<<(NEDGE + 255) / 256, 256>>>(edge_idx, edge_type);
    scan_kernel<<<1, 1024>>>();
    fill_kernel<<<(NEDGE + 255) / 256, 256>>>(edge_idx, edge_type);
    agg_kernel<<<(NE * 32 + 255) / 256, 256>>>();

    // --- pooling / gate / score ---
    tok_pool_kernel<<<BATCH, 128>>>(ctx_tok, tok_v);
    ent_pool_kernel<<<BATCH, 128>>>(ctx_ent, ent_Wa, ent_ba, ent_v);
    gate_kernel<<<BATCH, 128>>>(Wg, bg);
    final_kernel<<<(NE + 127) / 128, 256>>>(out);
}

// round 14
// speedup vs baseline: 1.1470x; 1.0169x over previous
#include <cuda_runtime.h>
#include <cuda_bf16.h>
#include <math.h>

#define NE      30000
#define NREL    18
#define NB      8
#define D       128
#define NEDGE   1000000
#define BATCH   64
#define LSEQ    256
#define NCTX    32
#define NHEAD   2
#define DH      64
#define FFND    512
#define NLAY    2
#define NEGV    (-1e9f)

// ---------------- device scratch (static, referenced ONLY in device code) ---
static __device__ float g_W[(size_t)NREL * NE * D];     // 276 MB
static __device__ float g_kg[(size_t)NE * D];
static __device__ int   g_cnt[NE * NREL];
static __device__ int   g_off[NE + 1];
static __device__ int   g_cur[NE];
static __device__ int   g_elist[NEDGE];
static __device__ float g_x [BATCH * LSEQ * D];
static __device__ float g_q [BATCH * LSEQ * D];
static __device__ float g_k [BATCH * LSEQ * D];
static __device__ float g_v [BATCH * LSEQ * D];
static __device__ float g_sc[(size_t)BATCH * NHEAD * LSEQ * LSEQ]; // 33.5MB
static __device__ float g_ao[BATCH * LSEQ * D];
static __device__ float g_tmp[BATCH * LSEQ * D];
static __device__ float g_tmp2[BATCH * LSEQ * D];
static __device__ float g_ffn[BATCH * LSEQ * FFND];
static __device__ float g_trep[BATCH * D];
static __device__ float g_erep[BATCH * D];
static __device__ float g_user[BATCH * D];
static __device__ float* g_bufs[8];

#define BUF_X    0
#define BUF_Q    1
#define BUF_K    2
#define BUF_V    3
#define BUF_AO   4
#define BUF_TMP  5
#define BUF_FFN  6
#define BUF_TMP2 7

__global__ void init_ptrs_kernel() {
    g_bufs[BUF_X] = g_x;  g_bufs[BUF_Q] = g_q;  g_bufs[BUF_K] = g_k;
    g_bufs[BUF_V] = g_v;  g_bufs[BUF_AO] = g_ao; g_bufs[BUF_TMP] = g_tmp;
    g_bufs[BUF_FFN] = g_ffn; g_bufs[BUF_TMP2] = g_tmp2;
}

// ---------------- helpers ----------------
__device__ __forceinline__ float warp_sum(float v) {
    #pragma unroll
    for (int o = 16; o > 0; o >>= 1) v += __shfl_xor_sync(0xFFFFFFFFu, v, o);
    return v;
}
__device__ __forceinline__ float warp_max(float v) {
    #pragma unroll
    for (int o = 16; o > 0; o >>= 1) v = fmaxf(v, __shfl_xor_sync(0xFFFFFFFFu, v, o));
    return v;
}
// bf16 m16n8k16
__device__ __forceinline__ void mma_bf16(float* c, const unsigned* a, const unsigned* b) {
    asm volatile(
        "mma.sync.aligned.m16n8k16.row.col.f32.bf16.bf16.f32 "
        "{%0,%1,%2,%3}, {%4,%5,%6,%7}, {%8,%9}, {%0,%1,%2,%3};\n"
        : "+f"(c[0]), "+f"(c[1]), "+f"(c[2]), "+f"(c[3])
        : "r"(a[0]), "r"(a[1]), "r"(a[2]), "r"(a[3]), "r"(b[0]), "r"(b[1]));
}
// split two floats (consecutive k) into packed bf16x2 hi and lo words
__device__ __forceinline__ void bf_split2(float x0, float x1, unsigned& hi, unsigned& lo) {
    __nv_bfloat16 h0 = __float2bfloat16_rn(x0);
    __nv_bfloat16 h1 = __float2bfloat16_rn(x1);
    __nv_bfloat16 l0 = __float2bfloat16_rn(__fsub_rn(x0, __bfloat162float(h0)));
    __nv_bfloat16 l1 = __float2bfloat16_rn(__fsub_rn(x1, __bfloat162float(h1)));
    __nv_bfloat162 hp = __halves2bfloat162(h0, h1);
    __nv_bfloat162 lp = __halves2bfloat162(l0, l1);
    hi = *(unsigned*)&hp;
    lo = *(unsigned*)&lp;
}

// ---------------- RGCN ----------------
__global__ void __launch_bounds__(256) zero_cnt_kernel() {
    int i = blockIdx.x * blockDim.x + threadIdx.x;
    if (i < NE * NREL) g_cnt[i] = 0;
}

__global__ void __launch_bounds__(128) rgcn_w_kernel(const float* __restrict__ basis,
                                                     const float* __restrict__ comp,
                                                     const float* __restrict__ root,
                                                     const float* __restrict__ bias) {
    int n = blockIdx.x, d = threadIdx.x;
    __shared__ float sc[NREL * NB];
    for (int i = d; i < NREL * NB; i += 128) sc[i] = comp[i];
    __syncthreads();
    float bb[NB];
    #pragma unroll
    for (int q = 0; q < NB; q++) bb[q] = basis[((size_t)q * NE + n) * D + d];
    #pragma unroll
    for (int r = 0; r < NREL; r++) {
        float a = 0.f;
        #pragma unroll
        for (int q = 0; q < NB; q++) a = fmaf(sc[r * NB + q], bb[q], a);
        g_W[((size_t)r * NE + n) * D + d] = a;
    }
    g_kg[(size_t)n * D + d] = root[(size_t)n * D + d] + bias[d];
}

__global__ void __launch_bounds__(256) count_kernel(const int* __restrict__ ei,
                                                    const int* __restrict__ et) {
    int e = blockIdx.x * blockDim.x + threadIdx.x;
    if (e < NEDGE) {
        int dst = ei[NEDGE + e];
        atomicAdd(&g_cnt[dst * NREL + et[e]], 1);
    }
}

__global__ void __launch_bounds__(1024) scan_kernel() {
    __shared__ int warp_sums[32];
    __shared__ int carry_s;
    int tid = threadIdx.x, lane = tid & 31, w = tid >> 5;
    if (tid == 0) carry_s = 0;
    __syncthreads();
    for (int base = 0; base < NE; base += 1024) {
        int i = base + tid;
        int v = 0;
        if (i < NE) {
            #pragma unroll
            for (int r = 0; r < NREL; r++) v += g_cnt[i * NREL + r];
        }
        int x = v;
        #pragma unroll
        for (int o = 1; o < 32; o <<= 1) {
            int y = __shfl_up_sync(0xFFFFFFFFu, x, o);
            if (lane >= o) x += y;
        }
        if (lane == 31) warp_sums[w] = x;
        __syncthreads();
        if (w == 0) {
            int s = warp_sums[lane];
            #pragma unroll
            for (int o = 1; o < 32; o <<= 1) {
                int y = __shfl_up_sync(0xFFFFFFFFu, s, o);
                if (lane >= o) s += y;
            }
            warp_sums[lane] = s;
        }
        __syncthreads();
        int block_excl = (w > 0) ? warp_sums[w - 1] : 0;
        int excl = carry_s + block_excl + x - v;
        if (i < NE) { g_off[i] = excl; g_cur[i] = excl; }
        __syncthreads();
        if (tid == 0) carry_s += warp_sums[31];
        __syncthreads();
    }
    if (tid == 0) g_off[NE] = carry_s;
}

__global__ void __launch_bounds__(256) fill_kernel(const int* __restrict__ ei,
                                                   const int* __restrict__ et) {
    int e = blockIdx.x * blockDim.x + threadIdx.x;
    if (e >= NEDGE) return;
    int dst = ei[NEDGE + e];
    int pos = atomicAdd(&g_cur[dst], 1);
    g_elist[pos] = ei[e] | (et[e] << 16);
}

__global__ void __launch_bounds__(256) agg_kernel() {
    int gw = (blockIdx.x * blockDim.x + threadIdx.x) >> 5;
    int lane = threadIdx.x & 31;
    if (gw >= NE) return;
    int off = g_off[gw], end = g_off[gw + 1];
    float a0 = 0.f, a1 = 0.f, a2 = 0.f, a3 = 0.f;
    for (int b = off; b < end; b += 32) {
        int n = min(32, end - b);
        int pk = (b + lane < end) ? g_elist[b + lane] : 0;
        int j = 0;
        for (; j + 4 <= n; j += 4) {
            int p0 = __shfl_sync(0xFFFFFFFFu, pk, j);
            int p1 = __shfl_sync(0xFFFFFFFFu, pk, j + 1);
            int p2 = __shfl_sync(0xFFFFFFFFu, pk, j + 2);
            int p3 = __shfl_sync(0xFFFFFFFFu, pk, j + 3);
            float4 v0 = *(const float4*)(g_W + ((size_t)(p0 >> 16) * NE + (p0 & 0xFFFF)) * D + lane * 4);
            float4 v1 = *(const float4*)(g_W + ((size_t)(p1 >> 16) * NE + (p1 & 0xFFFF)) * D + lane * 4);
            float4 v2 = *(const float4*)(g_W + ((size_t)(p2 >> 16) * NE + (p2 & 0xFFFF)) * D + lane * 4);
            float4 v3 = *(const float4*)(g_W + ((size_t)(p3 >> 16) * NE + (p3 & 0xFFFF)) * D + lane * 4);
            float n0 = 1.f / fmaxf((float)g_cnt[gw * NREL + (p0 >> 16)], 1.f);
            float n1 = 1.f / fmaxf((float)g_cnt[gw * NREL + (p1 >> 16)], 1.f);
            float n2 = 1.f / fmaxf((float)g_cnt[gw * NREL + (p2 >> 16)], 1.f);
            float n3 = 1.f / fmaxf((float)g_cnt[gw * NREL + (p3 >> 16)], 1.f);
            a0 = fmaf(v0.x, n0, a0); a1 = fmaf(v0.y, n0, a1); a2 = fmaf(v0.z, n0, a2); a3 = fmaf(v0.w, n0, a3);
            a0 = fmaf(v1.x, n1, a0); a1 = fmaf(v1.y, n1, a1); a2 = fmaf(v1.z, n1, a2); a3 = fmaf(v1.w, n1, a3);
            a0 = fmaf(v2.x, n2, a0); a1 = fmaf(v2.y, n2, a1); a2 = fmaf(v2.z, n2, a2); a3 = fmaf(v2.w, n2, a3);
            a0 = fmaf(v3.x, n3, a0); a1 = fmaf(v3.y, n3, a1); a2 = fmaf(v3.z, n3, a2); a3 = fmaf(v3.w, n3, a3);
        }
        for (; j < n; j++) {
            int p = __shfl_sync(0xFFFFFFFFu, pk, j);
            int src = p & 0xFFFF, r = p >> 16;
            float norm = 1.f / fmaxf((float)g_cnt[gw * NREL + r], 1.f);
            float4 v = *(const float4*)(g_W + ((size_t)r * NE + src) * D + lane * 4);
            a0 = fmaf(v.x, norm, a0); a1 = fmaf(v.y, norm, a1);
            a2 = fmaf(v.z, norm, a2); a3 = fmaf(v.w, norm, a3);
        }
    }
    float* o = g_kg + (size_t)gw * D + lane * 4;
    float4 cur = *(float4*)o;
    *(float4*)o = make_float4(cur.x + a0, cur.y + a1, cur.z + a2, cur.w + a3);
}

// ---------------- encoder ----------------
__global__ void __launch_bounds__(256) embed_kernel(const int* __restrict__ tokens,
                                                    const float* __restrict__ tok_emb,
                                                    const float* __restrict__ pos_emb) {
    int i = blockIdx.x * blockDim.x + threadIdx.x;
    int d = i & (D - 1);
    int bl = i >> 7;
    int l = bl & (LSEQ - 1);
    int tk = tokens[bl];
    g_x[i] = tok_emb[(size_t)tk * D + d] * 11.3137084989847603904f + pos_emb[l * D + d];
}

// ---- split-bf16 tensor-core GEMM (R11 single-buffer body + split-K mode) ----
// 128x128 tile, BK=16, 8 warps (4m x 2n), warp tile 32x64 of m16n8k16 frags.
// mode 0: grid.y tiles N; 1: qkv (grid.y selects weight+out); 2: split-K2 (grid.y halves K)
__global__ void __launch_bounds__(256, 2) gemm_tc_kernel(const float* __restrict__ Bw,
                                                         const float* __restrict__ bias,
                                                         int asel, int csel,
                                                         int M, int N, int K, int relu,
                                                         int mode) {
    int n0 = 0, kbeg = 0, kend = K;
    if (mode == 1) { Bw += (size_t)blockIdx.y * D * D; csel += blockIdx.y; }
    else if (mode == 2) { int half = K >> 1; kbeg = blockIdx.y * half; kend = kbeg + half;
                          if (blockIdx.y) { csel = BUF_TMP2; bias = nullptr; } }
    else n0 = blockIdx.y * 128;
    const float* __restrict__ A = g_bufs[asel];
    float* __restrict__ C = g_bufs[csel];
    __shared__ unsigned Ah_s[128][12], Al_s[128][12];
    __shared__ unsigned Bh_s[128][12], Bl_s[128][12];
    int m0 = blockIdx.x * 128;
    int tid = threadIdx.x;
    int wid = tid >> 5, lane = tid & 31;
    int wm = wid & 3, wn = wid >> 2;
    int g = lane >> 2, t4 = lane & 3;

    float acc[2][8][4];
    #pragma unroll
    for (int i = 0; i < 2; i++)
        #pragma unroll
        for (int j = 0; j < 8; j++)
            #pragma unroll
            for (int q = 0; q < 4; q++) acc[i][j][q] = 0.f;

    int ar = tid >> 1, aw = (tid & 1) * 4;
    int bkp = tid & 7, bn4 = (tid >> 3) * 4;

    float4 pa0, pa1, pb0, pb1;
    {
        const float* ap = A + (size_t)(m0 + ar) * K + kbeg + aw * 2;
        pa0 = *(const float4*)ap; pa1 = *(const float4*)(ap + 4);
        pb0 = *(const float4*)(Bw + (size_t)(kbeg + 2 * bkp)     * N + n0 + bn4);
        pb1 = *(const float4*)(Bw + (size_t)(kbeg + 2 * bkp + 1) * N + n0 + bn4);
    }

    for (int kc = kbeg; kc < kend; kc += 16) {
        {   // split+pack prefetched regs into smem
            float av[8] = {pa0.x, pa0.y, pa0.z, pa0.w, pa1.x, pa1.y, pa1.z, pa1.w};
            unsigned h4[4], l4[4];
            #pragma unroll
            for (int i = 0; i < 4; i++) bf_split2(av[2 * i], av[2 * i + 1], h4[i], l4[i]);
            *(uint4*)&Ah_s[ar][aw] = make_uint4(h4[0], h4[1], h4[2], h4[3]);
            *(uint4*)&Al_s[ar][aw] = make_uint4(l4[0], l4[1], l4[2], l4[3]);
            float b0v[4] = {pb0.x, pb0.y, pb0.z, pb0.w};
            float b1v[4] = {pb1.x, pb1.y, pb1.z, pb1.w};
            #pragma unroll
            for (int i = 0; i < 4; i++) {
                unsigned hw, lw;
                bf_split2(b0v[i], b1v[i], hw, lw);
                Bh_s[bn4 + i][bkp] = hw;
                Bl_s[bn4 + i][bkp] = lw;
            }
        }
        __syncthreads();
        if (kc + 16 < kend) {   // prefetch next tile (overlaps with compute)
            const float* ap = A + (size_t)(m0 + ar) * K + kc + 16 + aw * 2;
            pa0 = *(const float4*)ap; pa1 = *(const float4*)(ap + 4);
            pb0 = *(const float4*)(Bw + (size_t)(kc + 16 + 2 * bkp)     * N + n0 + bn4);
            pb1 = *(const float4*)(Bw + (size_t)(kc + 16 + 2 * bkp + 1) * N + n0 + bn4);
        }
        {
            unsigned ah[2][4], al_[2][4];
            #pragma unroll
            for (int mf = 0; mf < 2; mf++) {
                int mm = wm * 32 + mf * 16;
                ah[mf][0] = Ah_s[mm + g    ][t4    ];  al_[mf][0] = Al_s[mm + g    ][t4    ];
                ah[mf][1] = Ah_s[mm + g + 8][t4    ];  al_[mf][1] = Al_s[mm + g + 8][t4    ];
                ah[mf][2] = Ah_s[mm + g    ][t4 + 4];  al_[mf][2] = Al_s[mm + g    ][t4 + 4];
                ah[mf][3] = Ah_s[mm + g + 8][t4 + 4];  al_[mf][3] = Al_s[mm + g + 8][t4 + 4];
            }
            #pragma unroll
            for (int nf = 0; nf < 8; nf++) {
                int nn = wn * 64 + nf * 8 + g;
                unsigned bh2[2] = {Bh_s[nn][t4], Bh_s[nn][t4 + 4]};
                unsigned bl2[2] = {Bl_s[nn][t4], Bl_s[nn][t4 + 4]};
                #pragma unroll
                for (int mf = 0; mf < 2; mf++) {
                    mma_bf16(acc[mf][nf], al_[mf], bh2);
                    mma_bf16(acc[mf][nf], ah[mf], bl2);
                    mma_bf16(acc[mf][nf], ah[mf], bh2);
                }
            }
        }
        __syncthreads();
    }
    #pragma unroll
    for (int mf = 0; mf < 2; mf++) {
        int r0 = m0 + wm * 32 + mf * 16 + g;
        #pragma unroll
        for (int nf = 0; nf < 8; nf++) {
            int c0 = n0 + wn * 64 + nf * 8 + t4 * 2;
            float bb0 = bias ? bias[c0] : 0.f;
            float bb1 = bias ? bias[c0 + 1] : 0.f;
            float v0 = acc[mf][nf][0] + bb0, v1 = acc[mf][nf][1] + bb1;
            float v2 = acc[mf][nf][2] + bb0, v3 = acc[mf][nf][3] + bb1;
            if (relu) {
                v0 = fmaxf(v0, 0.f); v1 = fmaxf(v1, 0.f);
                v2 = fmaxf(v2, 0.f); v3 = fmaxf(v3, 0.f);
            }
            *(float2*)&C[(size_t)r0 * N + c0]       = make_float2(v0, v1);
            *(float2*)&C[(size_t)(r0 + 8) * N + c0] = make_float2(v2, v3);
        }
    }
}

// ---- split-bf16 attention scores: 64q x 64k tile, d=64 ----
__global__ void __launch_bounds__(256, 2) attn_scores_tc(const int* __restrict__ tokens) {
    int bh = blockIdx.x;
    int b = bh >> 1, h = bh & 1;
    int q0 = blockIdx.y * 64, k0 = blockIdx.z * 64;
    __shared__ unsigned Qh[64][36], Ql[64][36];
    __shared__ unsigned Kh[64][36], Kl[64][36];
    int tid = threadIdx.x;
    {
        int r = tid >> 2, c8 = (tid & 3) * 8;
        const float* qp = g_q + (size_t)(b * LSEQ + q0 + r) * D + h * DH + c8 * 2;
        const float* kp = g_k + (size_t)(b * LSEQ + k0 + r) * D + h * DH + c8 * 2;
        float qf[16], kf[16];
        #pragma unroll
        for (int u = 0; u < 4; u++) {
            *(float4*)&qf[u * 4] = *(const float4*)(qp + u * 4);
            *(float4*)&kf[u * 4] = *(const float4*)(kp + u * 4);
        }
        #pragma unroll
        for (int i = 0; i < 8; i++) {
            unsigned hw, lw;
            bf_split2(qf[2 * i], qf[2 * i + 1], hw, lw);
            Qh[r][c8 + i] = hw; Ql[r][c8 + i] = lw;
            bf_split2(kf[2 * i], kf[2 * i + 1], hw, lw);
            Kh[r][c8 + i] = hw; Kl[r][c8 + i] = lw;
        }
    }
    __syncthreads();
    int wid = tid >> 5, lane = tid & 31;
    int wm = wid & 3, wn = wid >> 2;
    int g = lane >> 2, t4 = lane & 3;
    int m0 = wm * 16;

    float acc[4][4];
    #pragma unroll
    for (int j = 0; j < 4; j++)
        #pragma unroll
        for (int q = 0; q < 4; q++) acc[j][q] = 0.f;

    #pragma unroll
    for (int ks = 0; ks < 4; ks++) {
        int wb = ks * 8;
        unsigned ah[4], al[4];
        ah[0] = Qh[m0 + g    ][wb + t4    ];  al[0] = Ql[m0 + g    ][wb + t4    ];
        ah[1] = Qh[m0 + g + 8][wb + t4    ];  al[1] = Ql[m0 + g + 8][wb + t4    ];
        ah[2] = Qh[m0 + g    ][wb + t4 + 4];  al[2] = Ql[m0 + g    ][wb + t4 + 4];
        ah[3] = Qh[m0 + g + 8][wb + t4 + 4];  al[3] = Ql[m0 + g + 8][wb + t4 + 4];
        #pragma unroll
        for (int nf = 0; nf < 4; nf++) {
            int nn = wn * 32 + nf * 8 + g;
            unsigned bh2[2] = {Kh[nn][wb + t4], Kh[nn][wb + t4 + 4]};
            unsigned bl2[2] = {Kl[nn][wb + t4], Kl[nn][wb + t4 + 4]};
            mma_bf16(acc[nf], al, bh2);
            mma_bf16(acc[nf], ah, bl2);
            mma_bf16(acc[nf], ah, bh2);
        }
    }
    int row0 = bh * LSEQ + q0 + m0 + g;
    #pragma unroll
    for (int nf = 0; nf < 4; nf++) {
        int c0 = k0 + wn * 32 + nf * 8 + t4 * 2;
        float mb0 = (tokens[b * LSEQ + c0] != 0) ? 0.f : NEGV;
        float mb1 = (tokens[b * LSEQ + c0 + 1] != 0) ? 0.f : NEGV;
        *(float2*)&g_sc[(size_t)row0 * LSEQ + c0] =
            make_float2(acc[nf][0] * 0.125f + mb0, acc[nf][1] * 0.125f + mb1);
        *(float2*)&g_sc[(size_t)(row0 + 8) * LSEQ + c0] =
            make_float2(acc[nf][2] * 0.125f + mb0, acc[nf][3] * 0.125f + mb1);
    }
}

__global__ void __launch_bounds__(128) softmax_kernel() {
    int row = blockIdx.x * 4 + (threadIdx.x >> 5);
    int lane = threadIdx.x & 31;
    float* p = g_sc + (size_t)row * LSEQ;
    float v[8];
    float m = -INFINITY;
    #pragma unroll
    for (int i = 0; i < 8; i++) { v[i] = p[lane + 32 * i]; m = fmaxf(m, v[i]); }
    m = warp_max(m);
    float s = 0.f;
    #pragma unroll
    for (int i = 0; i < 8; i++) { v[i] = expf(v[i] - m); s += v[i]; }
    s = warp_sum(s);
    float inv = 1.f / s;
    #pragma unroll
    for (int i = 0; i < 8; i++) p[lane + 32 * i] = v[i] * inv;
}

// ---- split-bf16 AV ----
__global__ void __launch_bounds__(256, 2) attn_av_tc() {
    int bh = blockIdx.x;
    int b = bh >> 1, h = bh & 1;
    int l0 = blockIdx.y * 128;
    __shared__ unsigned Ph[128][20], Pl[128][20];
    __shared__ unsigned Vh[64][20], Vl[64][20];
    int tid = threadIdx.x;
    int wid = tid >> 5, lane = tid & 31;
    int wm = wid & 3, wn = wid >> 2;
    int g = lane >> 2, t4 = lane & 3;

    float acc[2][4][4];
    #pragma unroll
    for (int i = 0; i < 2; i++)
        #pragma unroll
        for (int j = 0; j < 4; j++)
            #pragma unroll
            for (int q = 0; q < 4; q++) acc[i][j][q] = 0.f;

    int pr = tid >> 1, pw8 = (tid & 1) * 8;
    int td = tid & 63, tk4 = (tid >> 6) * 4;

    for (int kc = 0; kc < 8; kc++) {
        {
            const float* pp = g_sc + (size_t)(bh * LSEQ + l0 + pr) * LSEQ + kc * 32 + pw8 * 2;
            float pf[16];
            #pragma unroll
            for (int u = 0; u < 4; u++)
                *(float4*)&pf[u * 4] = *(const float4*)(pp + u * 4);
            #pragma unroll
            for (int i = 0; i < 8; i++) {
                unsigned hw, lw;
                bf_split2(pf[2 * i], pf[2 * i + 1], hw, lw);
                Ph[pr][pw8 + i] = hw; Pl[pr][pw8 + i] = lw;
            }
            #pragma unroll
            for (int kp = 0; kp < 4; kp++) {
                int kk = tk4 + kp;
                float v0 = g_v[(size_t)(b * LSEQ + kc * 32 + 2 * kk)     * D + h * DH + td];
                float v1 = g_v[(size_t)(b * LSEQ + kc * 32 + 2 * kk + 1) * D + h * DH + td];
                unsigned hw, lw;
                bf_split2(v0, v1, hw, lw);
                Vh[td][kk] = hw; Vl[td][kk] = lw;
            }
        }
        __syncthreads();
        #pragma unroll
        for (int ks = 0; ks < 2; ks++) {
            int wb = ks * 8;
            unsigned ah[2][4], al_[2][4];
            #pragma unroll
            for (int mf = 0; mf < 2; mf++) {
                int mm = wm * 32 + mf * 16;
                ah[mf][0] = Ph[mm + g    ][wb + t4    ];  al_[mf][0] = Pl[mm + g    ][wb + t4    ];
                ah[mf][1] = Ph[mm + g + 8][wb + t4    ];  al_[mf][1] = Pl[mm + g + 8][wb + t4    ];
                ah[mf][2] = Ph[mm + g    ][wb + t4 + 4];  al_[mf][2] = Pl[mm + g    ][wb + t4 + 4];
                ah[mf][3] = Ph[mm + g + 8][wb + t4 + 4];  al_[mf][3] = Pl[mm + g + 8][wb + t4 + 4];
            }
            #pragma unroll
            for (int nf = 0; nf < 4; nf++) {
                int nn = wn * 32 + nf * 8 + g;
                unsigned bh2[2] = {Vh[nn][wb + t4], Vh[nn][wb + t4 + 4]};
                unsigned bl2[2] = {Vl[nn][wb + t4], Vl[nn][wb + t4 + 4]};
                #pragma unroll
                for (int mf = 0; mf < 2; mf++) {
                    mma_bf16(acc[mf][nf], al_[mf], bh2);
                    mma_bf16(acc[mf][nf], ah[mf], bl2);
                    mma_bf16(acc[mf][nf], ah[mf], bh2);
                }
            }
        }
        __syncthreads();
    }
    #pragma unroll
    for (int mf = 0; mf < 2; mf++) {
        int r0 = b * LSEQ + l0 + wm * 32 + mf * 16 + g;
        #pragma unroll
        for (int nf = 0; nf < 4; nf++) {
            int c0 = h * DH + wn * 32 + nf * 8 + t4 * 2;
            *(float2*)&g_ao[(size_t)r0 * D + c0] = make_float2(acc[mf][nf][0], acc[mf][nf][1]);
            *(float2*)&g_ao[(size_t)(r0 + 8) * D + c0] = make_float2(acc[mf][nf][2], acc[mf][nf][3]);
        }
    }
}

__global__ void __launch_bounds__(128) add_ln_kernel(const float* __restrict__ g,
                                                     const float* __restrict__ b,
                                                     int sum2) {
    int row = blockIdx.x, tid = threadIdx.x;
    int w = tid >> 5, lane = tid & 31;
    float v = g_x[(size_t)row * D + tid] + g_tmp[(size_t)row * D + tid];
    if (sum2) v += g_tmp2[(size_t)row * D + tid];
    float s = warp_sum(v);
    float s2 = warp_sum(v * v);
    __shared__ float ws[4], ws2[4];
    if (lane == 0) { ws[w] = s; ws2[w] = s2; }
    __syncthreads();
    s = ws[0] + ws[1] + ws[2] + ws[3];
    s2 = ws2[0] + ws2[1] + ws2[2] + ws2[3];
    float m = s * (1.f / D);
    float var = s2 * (1.f / D) - m * m;
    float inv = rsqrtf(var + 1e-5f);
    g_x[(size_t)row * D + tid] = (v - m) * inv * g[tid] + b[tid];
}

// ---------------- pooling / gate / final ----------------
__global__ void __launch_bounds__(128) tok_pool_kernel(const int* __restrict__ tokens,
                                                       const float* __restrict__ vvec) {
    int b = blockIdx.x, tid = threadIdx.x;
    int w = tid >> 5, lane = tid & 31;
    __shared__ float s_s[LSEQ];
    __shared__ float red[4];
    for (int l = w; l < LSEQ; l += 4) {
        float val = 0.f;
        #pragma unroll
        for (int d = lane; d < D; d += 32)
            val += tanhf(g_ffn[((size_t)(b * LSEQ + l)) * D + d]) * vvec[d];
        val = warp_sum(val);
        if (lane == 0) s_s[l] = (tokens[b * LSEQ + l] != 0) ? val : NEGV;
    }
    __syncthreads();
    float m = fmaxf(s_s[tid], s_s[tid + 128]);
    m = warp_max(m);
    if (lane == 0) red[w] = m;
    __syncthreads();
    m = fmaxf(fmaxf(red[0], red[1]), fmaxf(red[2], red[3]));
    __syncthreads();
    float e0 = expf(s_s[tid] - m), e1 = expf(s_s[tid + 128] - m);
    float ssum = warp_sum(e0 + e1);
    if (lane == 0) red[w] = ssum;
    __syncthreads();
    ssum = red[0] + red[1] + red[2] + red[3];
    float inv = 1.f / ssum;
    __syncthreads();
    s_s[tid] = e0 * inv; s_s[tid + 128] = e1 * inv;
    __syncthreads();
    float acc = 0.f;
    for (int l = 0; l < LSEQ; l++)
        acc = fmaf(s_s[l], g_x[((size_t)(b * LSEQ + l)) * D + tid], acc);
    g_trep[b * D + tid] = acc;
}

__global__ void __launch_bounds__(128) ent_pool_kernel(const int* __restrict__ ctx,
                                                       const float* __restrict__ Wa,
                                                       const float* __restrict__ ba,
                                                       const float* __restrict__ vvec) {
    int b = blockIdx.x, tid = threadIdx.x;
    int w = tid >> 5, lane = tid & 31;
    __shared__ float h_s[NCTX][D];
    __shared__ float s_s[NCTX];
    __shared__ int cs[NCTX];
    if (tid < NCTX) cs[tid] = ctx[b * NCTX + tid];
    __syncthreads();
    for (int j = 0; j < NCTX; j++)
        h_s[j][tid] = g_kg[(size_t)cs[j] * D + tid];
    __syncthreads();
    for (int j = w; j < NCTX; j += 4) {
        float val = 0.f;
        for (int d = lane; d < D; d += 32) {
            float acc = ba[d];
            #pragma unroll 8
            for (int kk = 0; kk < D; kk++)
                acc = fmaf(h_s[j][kk], Wa[kk * D + d], acc);
            val += tanhf(acc) * vvec[d];
        }
        val = warp_sum(val);
        if (lane == 0) s_s[j] = (cs[j] != 0) ? val : NEGV;
    }
    __syncthreads();
    if (w == 0) {
        float sv = s_s[lane];
        float m = warp_max(sv);
        float e = expf(sv - m);
        float ssum = warp_sum(e);
        s_s[lane] = e / ssum;
    }
    __syncthreads();
    float acc = 0.f;
    #pragma unroll
    for (int j = 0; j < NCTX; j++) acc = fmaf(s_s[j], h_s[j][tid], acc);
    g_erep[b * D + tid] = acc;
}

__global__ void __launch_bounds__(128) gate_kernel(const float* __restrict__ Wg,
                                                   const float* __restrict__ bg) {
    int b = blockIdx.x, tid = threadIdx.x;
    __shared__ float cat[2 * D];
    cat[tid] = g_trep[b * D + tid];
    cat[D + tid] = g_erep[b * D + tid];
    __syncthreads();
    float acc = bg[tid];
    #pragma unroll 8
    for (int j = 0; j < 2 * D; j++) acc = fmaf(cat[j], Wg[j * D + tid], acc);
    float sg = 1.f / (1.f + expf(-acc));
    g_user[b * D + tid] = sg * cat[tid] + (1.f - sg) * cat[D + tid];
}

__global__ void __launch_bounds__(256) final_kernel(float* __restrict__ out) {
    __shared__ float kg_s[128][17];
    __shared__ float user_t[D][BATCH];
    int n0 = blockIdx.x * 128, tid = threadIdx.x;
    for (int i = tid; i < D * BATCH; i += 256) {
        int d = i >> 6, bb = i & 63;
        user_t[d][bb] = g_user[bb * D + d];
    }
    int tn = tid >> 3, tb = tid & 7;
    float acc[4][8];
    #pragma unroll
    for (int i = 0; i < 4; i++)
        #pragma unroll
        for (int j = 0; j < 8; j++) acc[i][j] = 0.f;
    for (int dc = 0; dc < D; dc += 16) {
        __syncthreads();
        for (int i = tid; i < 128 * 16; i += 256) {
            int nl = i >> 4, dd = i & 15;
            int n = n0 + nl;
            kg_s[nl][dd] = (n < NE) ? g_kg[(size_t)n * D + dc + dd] : 0.f;
        }
        __syncthreads();
        #pragma unroll
        for (int dd = 0; dd < 16; dd++) {
            float kv[4], uv[8];
            #pragma unroll
            for (int i = 0; i < 4; i++) kv[i] = kg_s[tn * 4 + i][dd];
            #pragma unroll
            for (int j = 0; j < 8; j++) uv[j] = user_t[dc + dd][tb * 8 + j];
            #pragma unroll
            for (int i = 0; i < 4; i++)
                #pragma unroll
                for (int j = 0; j < 8; j++) acc[i][j] = fmaf(kv[i], uv[j], acc[i][j]);
        }
    }
    #pragma unroll
    for (int i = 0; i < 4; i++) {
        int n = n0 + tn * 4 + i;
        if (n < NE) {
            #pragma unroll
            for (int j = 0; j < 8; j++)
                out[(size_t)(tb * 8 + j) * NE + n] = acc[i][j];
        }
    }
}

// ---------------- launch ----------------
extern "C" void kernel_launch(void* const* d_in, const int* in_sizes, int n_in,
                              void* d_out, int out_size) {
    const int*   edge_idx = (const int*)d_in[0];
    const int*   edge_type = (const int*)d_in[1];
    const int*   ctx_ent  = (const int*)d_in[2];
    const int*   ctx_tok  = (const int*)d_in[3];
    const float* basis    = (const float*)d_in[4];
    const float* comp     = (const float*)d_in[5];
    const float* root     = (const float*)d_in[6];
    const float* rgcn_b   = (const float*)d_in[7];
    const float* tok_emb  = (const float*)d_in[8];
    const float* pos_emb  = (const float*)d_in[9];
    const float* Wqkv     = (const float*)d_in[10];
    const float* Wo       = (const float*)d_in[11];
    const float* ln1_g    = (const float*)d_in[12];
    const float* ln1_b    = (const float*)d_in[13];
    const float* ln2_g    = (const float*)d_in[14];
    const float* ln2_b    = (const float*)d_in[15];
    const float* W1       = (const float*)d_in[16];
    const float* b1       = (const float*)d_in[17];
    const float* W2       = (const float*)d_in[18];
    const float* b2       = (const float*)d_in[19];
    const float* ent_Wa   = (const float*)d_in[20];
    const float* ent_ba   = (const float*)d_in[21];
    const float* ent_v    = (const float*)d_in[22];
    const float* tok_Wa   = (const float*)d_in[23];
    const float* tok_ba   = (const float*)d_in[24];
    const float* tok_v    = (const float*)d_in[25];
    const float* Wg       = (const float*)d_in[26];
    const float* bg       = (const float*)d_in[27];
    float* out = (float*)d_out;

    const int M = BATCH * LSEQ;  // 16384

    // --- encoder FIRST (QKV GEMM stays at the ncu-profiled launch slot) ---
    init_ptrs_kernel<<<1, 1>>>();
    zero_cnt_kernel<<<(NE * NREL + 255) / 256, 256>>>();
    embed_kernel<<<(BATCH * LSEQ * D) / 256, 256>>>(ctx_tok, tok_emb, pos_emb);
    for (int l = 0; l < NLAY; l++) {
        gemm_tc_kernel<<<dim3(M / 128, 3), 256>>>(Wqkv + (size_t)l * 3 * D * D, nullptr, BUF_X, BUF_Q, M, D, D, 0, 1);
        attn_scores_tc<<<dim3(BATCH * NHEAD, LSEQ / 64, LSEQ / 64), 256>>>(ctx_tok);
        softmax_kernel<<<(BATCH * NHEAD * LSEQ) / 4, 128>>>();
        attn_av_tc<<<dim3(BATCH * NHEAD, LSEQ / 128), 256>>>();
        gemm_tc_kernel<<<dim3(M / 128, 1), 256>>>(Wo + (size_t)l * D * D, nullptr, BUF_AO, BUF_TMP, M, D, D, 0, 0);
        add_ln_kernel<<<M, 128>>>(ln1_g + l * D, ln1_b + l * D, 0);
        gemm_tc_kernel<<<dim3(M / 128, FFND / 128), 256>>>(W1 + (size_t)l * D * FFND, b1 + l * FFND, BUF_X, BUF_FFN, M, FFND, D, 1, 0);
        gemm_tc_kernel<<<dim3(M / 128, 2), 256>>>(W2 + (size_t)l * FFND * D, b2 + l * D, BUF_FFN, BUF_TMP, M, D, FFND, 0, 2);
        add_ln_kernel<<<M, 128>>>(ln2_g + l * D, ln2_b + l * D, 1);
    }
    gemm_tc_kernel<<<dim3(M / 128, 1), 256>>>(tok_Wa, tok_ba, BUF_X, BUF_FFN, M, D, D, 0, 0);

    // --- RGCN (CSR, no atomics on kg) ---
    rgcn_w_kernel<<<NE, 128>>>(basis, comp, root, rgcn_b);
    count_kernel<<<(NEDGE + 255) / 256, 256>>>(edge_idx, edge_type);
    scan_kernel<<<1, 1024>>>();
    fill_kernel<<<(NEDGE + 255) / 256, 256>>>(edge_idx, edge_type);
    agg_kernel<<<(NE * 32 + 255) / 256, 256>>>();

    // --- pooling / gate / score ---
    tok_pool_kernel<<<BATCH, 128>>>(ctx_tok, tok_v);
    ent_pool_kernel<<<BATCH, 128>>>(ctx_ent, ent_Wa, ent_ba, ent_v);
    gate_kernel<<<BATCH, 128>>>(Wg, bg);
    final_kernel<<<(NE + 127) / 128, 256>>>(out);
}

// round 16
// speedup vs baseline: 1.2041x; 1.0498x over previous
#include <cuda_runtime.h>
#include <cuda_bf16.h>
#include <cuda_fp16.h>
#include <math.h>

#define NE      30000
#define NREL    18
#define NB      8
#define D       128
#define NEDGE   1000000
#define BATCH   64
#define LSEQ    256
#define NCTX    32
#define NHEAD   2
#define DH      64
#define FFND    512
#define NLAY    2
#define NEGV    (-1e9f)

// ---------------- device scratch (static, referenced ONLY in device code) ---
static __device__ __half g_W[(size_t)NREL * NE * D];   // 138 MB (fp16)
static __device__ float g_kg[(size_t)NE * D];
static __device__ int   g_cnt[NE * NREL];
static __device__ int   g_off[NE + 1];
static __device__ int   g_cur[NE];
static __device__ int   g_elist[NEDGE];
static __device__ float g_x [BATCH * LSEQ * D];
static __device__ float g_q [BATCH * LSEQ * D];
static __device__ float g_k [BATCH * LSEQ * D];
static __device__ float g_v [BATCH * LSEQ * D];
static __device__ float g_sc[(size_t)BATCH * NHEAD * LSEQ * LSEQ]; // 33.5MB
static __device__ float g_ao[BATCH * LSEQ * D];
static __device__ float g_tmp[BATCH * LSEQ * D];
static __device__ float g_tmp2[BATCH * LSEQ * D];
static __device__ float g_ffn[BATCH * LSEQ * FFND];
static __device__ float g_trep[BATCH * D];
static __device__ float g_erep[BATCH * D];
static __device__ float g_user[BATCH * D];
static __device__ float* g_bufs[8];

#define BUF_X    0
#define BUF_Q    1
#define BUF_K    2
#define BUF_V    3
#define BUF_AO   4
#define BUF_TMP  5
#define BUF_FFN  6
#define BUF_TMP2 7

__global__ void init_ptrs_kernel() {
    g_bufs[BUF_X] = g_x;  g_bufs[BUF_Q] = g_q;  g_bufs[BUF_K] = g_k;
    g_bufs[BUF_V] = g_v;  g_bufs[BUF_AO] = g_ao; g_bufs[BUF_TMP] = g_tmp;
    g_bufs[BUF_FFN] = g_ffn; g_bufs[BUF_TMP2] = g_tmp2;
}

// ---------------- helpers ----------------
__device__ __forceinline__ float warp_sum(float v) {
    #pragma unroll
    for (int o = 16; o > 0; o >>= 1) v += __shfl_xor_sync(0xFFFFFFFFu, v, o);
    return v;
}
__device__ __forceinline__ float warp_max(float v) {
    #pragma unroll
    for (int o = 16; o > 0; o >>= 1) v = fmaxf(v, __shfl_xor_sync(0xFFFFFFFFu, v, o));
    return v;
}
// bf16 m16n8k16
__device__ __forceinline__ void mma_bf16(float* c, const unsigned* a, const unsigned* b) {
    asm volatile(
        "mma.sync.aligned.m16n8k16.row.col.f32.bf16.bf16.f32 "
        "{%0,%1,%2,%3}, {%4,%5,%6,%7}, {%8,%9}, {%0,%1,%2,%3};\n"
        : "+f"(c[0]), "+f"(c[1]), "+f"(c[2]), "+f"(c[3])
        : "r"(a[0]), "r"(a[1]), "r"(a[2]), "r"(a[3]), "r"(b[0]), "r"(b[1]));
}
// split two floats (consecutive k) into packed bf16x2 hi and lo words
__device__ __forceinline__ void bf_split2(float x0, float x1, unsigned& hi, unsigned& lo) {
    __nv_bfloat16 h0 = __float2bfloat16_rn(x0);
    __nv_bfloat16 h1 = __float2bfloat16_rn(x1);
    __nv_bfloat16 l0 = __float2bfloat16_rn(__fsub_rn(x0, __bfloat162float(h0)));
    __nv_bfloat16 l1 = __float2bfloat16_rn(__fsub_rn(x1, __bfloat162float(h1)));
    __nv_bfloat162 hp = __halves2bfloat162(h0, h1);
    __nv_bfloat162 lp = __halves2bfloat162(l0, l1);
    hi = *(unsigned*)&hp;
    lo = *(unsigned*)&lp;
}

// ---------------- RGCN ----------------
__global__ void __launch_bounds__(256) zero_cnt_kernel() {
    int i = blockIdx.x * blockDim.x + threadIdx.x;
    if (i < NE * NREL) g_cnt[i] = 0;
}

// W stored fp16 (halves RGCN memory traffic, 11-bit mantissa); kg stays fp32
__global__ void __launch_bounds__(128) rgcn_w_kernel(const float* __restrict__ basis,
                                                     const float* __restrict__ comp,
                                                     const float* __restrict__ root,
                                                     const float* __restrict__ bias) {
    int n = blockIdx.x, d = threadIdx.x;
    __shared__ float sc[NREL * NB];
    for (int i = d; i < NREL * NB; i += 128) sc[i] = comp[i];
    __syncthreads();
    float bb[NB];
    #pragma unroll
    for (int q = 0; q < NB; q++) bb[q] = basis[((size_t)q * NE + n) * D + d];
    #pragma unroll
    for (int r = 0; r < NREL; r++) {
        float a = 0.f;
        #pragma unroll
        for (int q = 0; q < NB; q++) a = fmaf(sc[r * NB + q], bb[q], a);
        g_W[((size_t)r * NE + n) * D + d] = __float2half_rn(a);
    }
    g_kg[(size_t)n * D + d] = root[(size_t)n * D + d] + bias[d];
}

__global__ void __launch_bounds__(256) count_kernel(const int* __restrict__ ei,
                                                    const int* __restrict__ et) {
    int e = blockIdx.x * blockDim.x + threadIdx.x;
    if (e < NEDGE) {
        int dst = ei[NEDGE + e];
        atomicAdd(&g_cnt[dst * NREL + et[e]], 1);
    }
}

__global__ void __launch_bounds__(1024) scan_kernel() {
    __shared__ int warp_sums[32];
    __shared__ int carry_s;
    int tid = threadIdx.x, lane = tid & 31, w = tid >> 5;
    if (tid == 0) carry_s = 0;
    __syncthreads();
    for (int base = 0; base < NE; base += 1024) {
        int i = base + tid;
        int v = 0;
        if (i < NE) {
            #pragma unroll
            for (int r = 0; r < NREL; r++) v += g_cnt[i * NREL + r];
        }
        int x = v;
        #pragma unroll
        for (int o = 1; o < 32; o <<= 1) {
            int y = __shfl_up_sync(0xFFFFFFFFu, x, o);
            if (lane >= o) x += y;
        }
        if (lane == 31) warp_sums[w] = x;
        __syncthreads();
        if (w == 0) {
            int s = warp_sums[lane];
            #pragma unroll
            for (int o = 1; o < 32; o <<= 1) {
                int y = __shfl_up_sync(0xFFFFFFFFu, s, o);
                if (lane >= o) s += y;
            }
            warp_sums[lane] = s;
        }
        __syncthreads();
        int block_excl = (w > 0) ? warp_sums[w - 1] : 0;
        int excl = carry_s + block_excl + x - v;
        if (i < NE) { g_off[i] = excl; g_cur[i] = excl; }
        __syncthreads();
        if (tid == 0) carry_s += warp_sums[31];
        __syncthreads();
    }
    if (tid == 0) g_off[NE] = carry_s;
}

__global__ void __launch_bounds__(256) fill_kernel(const int* __restrict__ ei,
                                                   const int* __restrict__ et) {
    int e = blockIdx.x * blockDim.x + threadIdx.x;
    if (e >= NEDGE) return;
    int dst = ei[NEDGE + e];
    int pos = atomicAdd(&g_cur[dst], 1);
    g_elist[pos] = ei[e] | (et[e] << 16);
}

// one warp per dst: fp16 W rows (256B each), lane loads 4 halves via uint2
__global__ void __launch_bounds__(256) agg_kernel() {
    int gw = (blockIdx.x * blockDim.x + threadIdx.x) >> 5;
    int lane = threadIdx.x & 31;
    if (gw >= NE) return;
    int off = g_off[gw], end = g_off[gw + 1];
    float a0 = 0.f, a1 = 0.f, a2 = 0.f, a3 = 0.f;
    for (int b = off; b < end; b += 32) {
        int n = min(32, end - b);
        int pk = (b + lane < end) ? g_elist[b + lane] : 0;
        int j = 0;
        for (; j + 4 <= n; j += 4) {
            int p0 = __shfl_sync(0xFFFFFFFFu, pk, j);
            int p1 = __shfl_sync(0xFFFFFFFFu, pk, j + 1);
            int p2 = __shfl_sync(0xFFFFFFFFu, pk, j + 2);
            int p3 = __shfl_sync(0xFFFFFFFFu, pk, j + 3);
            uint2 u0 = *(const uint2*)(g_W + ((size_t)(p0 >> 16) * NE + (p0 & 0xFFFF)) * D + lane * 4);
            uint2 u1 = *(const uint2*)(g_W + ((size_t)(p1 >> 16) * NE + (p1 & 0xFFFF)) * D + lane * 4);
            uint2 u2 = *(const uint2*)(g_W + ((size_t)(p2 >> 16) * NE + (p2 & 0xFFFF)) * D + lane * 4);
            uint2 u3 = *(const uint2*)(g_W + ((size_t)(p3 >> 16) * NE + (p3 & 0xFFFF)) * D + lane * 4);
            float n0 = 1.f / fmaxf((float)g_cnt[gw * NREL + (p0 >> 16)], 1.f);
            float n1 = 1.f / fmaxf((float)g_cnt[gw * NREL + (p1 >> 16)], 1.f);
            float n2 = 1.f / fmaxf((float)g_cnt[gw * NREL + (p2 >> 16)], 1.f);
            float n3 = 1.f / fmaxf((float)g_cnt[gw * NREL + (p3 >> 16)], 1.f);
            float2 f;
            f = __half22float2(*(__half2*)&u0.x); a0 = fmaf(f.x, n0, a0); a1 = fmaf(f.y, n0, a1);
            f = __half22float2(*(__half2*)&u0.y); a2 = fmaf(f.x, n0, a2); a3 = fmaf(f.y, n0, a3);
            f = __half22float2(*(__half2*)&u1.x); a0 = fmaf(f.x, n1, a0); a1 = fmaf(f.y, n1, a1);
            f = __half22float2(*(__half2*)&u1.y); a2 = fmaf(f.x, n1, a2); a3 = fmaf(f.y, n1, a3);
            f = __half22float2(*(__half2*)&u2.x); a0 = fmaf(f.x, n2, a0); a1 = fmaf(f.y, n2, a1);
            f = __half22float2(*(__half2*)&u2.y); a2 = fmaf(f.x, n2, a2); a3 = fmaf(f.y, n2, a3);
            f = __half22float2(*(__half2*)&u3.x); a0 = fmaf(f.x, n3, a0); a1 = fmaf(f.y, n3, a1);
            f = __half22float2(*(__half2*)&u3.y); a2 = fmaf(f.x, n3, a2); a3 = fmaf(f.y, n3, a3);
        }
        for (; j < n; j++) {
            int p = __shfl_sync(0xFFFFFFFFu, pk, j);
            int src = p & 0xFFFF, r = p >> 16;
            float norm = 1.f / fmaxf((float)g_cnt[gw * NREL + r], 1.f);
            uint2 u = *(const uint2*)(g_W + ((size_t)r * NE + src) * D + lane * 4);
            float2 f;
            f = __half22float2(*(__half2*)&u.x); a0 = fmaf(f.x, norm, a0); a1 = fmaf(f.y, norm, a1);
            f = __half22float2(*(__half2*)&u.y); a2 = fmaf(f.x, norm, a2); a3 = fmaf(f.y, norm, a3);
        }
    }
    float* o = g_kg + (size_t)gw * D + lane * 4;
    float4 cur = *(float4*)o;
    *(float4*)o = make_float4(cur.x + a0, cur.y + a1, cur.z + a2, cur.w + a3);
}

// ---------------- encoder ----------------
__global__ void __launch_bounds__(256) embed_kernel(const int* __restrict__ tokens,
                                                    const float* __restrict__ tok_emb,
                                                    const float* __restrict__ pos_emb) {
    int i = blockIdx.x * blockDim.x + threadIdx.x;
    int d = i & (D - 1);
    int bl = i >> 7;
    int l = bl & (LSEQ - 1);
    int tk = tokens[bl];
    g_x[i] = tok_emb[(size_t)tk * D + d] * 11.3137084989847603904f + pos_emb[l * D + d];
}

// ---- split-bf16 tensor-core GEMM (single-buffer body + split-K mode) ----
__global__ void __launch_bounds__(256, 2) gemm_tc_kernel(const float* __restrict__ Bw,
                                                         const float* __restrict__ bias,
                                                         int asel, int csel,
                                                         int M, int N, int K, int relu,
                                                         int mode) {
    int n0 = 0, kbeg = 0, kend = K;
    if (mode == 1) { Bw += (size_t)blockIdx.y * D * D; csel += blockIdx.y; }
    else if (mode == 2) { int half = K >> 1; kbeg = blockIdx.y * half; kend = kbeg + half;
                          if (blockIdx.y) { csel = BUF_TMP2; bias = nullptr; } }
    else n0 = blockIdx.y * 128;
    const float* __restrict__ A = g_bufs[asel];
    float* __restrict__ C = g_bufs[csel];
    __shared__ unsigned Ah_s[128][12], Al_s[128][12];
    __shared__ unsigned Bh_s[128][12], Bl_s[128][12];
    int m0 = blockIdx.x * 128;
    int tid = threadIdx.x;
    int wid = tid >> 5, lane = tid & 31;
    int wm = wid & 3, wn = wid >> 2;
    int g = lane >> 2, t4 = lane & 3;

    float acc[2][8][4];
    #pragma unroll
    for (int i = 0; i < 2; i++)
        #pragma unroll
        for (int j = 0; j < 8; j++)
            #pragma unroll
            for (int q = 0; q < 4; q++) acc[i][j][q] = 0.f;

    int ar = tid >> 1, aw = (tid & 1) * 4;
    int bkp = tid & 7, bn4 = (tid >> 3) * 4;

    float4 pa0, pa1, pb0, pb1;
    {
        const float* ap = A + (size_t)(m0 + ar) * K + kbeg + aw * 2;
        pa0 = *(const float4*)ap; pa1 = *(const float4*)(ap + 4);
        pb0 = *(const float4*)(Bw + (size_t)(kbeg + 2 * bkp)     * N + n0 + bn4);
        pb1 = *(const float4*)(Bw + (size_t)(kbeg + 2 * bkp + 1) * N + n0 + bn4);
    }

    for (int kc = kbeg; kc < kend; kc += 16) {
        {
            float av[8] = {pa0.x, pa0.y, pa0.z, pa0.w, pa1.x, pa1.y, pa1.z, pa1.w};
            unsigned h4[4], l4[4];
            #pragma unroll
            for (int i = 0; i < 4; i++) bf_split2(av[2 * i], av[2 * i + 1], h4[i], l4[i]);
            *(uint4*)&Ah_s[ar][aw] = make_uint4(h4[0], h4[1], h4[2], h4[3]);
            *(uint4*)&Al_s[ar][aw] = make_uint4(l4[0], l4[1], l4[2], l4[3]);
            float b0v[4] = {pb0.x, pb0.y, pb0.z, pb0.w};
            float b1v[4] = {pb1.x, pb1.y, pb1.z, pb1.w};
            #pragma unroll
            for (int i = 0; i < 4; i++) {
                unsigned hw, lw;
                bf_split2(b0v[i], b1v[i], hw, lw);
                Bh_s[bn4 + i][bkp] = hw;
                Bl_s[bn4 + i][bkp] = lw;
            }
        }
        __syncthreads();
        if (kc + 16 < kend) {
            const float* ap = A + (size_t)(m0 + ar) * K + kc + 16 + aw * 2;
            pa0 = *(const float4*)ap; pa1 = *(const float4*)(ap + 4);
            pb0 = *(const float4*)(Bw + (size_t)(kc + 16 + 2 * bkp)     * N + n0 + bn4);
            pb1 = *(const float4*)(Bw + (size_t)(kc + 16 + 2 * bkp + 1) * N + n0 + bn4);
        }
        {
            unsigned ah[2][4], al_[2][4];
            #pragma unroll
            for (int mf = 0; mf < 2; mf++) {
                int mm = wm * 32 + mf * 16;
                ah[mf][0] = Ah_s[mm + g    ][t4    ];  al_[mf][0] = Al_s[mm + g    ][t4    ];
                ah[mf][1] = Ah_s[mm + g + 8][t4    ];  al_[mf][1] = Al_s[mm + g + 8][t4    ];
                ah[mf][2] = Ah_s[mm + g    ][t4 + 4];  al_[mf][2] = Al_s[mm + g    ][t4 + 4];
                ah[mf][3] = Ah_s[mm + g + 8][t4 + 4];  al_[mf][3] = Al_s[mm + g + 8][t4 + 4];
            }
            #pragma unroll
            for (int nf = 0; nf < 8; nf++) {
                int nn = wn * 64 + nf * 8 + g;
                unsigned bh2[2] = {Bh_s[nn][t4], Bh_s[nn][t4 + 4]};
                unsigned bl2[2] = {Bl_s[nn][t4], Bl_s[nn][t4 + 4]};
                #pragma unroll
                for (int mf = 0; mf < 2; mf++) {
                    mma_bf16(acc[mf][nf], al_[mf], bh2);
                    mma_bf16(acc[mf][nf], ah[mf], bl2);
                    mma_bf16(acc[mf][nf], ah[mf], bh2);
                }
            }
        }
        __syncthreads();
    }
    #pragma unroll
    for (int mf = 0; mf < 2; mf++) {
        int r0 = m0 + wm * 32 + mf * 16 + g;
        #pragma unroll
        for (int nf = 0; nf < 8; nf++) {
            int c0 = n0 + wn * 64 + nf * 8 + t4 * 2;
            float bb0 = bias ? bias[c0] : 0.f;
            float bb1 = bias ? bias[c0 + 1] : 0.f;
            float v0 = acc[mf][nf][0] + bb0, v1 = acc[mf][nf][1] + bb1;
            float v2 = acc[mf][nf][2] + bb0, v3 = acc[mf][nf][3] + bb1;
            if (relu) {
                v0 = fmaxf(v0, 0.f); v1 = fmaxf(v1, 0.f);
                v2 = fmaxf(v2, 0.f); v3 = fmaxf(v3, 0.f);
            }
            *(float2*)&C[(size_t)r0 * N + c0]       = make_float2(v0, v1);
            *(float2*)&C[(size_t)(r0 + 8) * N + c0] = make_float2(v2, v3);
        }
    }
}

// ---- split-bf16 attention scores: 64q x 64k tile, d=64 ----
__global__ void __launch_bounds__(256, 2) attn_scores_tc(const int* __restrict__ tokens) {
    int bh = blockIdx.x;
    int b = bh >> 1, h = bh & 1;
    int q0 = blockIdx.y * 64, k0 = blockIdx.z * 64;
    __shared__ unsigned Qh[64][36], Ql[64][36];
    __shared__ unsigned Kh[64][36], Kl[64][36];
    int tid = threadIdx.x;
    {
        int r = tid >> 2, c8 = (tid & 3) * 8;
        const float* qp = g_q + (size_t)(b * LSEQ + q0 + r) * D + h * DH + c8 * 2;
        const float* kp = g_k + (size_t)(b * LSEQ + k0 + r) * D + h * DH + c8 * 2;
        float qf[16], kf[16];
        #pragma unroll
        for (int u = 0; u < 4; u++) {
            *(float4*)&qf[u * 4] = *(const float4*)(qp + u * 4);
            *(float4*)&kf[u * 4] = *(const float4*)(kp + u * 4);
        }
        #pragma unroll
        for (int i = 0; i < 8; i++) {
            unsigned hw, lw;
            bf_split2(qf[2 * i], qf[2 * i + 1], hw, lw);
            Qh[r][c8 + i] = hw; Ql[r][c8 + i] = lw;
            bf_split2(kf[2 * i], kf[2 * i + 1], hw, lw);
            Kh[r][c8 + i] = hw; Kl[r][c8 + i] = lw;
        }
    }
    __syncthreads();
    int wid = tid >> 5, lane = tid & 31;
    int wm = wid & 3, wn = wid >> 2;
    int g = lane >> 2, t4 = lane & 3;
    int m0 = wm * 16;

    float acc[4][4];
    #pragma unroll
    for (int j = 0; j < 4; j++)
        #pragma unroll
        for (int q = 0; q < 4; q++) acc[j][q] = 0.f;

    #pragma unroll
    for (int ks = 0; ks < 4; ks++) {
        int wb = ks * 8;
        unsigned ah[4], al[4];
        ah[0] = Qh[m0 + g    ][wb + t4    ];  al[0] = Ql[m0 + g    ][wb + t4    ];
        ah[1] = Qh[m0 + g + 8][wb + t4    ];  al[1] = Ql[m0 + g + 8][wb + t4    ];
        ah[2] = Qh[m0 + g    ][wb + t4 + 4];  al[2] = Ql[m0 + g    ][wb + t4 + 4];
        ah[3] = Qh[m0 + g + 8][wb + t4 + 4];  al[3] = Ql[m0 + g + 8][wb + t4 + 4];
        #pragma unroll
        for (int nf = 0; nf < 4; nf++) {
            int nn = wn * 32 + nf * 8 + g;
            unsigned bh2[2] = {Kh[nn][wb + t4], Kh[nn][wb + t4 + 4]};
            unsigned bl2[2] = {Kl[nn][wb + t4], Kl[nn][wb + t4 + 4]};
            mma_bf16(acc[nf], al, bh2);
            mma_bf16(acc[nf], ah, bl2);
            mma_bf16(acc[nf], ah, bh2);
        }
    }
    int row0 = bh * LSEQ + q0 + m0 + g;
    #pragma unroll
    for (int nf = 0; nf < 4; nf++) {
        int c0 = k0 + wn * 32 + nf * 8 + t4 * 2;
        float mb0 = (tokens[b * LSEQ + c0] != 0) ? 0.f : NEGV;
        float mb1 = (tokens[b * LSEQ + c0 + 1] != 0) ? 0.f : NEGV;
        *(float2*)&g_sc[(size_t)row0 * LSEQ + c0] =
            make_float2(acc[nf][0] * 0.125f + mb0, acc[nf][1] * 0.125f + mb1);
        *(float2*)&g_sc[(size_t)(row0 + 8) * LSEQ + c0] =
            make_float2(acc[nf][2] * 0.125f + mb0, acc[nf][3] * 0.125f + mb1);
    }
}

__global__ void __launch_bounds__(128) softmax_kernel() {
    int row = blockIdx.x * 4 + (threadIdx.x >> 5);
    int lane = threadIdx.x & 31;
    float* p = g_sc + (size_t)row * LSEQ;
    float v[8];
    float m = -INFINITY;
    #pragma unroll
    for (int i = 0; i < 8; i++) { v[i] = p[lane + 32 * i]; m = fmaxf(m, v[i]); }
    m = warp_max(m);
    float s = 0.f;
    #pragma unroll
    for (int i = 0; i < 8; i++) { v[i] = expf(v[i] - m); s += v[i]; }
    s = warp_sum(s);
    float inv = 1.f / s;
    #pragma unroll
    for (int i = 0; i < 8; i++) p[lane + 32 * i] = v[i] * inv;
}

// ---- split-bf16 AV ----
__global__ void __launch_bounds__(256, 2) attn_av_tc() {
    int bh = blockIdx.x;
    int b = bh >> 1, h = bh & 1;
    int l0 = blockIdx.y * 128;
    __shared__ unsigned Ph[128][20], Pl[128][20];
    __shared__ unsigned Vh[64][20], Vl[64][20];
    int tid = threadIdx.x;
    int wid = tid >> 5, lane = tid & 31;
    int wm = wid & 3, wn = wid >> 2;
    int g = lane >> 2, t4 = lane & 3;

    float acc[2][4][4];
    #pragma unroll
    for (int i = 0; i < 2; i++)
        #pragma unroll
        for (int j = 0; j < 4; j++)
            #pragma unroll
            for (int q = 0; q < 4; q++) acc[i][j][q] = 0.f;

    int pr = tid >> 1, pw8 = (tid & 1) * 8;
    int td = tid & 63, tk4 = (tid >> 6) * 4;

    for (int kc = 0; kc < 8; kc++) {
        {
            const float* pp = g_sc + (size_t)(bh * LSEQ + l0 + pr) * LSEQ + kc * 32 + pw8 * 2;
            float pf[16];
            #pragma unroll
            for (int u = 0; u < 4; u++)
                *(float4*)&pf[u * 4] = *(const float4*)(pp + u * 4);
            #pragma unroll
            for (int i = 0; i < 8; i++) {
                unsigned hw, lw;
                bf_split2(pf[2 * i], pf[2 * i + 1], hw, lw);
                Ph[pr][pw8 + i] = hw; Pl[pr][pw8 + i] = lw;
            }
            #pragma unroll
            for (int kp = 0; kp < 4; kp++) {
                int kk = tk4 + kp;
                float v0 = g_v[(size_t)(b * LSEQ + kc * 32 + 2 * kk)     * D + h * DH + td];
                float v1 = g_v[(size_t)(b * LSEQ + kc * 32 + 2 * kk + 1) * D + h * DH + td];
                unsigned hw, lw;
                bf_split2(v0, v1, hw, lw);
                Vh[td][kk] = hw; Vl[td][kk] = lw;
            }
        }
        __syncthreads();
        #pragma unroll
        for (int ks = 0; ks < 2; ks++) {
            int wb = ks * 8;
            unsigned ah[2][4], al_[2][4];
            #pragma unroll
            for (int mf = 0; mf < 2; mf++) {
                int mm = wm * 32 + mf * 16;
                ah[mf][0] = Ph[mm + g    ][wb + t4    ];  al_[mf][0] = Pl[mm + g    ][wb + t4    ];
                ah[mf][1] = Ph[mm + g + 8][wb + t4    ];  al_[mf][1] = Pl[mm + g + 8][wb + t4    ];
                ah[mf][2] = Ph[mm + g    ][wb + t4 + 4];  al_[mf][2] = Pl[mm + g    ][wb + t4 + 4];
                ah[mf][3] = Ph[mm + g + 8][wb + t4 + 4];  al_[mf][3] = Pl[mm + g + 8][wb + t4 + 4];
            }
            #pragma unroll
            for (int nf = 0; nf < 4; nf++) {
                int nn = wn * 32 + nf * 8 + g;
                unsigned bh2[2] = {Vh[nn][wb + t4], Vh[nn][wb + t4 + 4]};
                unsigned bl2[2] = {Vl[nn][wb + t4], Vl[nn][wb + t4 + 4]};
                #pragma unroll
                for (int mf = 0; mf < 2; mf++) {
                    mma_bf16(acc[mf][nf], al_[mf], bh2);
                    mma_bf16(acc[mf][nf], ah[mf], bl2);
                    mma_bf16(acc[mf][nf], ah[mf], bh2);
                }
            }
        }
        __syncthreads();
    }
    #pragma unroll
    for (int mf = 0; mf < 2; mf++) {
        int r0 = b * LSEQ + l0 + wm * 32 + mf * 16 + g;
        #pragma unroll
        for (int nf = 0; nf < 4; nf++) {
            int c0 = h * DH + wn * 32 + nf * 8 + t4 * 2;
            *(float2*)&g_ao[(size_t)r0 * D + c0] = make_float2(acc[mf][nf][0], acc[mf][nf][1]);
            *(float2*)&g_ao[(size_t)(r0 + 8) * D + c0] = make_float2(acc[mf][nf][2], acc[mf][nf][3]);
        }
    }
}

// 2 rows per block (256 threads); row handled by its own 4 warps
__global__ void __launch_bounds__(256) add_ln_kernel(const float* __restrict__ g,
                                                     const float* __restrict__ b,
                                                     int sum2) {
    int tid = threadIdx.x;
    int half = tid >> 7;                     // 0 or 1 -> row select
    int t = tid & 127;
    int row = blockIdx.x * 2 + half;
    int w = t >> 5, lane = t & 31;
    float v = g_x[(size_t)row * D + t] + g_tmp[(size_t)row * D + t];
    if (sum2) v += g_tmp2[(size_t)row * D + t];
    float s = warp_sum(v);
    float s2 = warp_sum(v * v);
    __shared__ float ws[8], ws2[8];
    if (lane == 0) { ws[half * 4 + w] = s; ws2[half * 4 + w] = s2; }
    __syncthreads();
    int base = half * 4;
    s = ws[base] + ws[base + 1] + ws[base + 2] + ws[base + 3];
    s2 = ws2[base] + ws2[base + 1] + ws2[base + 2] + ws2[base + 3];
    float m = s * (1.f / D);
    float var = s2 * (1.f / D) - m * m;
    float inv = rsqrtf(var + 1e-5f);
    g_x[(size_t)row * D + t] = (v - m) * inv * g[t] + b[t];
}

// ---------------- pooling / gate / final ----------------
__global__ void __launch_bounds__(128) tok_pool_kernel(const int* __restrict__ tokens,
                                                       const float* __restrict__ vvec) {
    int b = blockIdx.x, tid = threadIdx.x;
    int w = tid >> 5, lane = tid & 31;
    __shared__ float s_s[LSEQ];
    __shared__ float red[4];
    for (int l = w; l < LSEQ; l += 4) {
        float val = 0.f;
        #pragma unroll
        for (int d = lane; d < D; d += 32)
            val += tanhf(g_ffn[((size_t)(b * LSEQ + l)) * D + d]) * vvec[d];
        val = warp_sum(val);
        if (lane == 0) s_s[l] = (tokens[b * LSEQ + l] != 0) ? val : NEGV;
    }
    __syncthreads();
    float m = fmaxf(s_s[tid], s_s[tid + 128]);
    m = warp_max(m);
    if (lane == 0) red[w] = m;
    __syncthreads();
    m = fmaxf(fmaxf(red[0], red[1]), fmaxf(red[2], red[3]));
    __syncthreads();
    float e0 = expf(s_s[tid] - m), e1 = expf(s_s[tid + 128] - m);
    float ssum = warp_sum(e0 + e1);
    if (lane == 0) red[w] = ssum;
    __syncthreads();
    ssum = red[0] + red[1] + red[2] + red[3];
    float inv = 1.f / ssum;
    __syncthreads();
    s_s[tid] = e0 * inv; s_s[tid + 128] = e1 * inv;
    __syncthreads();
    float acc = 0.f;
    for (int l = 0; l < LSEQ; l++)
        acc = fmaf(s_s[l], g_x[((size_t)(b * LSEQ + l)) * D + tid], acc);
    g_trep[b * D + tid] = acc;
}

__global__ void __launch_bounds__(128) ent_pool_kernel(const int* __restrict__ ctx,
                                                       const float* __restrict__ Wa,
                                                       const float* __restrict__ ba,
                                                       const float* __restrict__ vvec) {
    int b = blockIdx.x, tid = threadIdx.x;
    int w = tid >> 5, lane = tid & 31;
    __shared__ float h_s[NCTX][D];
    __shared__ float s_s[NCTX];
    __shared__ int cs[NCTX];
    if (tid < NCTX) cs[tid] = ctx[b * NCTX + tid];
    __syncthreads();
    for (int j = 0; j < NCTX; j++)
        h_s[j][tid] = g_kg[(size_t)cs[j] * D + tid];
    __syncthreads();
    for (int j = w; j < NCTX; j += 4) {
        float val = 0.f;
        for (int d = lane; d < D; d += 32) {
            float acc = ba[d];
            #pragma unroll 8
            for (int kk = 0; kk < D; kk++)
                acc = fmaf(h_s[j][kk], Wa[kk * D + d], acc);
            val += tanhf(acc) * vvec[d];
        }
        val = warp_sum(val);
        if (lane == 0) s_s[j] = (cs[j] != 0) ? val : NEGV;
    }
    __syncthreads();
    if (w == 0) {
        float sv = s_s[lane];
        float m = warp_max(sv);
        float e = expf(sv - m);
        float ssum = warp_sum(e);
        s_s[lane] = e / ssum;
    }
    __syncthreads();
    float acc = 0.f;
    #pragma unroll
    for (int j = 0; j < NCTX; j++) acc = fmaf(s_s[j], h_s[j][tid], acc);
    g_erep[b * D + tid] = acc;
}

__global__ void __launch_bounds__(128) gate_kernel(const float* __restrict__ Wg,
                                                   const float* __restrict__ bg) {
    int b = blockIdx.x, tid = threadIdx.x;
    __shared__ float cat[2 * D];
    cat[tid] = g_trep[b * D + tid];
    cat[D + tid] = g_erep[b * D + tid];
    __syncthreads();
    float acc = bg[tid];
    #pragma unroll 8
    for (int j = 0; j < 2 * D; j++) acc = fmaf(cat[j], Wg[j * D + tid], acc);
    float sg = 1.f / (1.f + expf(-acc));
    g_user[b * D + tid] = sg * cat[tid] + (1.f - sg) * cat[D + tid];
}

__global__ void __launch_bounds__(256) final_kernel(float* __restrict__ out) {
    __shared__ float kg_s[128][17];
    __shared__ float user_t[D][BATCH];
    int n0 = blockIdx.x * 128, tid = threadIdx.x;
    for (int i = tid; i < D * BATCH; i += 256) {
        int d = i >> 6, bb = i & 63;
        user_t[d][bb] = g_user[bb * D + d];
    }
    int tn = tid >> 3, tb = tid & 7;
    float acc[4][8];
    #pragma unroll
    for (int i = 0; i < 4; i++)
        #pragma unroll
        for (int j = 0; j < 8; j++) acc[i][j] = 0.f;
    for (int dc = 0; dc < D; dc += 16) {
        __syncthreads();
        for (int i = tid; i < 128 * 16; i += 256) {
            int nl = i >> 4, dd = i & 15;
            int n = n0 + nl;
            kg_s[nl][dd] = (n < NE) ? g_kg[(size_t)n * D + dc + dd] : 0.f;
        }
        __syncthreads();
        #pragma unroll
        for (int dd = 0; dd < 16; dd++) {
            float kv[4], uv[8];
            #pragma unroll
            for (int i = 0; i < 4; i++) kv[i] = kg_s[tn * 4 + i][dd];
            #pragma unroll
            for (int j = 0; j < 8; j++) uv[j] = user_t[dc + dd][tb * 8 + j];
            #pragma unroll
            for (int i = 0; i < 4; i++)
                #pragma unroll
                for (int j = 0; j < 8; j++) acc[i][j] = fmaf(kv[i], uv[j], acc[i][j]);
        }
    }
    #pragma unroll
    for (int i = 0; i < 4; i++) {
        int n = n0 + tn * 4 + i;
        if (n < NE) {
            #pragma unroll
            for (int j = 0; j < 8; j++)
                out[(size_t)(tb * 8 + j) * NE + n] = acc[i][j];
        }
    }
}

// ---------------- launch ----------------
extern "C" void kernel_launch(void* const* d_in, const int* in_sizes, int n_in,
                              void* d_out, int out_size) {
    const int*   edge_idx = (const int*)d_in[0];
    const int*   edge_type = (const int*)d_in[1];
    const int*   ctx_ent  = (const int*)d_in[2];
    const int*   ctx_tok  = (const int*)d_in[3];
    const float* basis    = (const float*)d_in[4];
    const float* comp     = (const float*)d_in[5];
    const float* root     = (const float*)d_in[6];
    const float* rgcn_b   = (const float*)d_in[7];
    const float* tok_emb  = (const float*)d_in[8];
    const float* pos_emb  = (const float*)d_in[9];
    const float* Wqkv     = (const float*)d_in[10];
    const float* Wo       = (const float*)d_in[11];
    const float* ln1_g    = (const float*)d_in[12];
    const float* ln1_b    = (const float*)d_in[13];
    const float* ln2_g    = (const float*)d_in[14];
    const float* ln2_b    = (const float*)d_in[15];
    const float* W1       = (const float*)d_in[16];
    const float* b1       = (const float*)d_in[17];
    const float* W2       = (const float*)d_in[18];
    const float* b2       = (const float*)d_in[19];
    const float* ent_Wa   = (const float*)d_in[20];
    const float* ent_ba   = (const float*)d_in[21];
    const float* ent_v    = (const float*)d_in[22];
    const float* tok_Wa   = (const float*)d_in[23];
    const float* tok_ba   = (const float*)d_in[24];
    const float* tok_v    = (const float*)d_in[25];
    const float* Wg       = (const float*)d_in[26];
    const float* bg       = (const float*)d_in[27];
    float* out = (float*)d_out;

    const int M = BATCH * LSEQ;  // 16384

    // --- encoder FIRST (QKV GEMM stays at the ncu-profiled launch slot) ---
    init_ptrs_kernel<<<1, 1>>>();
    zero_cnt_kernel<<<(NE * NREL + 255) / 256, 256>>>();
    embed_kernel<<<(BATCH * LSEQ * D) / 256, 256>>>(ctx_tok, tok_emb, pos_emb);
    for (int l = 0; l < NLAY; l++) {
        gemm_tc_kernel<<<dim3(M / 128, 3), 256>>>(Wqkv + (size_t)l * 3 * D * D, nullptr, BUF_X, BUF_Q, M, D, D, 0, 1);
        attn_scores_tc<<<dim3(BATCH * NHEAD, LSEQ / 64, LSEQ / 64), 256>>>(ctx_tok);
        softmax_kernel<<<(BATCH * NHEAD * LSEQ) / 4, 128>>>();
        attn_av_tc<<<dim3(BATCH * NHEAD, LSEQ / 128), 256>>>();
        gemm_tc_kernel<<<dim3(M / 128, 1), 256>>>(Wo + (size_t)l * D * D, nullptr, BUF_AO, BUF_TMP, M, D, D, 0, 0);
        add_ln_kernel<<<M / 2, 256>>>(ln1_g + l * D, ln1_b + l * D, 0);
        gemm_tc_kernel<<<dim3(M / 128, FFND / 128), 256>>>(W1 + (size_t)l * D * FFND, b1 + l * FFND, BUF_X, BUF_FFN, M, FFND, D, 1, 0);
        gemm_tc_kernel<<<dim3(M / 128, 2), 256>>>(W2 + (size_t)l * FFND * D, b2 + l * D, BUF_FFN, BUF_TMP, M, D, FFND, 0, 2);
        add_ln_kernel<<<M / 2, 256>>>(ln2_g + l * D, ln2_b + l * D, 1);
    }
    gemm_tc_kernel<<<dim3(M / 128, 1), 256>>>(tok_Wa, tok_ba, BUF_X, BUF_FFN, M, D, D, 0, 0);

    // --- RGCN (CSR, fp16 W, no atomics on kg) ---
    rgcn_w_kernel<<<NE, 128>>>(basis, comp, root, rgcn_b);
    count_kernel<<<(NEDGE + 255) / 256, 256>>>(edge_idx, edge_type);
    scan_kernel<<<1, 1024>>>();
    fill_kernel<<<(NEDGE + 255) / 256, 256>>>(edge_idx, edge_type);
    agg_kernel<<<(NE * 32 + 255) / 256, 256>>>();

    // --- pooling / gate / score ---
    tok_pool_kernel<<<BATCH, 128>>>(ctx_tok, tok_v);
    ent_pool_kernel<<<BATCH, 128>>>(ctx_ent, ent_Wa, ent_ba, ent_v);
    gate_kernel<<<BATCH, 128>>>(Wg, bg);
    final_kernel<<<(NE + 127) / 128, 256>>>(out);
}

// round 17
// speedup vs baseline: 1.2195x; 1.0128x over previous
#include <cuda_runtime.h>
#include <cuda_bf16.h>
#include <cuda_fp16.h>
#include <math.h>

#define NE      30000
#define NREL    18
#define NB      8
#define D       128
#define NEDGE   1000000
#define BATCH   64
#define LSEQ    256
#define NCTX    32
#define NHEAD   2
#define DH      64
#define FFND    512
#define NLAY    2
#define NEGV    (-1e9f)

// ---------------- device scratch (static, referenced ONLY in device code) ---
static __device__ __half g_W[(size_t)NREL * NE * D];   // 138 MB (fp16)
static __device__ float g_kg[(size_t)NE * D];
static __device__ int   g_cnt[NE * NREL];
static __device__ int   g_off[NE + 1];
static __device__ int   g_cur[NE];
static __device__ int   g_elist[NEDGE];
static __device__ float g_x [BATCH * LSEQ * D];
static __device__ float g_q [BATCH * LSEQ * D];
static __device__ float g_k [BATCH * LSEQ * D];
static __device__ float g_v [BATCH * LSEQ * D];
static __device__ float g_sc[(size_t)BATCH * NHEAD * LSEQ * LSEQ]; // 33.5MB
static __device__ float g_ao[BATCH * LSEQ * D];
static __device__ float g_tmp[BATCH * LSEQ * D];
static __device__ float g_tmp2[BATCH * LSEQ * D];
static __device__ float g_ffn[BATCH * LSEQ * FFND];
static __device__ float g_trep[BATCH * D];
static __device__ float g_erep[BATCH * D];
static __device__ float g_user[BATCH * D];
static __device__ float* g_bufs[8];

#define BUF_X    0
#define BUF_Q    1
#define BUF_K    2
#define BUF_V    3
#define BUF_AO   4
#define BUF_TMP  5
#define BUF_FFN  6
#define BUF_TMP2 7

__global__ void init_ptrs_kernel() {
    g_bufs[BUF_X] = g_x;  g_bufs[BUF_Q] = g_q;  g_bufs[BUF_K] = g_k;
    g_bufs[BUF_V] = g_v;  g_bufs[BUF_AO] = g_ao; g_bufs[BUF_TMP] = g_tmp;
    g_bufs[BUF_FFN] = g_ffn; g_bufs[BUF_TMP2] = g_tmp2;
}

// ---------------- helpers ----------------
__device__ __forceinline__ float warp_sum(float v) {
    #pragma unroll
    for (int o = 16; o > 0; o >>= 1) v += __shfl_xor_sync(0xFFFFFFFFu, v, o);
    return v;
}
__device__ __forceinline__ float warp_max(float v) {
    #pragma unroll
    for (int o = 16; o > 0; o >>= 1) v = fmaxf(v, __shfl_xor_sync(0xFFFFFFFFu, v, o));
    return v;
}
// bf16 m16n8k16
__device__ __forceinline__ void mma_bf16(float* c, const unsigned* a, const unsigned* b) {
    asm volatile(
        "mma.sync.aligned.m16n8k16.row.col.f32.bf16.bf16.f32 "
        "{%0,%1,%2,%3}, {%4,%5,%6,%7}, {%8,%9}, {%0,%1,%2,%3};\n"
        : "+f"(c[0]), "+f"(c[1]), "+f"(c[2]), "+f"(c[3])
        : "r"(a[0]), "r"(a[1]), "r"(a[2]), "r"(a[3]), "r"(b[0]), "r"(b[1]));
}
__device__ __forceinline__ void ldsm_x4(unsigned& r0, unsigned& r1, unsigned& r2, unsigned& r3,
                                        unsigned addr) {
    asm volatile("ldmatrix.sync.aligned.m8n8.x4.shared.b16 {%0,%1,%2,%3}, [%4];"
                 : "=r"(r0), "=r"(r1), "=r"(r2), "=r"(r3) : "r"(addr));
}
// split two floats (consecutive k) into packed bf16x2 hi and lo words
__device__ __forceinline__ void bf_split2(float x0, float x1, unsigned& hi, unsigned& lo) {
    __nv_bfloat16 h0 = __float2bfloat16_rn(x0);
    __nv_bfloat16 h1 = __float2bfloat16_rn(x1);
    __nv_bfloat16 l0 = __float2bfloat16_rn(__fsub_rn(x0, __bfloat162float(h0)));
    __nv_bfloat16 l1 = __float2bfloat16_rn(__fsub_rn(x1, __bfloat162float(h1)));
    __nv_bfloat162 hp = __halves2bfloat162(h0, h1);
    __nv_bfloat162 lp = __halves2bfloat162(l0, l1);
    hi = *(unsigned*)&hp;
    lo = *(unsigned*)&lp;
}

// ---------------- RGCN ----------------
__global__ void __launch_bounds__(256) zero_cnt_kernel() {
    int i = blockIdx.x * blockDim.x + threadIdx.x;
    if (i < NE * NREL) g_cnt[i] = 0;
}

// W stored fp16 (halves RGCN memory traffic, 11-bit mantissa); kg stays fp32
__global__ void __launch_bounds__(128) rgcn_w_kernel(const float* __restrict__ basis,
                                                     const float* __restrict__ comp,
                                                     const float* __restrict__ root,
                                                     const float* __restrict__ bias) {
    int n = blockIdx.x, d = threadIdx.x;
    __shared__ float sc[NREL * NB];
    for (int i = d; i < NREL * NB; i += 128) sc[i] = comp[i];
    __syncthreads();
    float bb[NB];
    #pragma unroll
    for (int q = 0; q < NB; q++) bb[q] = basis[((size_t)q * NE + n) * D + d];
    #pragma unroll
    for (int r = 0; r < NREL; r++) {
        float a = 0.f;
        #pragma unroll
        for (int q = 0; q < NB; q++) a = fmaf(sc[r * NB + q], bb[q], a);
        g_W[((size_t)r * NE + n) * D + d] = __float2half_rn(a);
    }
    g_kg[(size_t)n * D + d] = root[(size_t)n * D + d] + bias[d];
}

__global__ void __launch_bounds__(256) count_kernel(const int* __restrict__ ei,
                                                    const int* __restrict__ et) {
    int e = blockIdx.x * blockDim.x + threadIdx.x;
    if (e < NEDGE) {
        int dst = ei[NEDGE + e];
        atomicAdd(&g_cnt[dst * NREL + et[e]], 1);
    }
}

__global__ void __launch_bounds__(1024) scan_kernel() {
    __shared__ int warp_sums[32];
    __shared__ int carry_s;
    int tid = threadIdx.x, lane = tid & 31, w = tid >> 5;
    if (tid == 0) carry_s = 0;
    __syncthreads();
    for (int base = 0; base < NE; base += 1024) {
        int i = base + tid;
        int v = 0;
        if (i < NE) {
            #pragma unroll
            for (int r = 0; r < NREL; r++) v += g_cnt[i * NREL + r];
        }
        int x = v;
        #pragma unroll
        for (int o = 1; o < 32; o <<= 1) {
            int y = __shfl_up_sync(0xFFFFFFFFu, x, o);
            if (lane >= o) x += y;
        }
        if (lane == 31) warp_sums[w] = x;
        __syncthreads();
        if (w == 0) {
            int s = warp_sums[lane];
            #pragma unroll
            for (int o = 1; o < 32; o <<= 1) {
                int y = __shfl_up_sync(0xFFFFFFFFu, s, o);
                if (lane >= o) s += y;
            }
            warp_sums[lane] = s;
        }
        __syncthreads();
        int block_excl = (w > 0) ? warp_sums[w - 1] : 0;
        int excl = carry_s + block_excl + x - v;
        if (i < NE) { g_off[i] = excl; g_cur[i] = excl; }
        __syncthreads();
        if (tid == 0) carry_s += warp_sums[31];
        __syncthreads();
    }
    if (tid == 0) g_off[NE] = carry_s;
}

__global__ void __launch_bounds__(256) fill_kernel(const int* __restrict__ ei,
                                                   const int* __restrict__ et) {
    int e = blockIdx.x * blockDim.x + threadIdx.x;
    if (e >= NEDGE) return;
    int dst = ei[NEDGE + e];
    int pos = atomicAdd(&g_cur[dst], 1);
    g_elist[pos] = ei[e] | (et[e] << 16);
}

// one warp per dst: fp16 W rows (256B each), lane loads 4 halves via uint2
__global__ void __launch_bounds__(256) agg_kernel() {
    int gw = (blockIdx.x * blockDim.x + threadIdx.x) >> 5;
    int lane = threadIdx.x & 31;
    if (gw >= NE) return;
    int off = g_off[gw], end = g_off[gw + 1];
    float a0 = 0.f, a1 = 0.f, a2 = 0.f, a3 = 0.f;
    for (int b = off; b < end; b += 32) {
        int n = min(32, end - b);
        int pk = (b + lane < end) ? g_elist[b + lane] : 0;
        int j = 0;
        for (; j + 4 <= n; j += 4) {
            int p0 = __shfl_sync(0xFFFFFFFFu, pk, j);
            int p1 = __shfl_sync(0xFFFFFFFFu, pk, j + 1);
            int p2 = __shfl_sync(0xFFFFFFFFu, pk, j + 2);
            int p3 = __shfl_sync(0xFFFFFFFFu, pk, j + 3);
            uint2 u0 = *(const uint2*)(g_W + ((size_t)(p0 >> 16) * NE + (p0 & 0xFFFF)) * D + lane * 4);
            uint2 u1 = *(const uint2*)(g_W + ((size_t)(p1 >> 16) * NE + (p1 & 0xFFFF)) * D + lane * 4);
            uint2 u2 = *(const uint2*)(g_W + ((size_t)(p2 >> 16) * NE + (p2 & 0xFFFF)) * D + lane * 4);
            uint2 u3 = *(const uint2*)(g_W + ((size_t)(p3 >> 16) * NE + (p3 & 0xFFFF)) * D + lane * 4);
            float n0 = 1.f / fmaxf((float)g_cnt[gw * NREL + (p0 >> 16)], 1.f);
            float n1 = 1.f / fmaxf((float)g_cnt[gw * NREL + (p1 >> 16)], 1.f);
            float n2 = 1.f / fmaxf((float)g_cnt[gw * NREL + (p2 >> 16)], 1.f);
            float n3 = 1.f / fmaxf((float)g_cnt[gw * NREL + (p3 >> 16)], 1.f);
            float2 f;
            f = __half22float2(*(__half2*)&u0.x); a0 = fmaf(f.x, n0, a0); a1 = fmaf(f.y, n0, a1);
            f = __half22float2(*(__half2*)&u0.y); a2 = fmaf(f.x, n0, a2); a3 = fmaf(f.y, n0, a3);
            f = __half22float2(*(__half2*)&u1.x); a0 = fmaf(f.x, n1, a0); a1 = fmaf(f.y, n1, a1);
            f = __half22float2(*(__half2*)&u1.y); a2 = fmaf(f.x, n1, a2); a3 = fmaf(f.y, n1, a3);
            f = __half22float2(*(__half2*)&u2.x); a0 = fmaf(f.x, n2, a0); a1 = fmaf(f.y, n2, a1);
            f = __half22float2(*(__half2*)&u2.y); a2 = fmaf(f.x, n2, a2); a3 = fmaf(f.y, n2, a3);
            f = __half22float2(*(__half2*)&u3.x); a0 = fmaf(f.x, n3, a0); a1 = fmaf(f.y, n3, a1);
            f = __half22float2(*(__half2*)&u3.y); a2 = fmaf(f.x, n3, a2); a3 = fmaf(f.y, n3, a3);
        }
        for (; j < n; j++) {
            int p = __shfl_sync(0xFFFFFFFFu, pk, j);
            int src = p & 0xFFFF, r = p >> 16;
            float norm = 1.f / fmaxf((float)g_cnt[gw * NREL + r], 1.f);
            uint2 u = *(const uint2*)(g_W + ((size_t)r * NE + src) * D + lane * 4);
            float2 f;
            f = __half22float2(*(__half2*)&u.x); a0 = fmaf(f.x, norm, a0); a1 = fmaf(f.y, norm, a1);
            f = __half22float2(*(__half2*)&u.y); a2 = fmaf(f.x, norm, a2); a3 = fmaf(f.y, norm, a3);
        }
    }
    float* o = g_kg + (size_t)gw * D + lane * 4;
    float4 cur = *(float4*)o;
    *(float4*)o = make_float4(cur.x + a0, cur.y + a1, cur.z + a2, cur.w + a3);
}

// ---------------- encoder ----------------
__global__ void __launch_bounds__(256) embed_kernel(const int* __restrict__ tokens,
                                                    const float* __restrict__ tok_emb,
                                                    const float* __restrict__ pos_emb) {
    int i = blockIdx.x * blockDim.x + threadIdx.x;
    int d = i & (D - 1);
    int bl = i >> 7;
    int l = bl & (LSEQ - 1);
    int tk = tokens[bl];
    g_x[i] = tok_emb[(size_t)tk * D + d] * 11.3137084989847603904f + pos_emb[l * D + d];
}

// ---- split-bf16 tensor-core GEMM with ldmatrix fragment loads ----
// 128x128 tile, BK=16, 8 warps (4m x 2n), warp tile 32x64 of m16n8k16 frags.
// mode 0: grid.y tiles N; 1: qkv (grid.y selects weight+out); 2: split-K2
__global__ void __launch_bounds__(256, 2) gemm_tc_kernel(const float* __restrict__ Bw,
                                                         const float* __restrict__ bias,
                                                         int asel, int csel,
                                                         int M, int N, int K, int relu,
                                                         int mode) {
    int n0 = 0, kbeg = 0, kend = K;
    if (mode == 1) { Bw += (size_t)blockIdx.y * D * D; csel += blockIdx.y; }
    else if (mode == 2) { int half = K >> 1; kbeg = blockIdx.y * half; kend = kbeg + half;
                          if (blockIdx.y) { csel = BUF_TMP2; bias = nullptr; } }
    else n0 = blockIdx.y * 128;
    const float* __restrict__ A = g_bufs[asel];
    float* __restrict__ C = g_bufs[csel];
    __shared__ unsigned Ah_s[128][12], Al_s[128][12];
    __shared__ unsigned Bh_s[128][12], Bl_s[128][12];
    int m0 = blockIdx.x * 128;
    int tid = threadIdx.x;
    int wid = tid >> 5, lane = tid & 31;
    int wm = wid & 3, wn = wid >> 2;
    int g = lane >> 2, t4 = lane & 3;
    (void)g; (void)t4;

    float acc[2][8][4];
    #pragma unroll
    for (int i = 0; i < 2; i++)
        #pragma unroll
        for (int j = 0; j < 8; j++)
            #pragma unroll
            for (int q = 0; q < 4; q++) acc[i][j][q] = 0.f;

    int ar = tid >> 1, aw = (tid & 1) * 4;
    int bkp = tid & 7, bn4 = (tid >> 3) * 4;

    // loop-invariant ldmatrix addresses (smem rewritten in place each iter)
    unsigned baseAh = (unsigned)__cvta_generic_to_shared(&Ah_s[0][0]);
    unsigned baseAl = (unsigned)__cvta_generic_to_shared(&Al_s[0][0]);
    unsigned baseBh = (unsigned)__cvta_generic_to_shared(&Bh_s[0][0]);
    unsigned baseBl = (unsigned)__cvta_generic_to_shared(&Bl_s[0][0]);
    int lq = lane >> 3, lr = lane & 7;
    unsigned offA[2], offB[4];
    #pragma unroll
    for (int mf = 0; mf < 2; mf++) {
        int row = wm * 32 + mf * 16 + (lq & 1) * 8 + lr;
        offA[mf] = (unsigned)((row * 12 + (lq >> 1) * 4) * 4);
    }
    #pragma unroll
    for (int nfp = 0; nfp < 4; nfp++) {
        int row = wn * 64 + nfp * 16 + (lq >> 1) * 8 + lr;
        offB[nfp] = (unsigned)((row * 12 + (lq & 1) * 4) * 4);
    }

    float4 pa0, pa1, pb0, pb1;
    {
        const float* ap = A + (size_t)(m0 + ar) * K + kbeg + aw * 2;
        pa0 = *(const float4*)ap; pa1 = *(const float4*)(ap + 4);
        pb0 = *(const float4*)(Bw + (size_t)(kbeg + 2 * bkp)     * N + n0 + bn4);
        pb1 = *(const float4*)(Bw + (size_t)(kbeg + 2 * bkp + 1) * N + n0 + bn4);
    }

    for (int kc = kbeg; kc < kend; kc += 16) {
        {   // split+pack prefetched regs into smem
            float av[8] = {pa0.x, pa0.y, pa0.z, pa0.w, pa1.x, pa1.y, pa1.z, pa1.w};
            unsigned h4[4], l4[4];
            #pragma unroll
            for (int i = 0; i < 4; i++) bf_split2(av[2 * i], av[2 * i + 1], h4[i], l4[i]);
            *(uint4*)&Ah_s[ar][aw] = make_uint4(h4[0], h4[1], h4[2], h4[3]);
            *(uint4*)&Al_s[ar][aw] = make_uint4(l4[0], l4[1], l4[2], l4[3]);
            float b0v[4] = {pb0.x, pb0.y, pb0.z, pb0.w};
            float b1v[4] = {pb1.x, pb1.y, pb1.z, pb1.w};
            #pragma unroll
            for (int i = 0; i < 4; i++) {
                unsigned hw, lw;
                bf_split2(b0v[i], b1v[i], hw, lw);
                Bh_s[bn4 + i][bkp] = hw;
                Bl_s[bn4 + i][bkp] = lw;
            }
        }
        __syncthreads();
        if (kc + 16 < kend) {
            const float* ap = A + (size_t)(m0 + ar) * K + kc + 16 + aw * 2;
            pa0 = *(const float4*)ap; pa1 = *(const float4*)(ap + 4);
            pb0 = *(const float4*)(Bw + (size_t)(kc + 16 + 2 * bkp)     * N + n0 + bn4);
            pb1 = *(const float4*)(Bw + (size_t)(kc + 16 + 2 * bkp + 1) * N + n0 + bn4);
        }
        {
            unsigned ah[2][4], al_[2][4];
            #pragma unroll
            for (int mf = 0; mf < 2; mf++) {
                ldsm_x4(ah[mf][0], ah[mf][1], ah[mf][2], ah[mf][3], baseAh + offA[mf]);
                ldsm_x4(al_[mf][0], al_[mf][1], al_[mf][2], al_[mf][3], baseAl + offA[mf]);
            }
            #pragma unroll
            for (int nfp = 0; nfp < 4; nfp++) {
                unsigned bh4[4], bl4[4];
                ldsm_x4(bh4[0], bh4[1], bh4[2], bh4[3], baseBh + offB[nfp]);
                ldsm_x4(bl4[0], bl4[1], bl4[2], bl4[3], baseBl + offB[nfp]);
                #pragma unroll
                for (int half = 0; half < 2; half++) {
                    int nf = nfp * 2 + half;
                    unsigned bh2[2] = {bh4[half * 2], bh4[half * 2 + 1]};
                    unsigned bl2[2] = {bl4[half * 2], bl4[half * 2 + 1]};
                    #pragma unroll
                    for (int mf = 0; mf < 2; mf++) {
                        mma_bf16(acc[mf][nf], al_[mf], bh2);
                        mma_bf16(acc[mf][nf], ah[mf], bl2);
                        mma_bf16(acc[mf][nf], ah[mf], bh2);
                    }
                }
            }
        }
        __syncthreads();
    }
    int go = lane >> 2, gt = lane & 3;
    #pragma unroll
    for (int mf = 0; mf < 2; mf++) {
        int r0 = m0 + wm * 32 + mf * 16 + go;
        #pragma unroll
        for (int nf = 0; nf < 8; nf++) {
            int c0 = n0 + wn * 64 + nf * 8 + gt * 2;
            float bb0 = bias ? bias[c0] : 0.f;
            float bb1 = bias ? bias[c0 + 1] : 0.f;
            float v0 = acc[mf][nf][0] + bb0, v1 = acc[mf][nf][1] + bb1;
            float v2 = acc[mf][nf][2] + bb0, v3 = acc[mf][nf][3] + bb1;
            if (relu) {
                v0 = fmaxf(v0, 0.f); v1 = fmaxf(v1, 0.f);
                v2 = fmaxf(v2, 0.f); v3 = fmaxf(v3, 0.f);
            }
            *(float2*)&C[(size_t)r0 * N + c0]       = make_float2(v0, v1);
            *(float2*)&C[(size_t)(r0 + 8) * N + c0] = make_float2(v2, v3);
        }
    }
}

// ---- split-bf16 attention scores: 64q x 64k tile, d=64 ----
__global__ void __launch_bounds__(256, 2) attn_scores_tc(const int* __restrict__ tokens) {
    int bh = blockIdx.x;
    int b = bh >> 1, h = bh & 1;
    int q0 = blockIdx.y * 64, k0 = blockIdx.z * 64;
    __shared__ unsigned Qh[64][36], Ql[64][36];
    __shared__ unsigned Kh[64][36], Kl[64][36];
    int tid = threadIdx.x;
    {
        int r = tid >> 2, c8 = (tid & 3) * 8;
        const float* qp = g_q + (size_t)(b * LSEQ + q0 + r) * D + h * DH + c8 * 2;
        const float* kp = g_k + (size_t)(b * LSEQ + k0 + r) * D + h * DH + c8 * 2;
        float qf[16], kf[16];
        #pragma unroll
        for (int u = 0; u < 4; u++) {
            *(float4*)&qf[u * 4] = *(const float4*)(qp + u * 4);
            *(float4*)&kf[u * 4] = *(const float4*)(kp + u * 4);
        }
        #pragma unroll
        for (int i = 0; i < 8; i++) {
            unsigned hw, lw;
            bf_split2(qf[2 * i], qf[2 * i + 1], hw, lw);
            Qh[r][c8 + i] = hw; Ql[r][c8 + i] = lw;
            bf_split2(kf[2 * i], kf[2 * i + 1], hw, lw);
            Kh[r][c8 + i] = hw; Kl[r][c8 + i] = lw;
        }
    }
    __syncthreads();
    int wid = tid >> 5, lane = tid & 31;
    int wm = wid & 3, wn = wid >> 2;
    int g = lane >> 2, t4 = lane & 3;
    int m0 = wm * 16;

    float acc[4][4];
    #pragma unroll
    for (int j = 0; j < 4; j++)
        #pragma unroll
        for (int q = 0; q < 4; q++) acc[j][q] = 0.f;

    #pragma unroll
    for (int ks = 0; ks < 4; ks++) {
        int wb = ks * 8;
        unsigned ah[4], al[4];
        ah[0] = Qh[m0 + g    ][wb + t4    ];  al[0] = Ql[m0 + g    ][wb + t4    ];
        ah[1] = Qh[m0 + g + 8][wb + t4    ];  al[1] = Ql[m0 + g + 8][wb + t4    ];
        ah[2] = Qh[m0 + g    ][wb + t4 + 4];  al[2] = Ql[m0 + g    ][wb + t4 + 4];
        ah[3] = Qh[m0 + g + 8][wb + t4 + 4];  al[3] = Ql[m0 + g + 8][wb + t4 + 4];
        #pragma unroll
        for (int nf = 0; nf < 4; nf++) {
            int nn = wn * 32 + nf * 8 + g;
            unsigned bh2[2] = {Kh[nn][wb + t4], Kh[nn][wb + t4 + 4]};
            unsigned bl2[2] = {Kl[nn][wb + t4], Kl[nn][wb + t4 + 4]};
            mma_bf16(acc[nf], al, bh2);
            mma_bf16(acc[nf], ah, bl2);
            mma_bf16(acc[nf], ah, bh2);
        }
    }
    int row0 = bh * LSEQ + q0 + m0 + g;
    #pragma unroll
    for (int nf = 0; nf < 4; nf++) {
        int c0 = k0 + wn * 32 + nf * 8 + t4 * 2;
        float mb0 = (tokens[b * LSEQ + c0] != 0) ? 0.f : NEGV;
        float mb1 = (tokens[b * LSEQ + c0 + 1] != 0) ? 0.f : NEGV;
        *(float2*)&g_sc[(size_t)row0 * LSEQ + c0] =
            make_float2(acc[nf][0] * 0.125f + mb0, acc[nf][1] * 0.125f + mb1);
        *(float2*)&g_sc[(size_t)(row0 + 8) * LSEQ + c0] =
            make_float2(acc[nf][2] * 0.125f + mb0, acc[nf][3] * 0.125f + mb1);
    }
}

__global__ void __launch_bounds__(128) softmax_kernel() {
    int row = blockIdx.x * 4 + (threadIdx.x >> 5);
    int lane = threadIdx.x & 31;
    float* p = g_sc + (size_t)row * LSEQ;
    float v[8];
    float m = -INFINITY;
    #pragma unroll
    for (int i = 0; i < 8; i++) { v[i] = p[lane + 32 * i]; m = fmaxf(m, v[i]); }
    m = warp_max(m);
    float s = 0.f;
    #pragma unroll
    for (int i = 0; i < 8; i++) { v[i] = expf(v[i] - m); s += v[i]; }
    s = warp_sum(s);
    float inv = 1.f / s;
    #pragma unroll
    for (int i = 0; i < 8; i++) p[lane + 32 * i] = v[i] * inv;
}

// ---- split-bf16 AV ----
__global__ void __launch_bounds__(256, 2) attn_av_tc() {
    int bh = blockIdx.x;
    int b = bh >> 1, h = bh & 1;
    int l0 = blockIdx.y * 128;
    __shared__ unsigned Ph[128][20], Pl[128][20];
    __shared__ unsigned Vh[64][20], Vl[64][20];
    int tid = threadIdx.x;
    int wid = tid >> 5, lane = tid & 31;
    int wm = wid & 3, wn = wid >> 2;
    int g = lane >> 2, t4 = lane & 3;

    float acc[2][4][4];
    #pragma unroll
    for (int i = 0; i < 2; i++)
        #pragma unroll
        for (int j = 0; j < 4; j++)
            #pragma unroll
            for (int q = 0; q < 4; q++) acc[i][j][q] = 0.f;

    int pr = tid >> 1, pw8 = (tid & 1) * 8;
    int td = tid & 63, tk4 = (tid >> 6) * 4;

    for (int kc = 0; kc < 8; kc++) {
        {
            const float* pp = g_sc + (size_t)(bh * LSEQ + l0 + pr) * LSEQ + kc * 32 + pw8 * 2;
            float pf[16];
            #pragma unroll
            for (int u = 0; u < 4; u++)
                *(float4*)&pf[u * 4] = *(const float4*)(pp + u * 4);
            #pragma unroll
            for (int i = 0; i < 8; i++) {
                unsigned hw, lw;
                bf_split2(pf[2 * i], pf[2 * i + 1], hw, lw);
                Ph[pr][pw8 + i] = hw; Pl[pr][pw8 + i] = lw;
            }
            #pragma unroll
            for (int kp = 0; kp < 4; kp++) {
                int kk = tk4 + kp;
                float v0 = g_v[(size_t)(b * LSEQ + kc * 32 + 2 * kk)     * D + h * DH + td];
                float v1 = g_v[(size_t)(b * LSEQ + kc * 32 + 2 * kk + 1) * D + h * DH + td];
                unsigned hw, lw;
                bf_split2(v0, v1, hw, lw);
                Vh[td][kk] = hw; Vl[td][kk] = lw;
            }
        }
        __syncthreads();
        #pragma unroll
        for (int ks = 0; ks < 2; ks++) {
            int wb = ks * 8;
            unsigned ah[2][4], al_[2][4];
            #pragma unroll
            for (int mf = 0; mf < 2; mf++) {
                int mm = wm * 32 + mf * 16;
                ah[mf][0] = Ph[mm + g    ][wb + t4    ];  al_[mf][0] = Pl[mm + g    ][wb + t4    ];
                ah[mf][1] = Ph[mm + g + 8][wb + t4    ];  al_[mf][1] = Pl[mm + g + 8][wb + t4    ];
                ah[mf][2] = Ph[mm + g    ][wb + t4 + 4];  al_[mf][2] = Pl[mm + g    ][wb + t4 + 4];
                ah[mf][3] = Ph[mm + g + 8][wb + t4 + 4];  al_[mf][3] = Pl[mm + g + 8][wb + t4 + 4];
            }
            #pragma unroll
            for (int nf = 0; nf < 4; nf++) {
                int nn = wn * 32 + nf * 8 + g;
                unsigned bh2[2] = {Vh[nn][wb + t4], Vh[nn][wb + t4 + 4]};
                unsigned bl2[2] = {Vl[nn][wb + t4], Vl[nn][wb + t4 + 4]};
                #pragma unroll
                for (int mf = 0; mf < 2; mf++) {
                    mma_bf16(acc[mf][nf], al_[mf], bh2);
                    mma_bf16(acc[mf][nf], ah[mf], bl2);
                    mma_bf16(acc[mf][nf], ah[mf], bh2);
                }
            }
        }
        __syncthreads();
    }
    #pragma unroll
    for (int mf = 0; mf < 2; mf++) {
        int r0 = b * LSEQ + l0 + wm * 32 + mf * 16 + g;
        #pragma unroll
        for (int nf = 0; nf < 4; nf++) {
            int c0 = h * DH + wn * 32 + nf * 8 + t4 * 2;
            *(float2*)&g_ao[(size_t)r0 * D + c0] = make_float2(acc[mf][nf][0], acc[mf][nf][1]);
            *(float2*)&g_ao[(size_t)(r0 + 8) * D + c0] = make_float2(acc[mf][nf][2], acc[mf][nf][3]);
        }
    }
}

// 2 rows per block (256 threads); row handled by its own 4 warps
__global__ void __launch_bounds__(256) add_ln_kernel(const float* __restrict__ g,
                                                     const float* __restrict__ b,
                                                     int sum2) {
    int tid = threadIdx.x;
    int half = tid >> 7;
    int t = tid & 127;
    int row = blockIdx.x * 2 + half;
    int w = t >> 5, lane = t & 31;
    float v = g_x[(size_t)row * D + t] + g_tmp[(size_t)row * D + t];
    if (sum2) v += g_tmp2[(size_t)row * D + t];
    float s = warp_sum(v);
    float s2 = warp_sum(v * v);
    __shared__ float ws[8], ws2[8];
    if (lane == 0) { ws[half * 4 + w] = s; ws2[half * 4 + w] = s2; }
    __syncthreads();
    int base = half * 4;
    s = ws[base] + ws[base + 1] + ws[base + 2] + ws[base + 3];
    s2 = ws2[base] + ws2[base + 1] + ws2[base + 2] + ws2[base + 3];
    float m = s * (1.f / D);
    float var = s2 * (1.f / D) - m * m;
    float inv = rsqrtf(var + 1e-5f);
    g_x[(size_t)row * D + t] = (v - m) * inv * g[t] + b[t];
}

// ---------------- pooling / gate / final ----------------
__global__ void __launch_bounds__(128) tok_pool_kernel(const int* __restrict__ tokens,
                                                       const float* __restrict__ vvec) {
    int b = blockIdx.x, tid = threadIdx.x;
    int w = tid >> 5, lane = tid & 31;
    __shared__ float s_s[LSEQ];
    __shared__ float red[4];
    for (int l = w; l < LSEQ; l += 4) {
        float val = 0.f;
        #pragma unroll
        for (int d = lane; d < D; d += 32)
            val += tanhf(g_ffn[((size_t)(b * LSEQ + l)) * D + d]) * vvec[d];
        val = warp_sum(val);
        if (lane == 0) s_s[l] = (tokens[b * LSEQ + l] != 0) ? val : NEGV;
    }
    __syncthreads();
    float m = fmaxf(s_s[tid], s_s[tid + 128]);
    m = warp_max(m);
    if (lane == 0) red[w] = m;
    __syncthreads();
    m = fmaxf(fmaxf(red[0], red[1]), fmaxf(red[2], red[3]));
    __syncthreads();
    float e0 = expf(s_s[tid] - m), e1 = expf(s_s[tid + 128] - m);
    float ssum = warp_sum(e0 + e1);
    if (lane == 0) red[w] = ssum;
    __syncthreads();
    ssum = red[0] + red[1] + red[2] + red[3];
    float inv = 1.f / ssum;
    __syncthreads();
    s_s[tid] = e0 * inv; s_s[tid + 128] = e1 * inv;
    __syncthreads();
    float acc = 0.f;
    for (int l = 0; l < LSEQ; l++)
        acc = fmaf(s_s[l], g_x[((size_t)(b * LSEQ + l)) * D + tid], acc);
    g_trep[b * D + tid] = acc;
}

__global__ void __launch_bounds__(128) ent_pool_kernel(const int* __restrict__ ctx,
                                                       const float* __restrict__ Wa,
                                                       const float* __restrict__ ba,
                                                       const float* __restrict__ vvec) {
    int b = blockIdx.x, tid = threadIdx.x;
    int w = tid >> 5, lane = tid & 31;
    __shared__ float h_s[NCTX][D];
    __shared__ float s_s[NCTX];
    __shared__ int cs[NCTX];
    if (tid < NCTX) cs[tid] = ctx[b * NCTX + tid];
    __syncthreads();
    for (int j = 0; j < NCTX; j++)
        h_s[j][tid] = g_kg[(size_t)cs[j] * D + tid];
    __syncthreads();
    for (int j = w; j < NCTX; j += 4) {
        float val = 0.f;
        for (int d = lane; d < D; d += 32) {
            float acc = ba[d];
            #pragma unroll 8
            for (int kk = 0; kk < D; kk++)
                acc = fmaf(h_s[j][kk], Wa[kk * D + d], acc);
            val += tanhf(acc) * vvec[d];
        }
        val = warp_sum(val);
        if (lane == 0) s_s[j] = (cs[j] != 0) ? val : NEGV;
    }
    __syncthreads();
    if (w == 0) {
        float sv = s_s[lane];
        float m = warp_max(sv);
        float e = expf(sv - m);
        float ssum = warp_sum(e);
        s_s[lane] = e / ssum;
    }
    __syncthreads();
    float acc = 0.f;
    #pragma unroll
    for (int j = 0; j < NCTX; j++) acc = fmaf(s_s[j], h_s[j][tid], acc);
    g_erep[b * D + tid] = acc;
}

__global__ void __launch_bounds__(128) gate_kernel(const float* __restrict__ Wg,
                                                   const float* __restrict__ bg) {
    int b = blockIdx.x, tid = threadIdx.x;
    __shared__ float cat[2 * D];
    cat[tid] = g_trep[b * D + tid];
    cat[D + tid] = g_erep[b * D + tid];
    __syncthreads();
    float acc = bg[tid];
    #pragma unroll 8
    for (int j = 0; j < 2 * D; j++) acc = fmaf(cat[j], Wg[j * D + tid], acc);
    float sg = 1.f / (1.f + expf(-acc));
    g_user[b * D + tid] = sg * cat[tid] + (1.f - sg) * cat[D + tid];
}

__global__ void __launch_bounds__(256) final_kernel(float* __restrict__ out) {
    __shared__ float kg_s[128][17];
    __shared__ float user_t[D][BATCH];
    int n0 = blockIdx.x * 128, tid = threadIdx.x;
    for (int i = tid; i < D * BATCH; i += 256) {
        int d = i >> 6, bb = i & 63;
        user_t[d][bb] = g_user[bb * D + d];
    }
    int tn = tid >> 3, tb = tid & 7;
    float acc[4][8];
    #pragma unroll
    for (int i = 0; i < 4; i++)
        #pragma unroll
        for (int j = 0; j < 8; j++) acc[i][j] = 0.f;
    for (int dc = 0; dc < D; dc += 16) {
        __syncthreads();
        for (int i = tid; i < 128 * 16; i += 256) {
            int nl = i >> 4, dd = i & 15;
            int n = n0 + nl;
            kg_s[nl][dd] = (n < NE) ? g_kg[(size_t)n * D + dc + dd] : 0.f;
        }
        __syncthreads();
        #pragma unroll
        for (int dd = 0; dd < 16; dd++) {
            float kv[4], uv[8];
            #pragma unroll
            for (int i = 0; i < 4; i++) kv[i] = kg_s[tn * 4 + i][dd];
            #pragma unroll
            for (int j = 0; j < 8; j++) uv[j] = user_t[dc + dd][tb * 8 + j];
            #pragma unroll
            for (int i = 0; i < 4; i++)
                #pragma unroll
                for (int j = 0; j < 8; j++) acc[i][j] = fmaf(kv[i], uv[j], acc[i][j]);
        }
    }
    #pragma unroll
    for (int i = 0; i < 4; i++) {
        int n = n0 + tn * 4 + i;
        if (n < NE) {
            #pragma unroll
            for (int j = 0; j < 8; j++)
                out[(size_t)(tb * 8 + j) * NE + n] = acc[i][j];
        }
    }
}

// ---------------- launch ----------------
extern "C" void kernel_launch(void* const* d_in, const int* in_sizes, int n_in,
                              void* d_out, int out_size) {
    const int*   edge_idx = (const int*)d_in[0];
    const int*   edge_type = (const int*)d_in[1];
    const int*   ctx_ent  = (const int*)d_in[2];
    const int*   ctx_tok  = (const int*)d_in[3];
    const float* basis    = (const float*)d_in[4];
    const float* comp     = (const float*)d_in[5];
    const float* root     = (const float*)d_in[6];
    const float* rgcn_b   = (const float*)d_in[7];
    const float* tok_emb  = (const float*)d_in[8];
    const float* pos_emb  = (const float*)d_in[9];
    const float* Wqkv     = (const float*)d_in[10];
    const float* Wo       = (const float*)d_in[11];
    const float* ln1_g    = (const float*)d_in[12];
    const float* ln1_b    = (const float*)d_in[13];
    const float* ln2_g    = (const float*)d_in[14];
    const float* ln2_b    = (const float*)d_in[15];
    const float* W1       = (const float*)d_in[16];
    const float* b1       = (const float*)d_in[17];
    const float* W2       = (const float*)d_in[18];
    const float* b2       = (const float*)d_in[19];
    const float* ent_Wa   = (const float*)d_in[20];
    const float* ent_ba   = (const float*)d_in[21];
    const float* ent_v    = (const float*)d_in[22];
    const float* tok_Wa   = (const float*)d_in[23];
    const float* tok_ba   = (const float*)d_in[24];
    const float* tok_v    = (const float*)d_in[25];
    const float* Wg       = (const float*)d_in[26];
    const float* bg       = (const float*)d_in[27];
    float* out = (float*)d_out;

    const int M = BATCH * LSEQ;  // 16384

    // --- encoder FIRST (QKV GEMM stays at the ncu-profiled launch slot) ---
    init_ptrs_kernel<<<1, 1>>>();
    zero_cnt_kernel<<<(NE * NREL + 255) / 256, 256>>>();
    embed_kernel<<<(BATCH * LSEQ * D) / 256, 256>>>(ctx_tok, tok_emb, pos_emb);
    for (int l = 0; l < NLAY; l++) {
        gemm_tc_kernel<<<dim3(M / 128, 3), 256>>>(Wqkv + (size_t)l * 3 * D * D, nullptr, BUF_X, BUF_Q, M, D, D, 0, 1);
        attn_scores_tc<<<dim3(BATCH * NHEAD, LSEQ / 64, LSEQ / 64), 256>>>(ctx_tok);
        softmax_kernel<<<(BATCH * NHEAD * LSEQ) / 4, 128>>>();
        attn_av_tc<<<dim3(BATCH * NHEAD, LSEQ / 128), 256>>>();
        gemm_tc_kernel<<<dim3(M / 128, 1), 256>>>(Wo + (size_t)l * D * D, nullptr, BUF_AO, BUF_TMP, M, D, D, 0, 0);
        add_ln_kernel<<<M / 2, 256>>>(ln1_g + l * D, ln1_b + l * D, 0);
        gemm_tc_kernel<<<dim3(M / 128, FFND / 128), 256>>>(W1 + (size_t)l * D * FFND, b1 + l * FFND, BUF_X, BUF_FFN, M, FFND, D, 1, 0);
        gemm_tc_kernel<<<dim3(M / 128, 2), 256>>>(W2 + (size_t)l * FFND * D, b2 + l * D, BUF_FFN, BUF_TMP, M, D, FFND, 0, 2);
        add_ln_kernel<<<M / 2, 256>>>(ln2_g + l * D, ln2_b + l * D, 1);
    }
    gemm_tc_kernel<<<dim3(M / 128, 1), 256>>>(tok_Wa, tok_ba, BUF_X, BUF_FFN, M, D, D, 0, 0);

    // --- RGCN (CSR, fp16 W, no atomics on kg) ---
    rgcn_w_kernel<<<NE, 128>>>(basis, comp, root, rgcn_b);
    count_kernel<<<(NEDGE + 255) / 256, 256>>>(edge_idx, edge_type);
    scan_kernel<<<1, 1024>>>();
    fill_kernel<<<(NEDGE + 255) / 256, 256>>>(edge_idx, edge_type);
    agg_kernel<<<(NE * 32 + 255) / 256, 256>>>();

    // --- pooling / gate / score ---
    tok_pool_kernel<<<BATCH, 128>>>(ctx_tok, tok_v);
    ent_pool_kernel<<<BATCH, 128>>>(ctx_ent, ent_Wa, ent_ba, ent_v);
    gate_kernel<<<BATCH, 128>>>(Wg, bg);
    final_kernel<<<(NE + 127) / 128, 256>>>(out);
}